// round 2
// baseline (speedup 1.0000x reference)
#include <cuda_runtime.h>
#include <cstdint>

#define NN   65536
#define EE   1048576
#define D1   512
#define DOUTD 128
#define KIN  1024

// ---------------- device scratch (static: allocation-free) ----------------
__device__ float g_Wcat[KIN * D1];            // 2 MB   concat [W_t1;W_t2]
__device__ float g_bcat[D1];
__device__ float g_h0 [(size_t)NN * D1];      // 128 MB  h0, later h1(relu)
__device__ float g_t1 [(size_t)NN * D1];      // 128 MB  h0@W1 (pre-aggregate)
__device__ float g_h2a[(size_t)NN * DOUTD];   // 32 MB   h1@W2, later T = h2@matrix
__device__ float g_h2b[(size_t)NN * DOUTD];   // 32 MB   h2 (post conv2)
__device__ float g_isq[NN];
__device__ int   g_cnt[NN];
__device__ int   g_rowptr[NN + 1];
__device__ int   g_cursor[NN];
__device__ int   g_bsum[256];
__device__ int   g_boff[256];
__device__ int   g_adj[EE];
__device__ int   g_is64;

// ---------------- f32x2 packed-FMA helpers ----------------
__device__ __forceinline__ void ffma2(unsigned long long& d,
                                      unsigned long long a,
                                      unsigned long long b) {
    asm("fma.rn.f32x2 %0, %1, %2, %0;" : "+l"(d) : "l"(a), "l"(b));
}
__device__ __forceinline__ void unpack2(unsigned long long v, float& lo, float& hi) {
    asm("mov.b64 {%0, %1}, %2;" : "=f"(lo), "=f"(hi) : "l"(v));
}

// edge_index dtype is ambiguous: reference says int64 but JAX downgrades to
// int32 unless x64 is enabled. Detect at runtime (device-side, capture-safe):
// for int64 values in [0, 65536), every odd 32-bit word is 0.
__global__ void k_detect(const int* __restrict__ ei) {
    if (blockIdx.x == 0 && threadIdx.x == 0) {
        int ok = 1;
#pragma unroll 1
        for (int i = 1; i < 512; i += 2)
            if (ei[i] != 0) { ok = 0; break; }
        g_is64 = ok;
    }
}
__device__ __forceinline__ int edge_at(const void* eiv, int idx) {
    if (g_is64) return (int)((const long long*)eiv)[idx];
    return ((const int*)eiv)[idx];
}

// ---------------- small prep kernels ----------------
__global__ void k_wcat(const float* __restrict__ Wt1, const float* __restrict__ Wt2) {
    int i = blockIdx.x * blockDim.x + threadIdx.x;
    if (i >= KIN * D1) return;
    int k = i >> 9, j = i & 511;
    g_Wcat[i] = (k < 256) ? Wt1[k * D1 + j] : Wt2[(k - 256) * D1 + j];
}
__global__ void k_bcat(const float* __restrict__ bt1, const float* __restrict__ bt2) {
    int j = blockIdx.x * blockDim.x + threadIdx.x;
    if (j < D1) g_bcat[j] = bt1[j] + bt2[j];
}
__global__ void k_zero_cnt() {
    int i = blockIdx.x * blockDim.x + threadIdx.x;
    if (i < NN) g_cnt[i] = 0;
}
__global__ void k_count(const void* __restrict__ eiv) {
    int e = blockIdx.x * blockDim.x + threadIdx.x;
    if (e >= EE) return;
    int d = edge_at(eiv, EE + e);
    atomicAdd(&g_cnt[d], 1);
}
__global__ void k_isq() {
    int i = blockIdx.x * blockDim.x + threadIdx.x;
    if (i < NN) g_isq[i] = rsqrtf((float)g_cnt[i] + 1.0f);
}
__global__ void k_scanA() {
    __shared__ int sh[256];
    int t = threadIdx.x, b = blockIdx.x;
    sh[t] = g_cnt[b * 256 + t];
    __syncthreads();
    for (int off = 128; off > 0; off >>= 1) {
        if (t < off) sh[t] += sh[t + off];
        __syncthreads();
    }
    if (t == 0) g_bsum[b] = sh[0];
}
__global__ void k_scanB() {
    __shared__ int sh[256];
    int t = threadIdx.x;
    int v = g_bsum[t];
    sh[t] = v;
    __syncthreads();
    for (int off = 1; off < 256; off <<= 1) {
        int x = (t >= off) ? sh[t - off] : 0;
        __syncthreads();
        sh[t] += x;
        __syncthreads();
    }
    g_boff[t] = sh[t] - v;
    if (t == 255) g_rowptr[NN] = sh[255];
}
__global__ void k_scanC() {
    __shared__ int sh[256];
    int t = threadIdx.x, b = blockIdx.x;
    int i = b * 256 + t;
    int v = g_cnt[i];
    sh[t] = v;
    __syncthreads();
    for (int off = 1; off < 256; off <<= 1) {
        int x = (t >= off) ? sh[t - off] : 0;
        __syncthreads();
        sh[t] += x;
        __syncthreads();
    }
    int excl = sh[t] - v + g_boff[b];
    g_rowptr[i] = excl;
    g_cursor[i] = excl;
}
__global__ void k_fill(const void* __restrict__ eiv) {
    int e = blockIdx.x * blockDim.x + threadIdx.x;
    if (e >= EE) return;
    int s = edge_at(eiv, e);
    int d = edge_at(eiv, EE + e);
    int pos = atomicAdd(&g_cursor[d], 1);
    g_adj[pos] = s;
}

// ---------------- SGEMM: C = A@B (+bias), f32x2 packed ----------------
// BM=BN=128, BK=8, 256 threads, 8x8 micro-tile per thread.
// A-side values stored DUPLICATED in shared so ulonglong2 loads give packed
// broadcast pairs; B-side pairs come packed naturally.
template <int BIAS>
__global__ __launch_bounds__(256, 2) void sgemm_k(
    const float* __restrict__ A, const float* __restrict__ B,
    const float* __restrict__ bias, float* __restrict__ C,
    int M, int N, int K)
{
    __shared__ __align__(16) float As2[8][268];  // duplicated: col 2m,2m+1 = A[m]
    __shared__ __align__(16) float Bs[8][128];

    int tid = threadIdx.x;
    int bx = blockIdx.x, by = blockIdx.y;
    int ty = tid >> 4, tx = tid & 15;

    int arow = tid >> 1;
    int acol4 = (tid & 1) * 4;
    int brow = tid >> 5;
    int bcol4 = (tid & 31) * 4;

    const float* Ap = A + (size_t)(by * 128 + arow) * K;
    const float* Bp = B + (size_t)brow * N + bx * 128 + bcol4;

    unsigned long long acc[8][4];
#pragma unroll
    for (int i = 0; i < 8; i++)
#pragma unroll
        for (int j = 0; j < 4; j++) acc[i][j] = 0ull;

    for (int kt = 0; kt < K; kt += 8) {
        float4 av = *(const float4*)(Ap + kt + acol4);
        *(float2*)&As2[acol4 + 0][2 * arow] = make_float2(av.x, av.x);
        *(float2*)&As2[acol4 + 1][2 * arow] = make_float2(av.y, av.y);
        *(float2*)&As2[acol4 + 2][2 * arow] = make_float2(av.z, av.z);
        *(float2*)&As2[acol4 + 3][2 * arow] = make_float2(av.w, av.w);
        float4 bv = *(const float4*)(Bp + (size_t)kt * N);
        *(float4*)&Bs[brow][bcol4] = bv;
        __syncthreads();
#pragma unroll
        for (int k = 0; k < 8; k++) {
            ulonglong2 a0 = *(const ulonglong2*)&As2[k][ty * 16 + 0];
            ulonglong2 a1 = *(const ulonglong2*)&As2[k][ty * 16 + 4];
            ulonglong2 a2 = *(const ulonglong2*)&As2[k][ty * 16 + 8];
            ulonglong2 a3 = *(const ulonglong2*)&As2[k][ty * 16 + 12];
            ulonglong2 b0 = *(const ulonglong2*)&Bs[k][tx * 8 + 0];
            ulonglong2 b1 = *(const ulonglong2*)&Bs[k][tx * 8 + 4];
            unsigned long long ap[8] = {a0.x, a0.y, a1.x, a1.y, a2.x, a2.y, a3.x, a3.y};
            unsigned long long bp[4] = {b0.x, b0.y, b1.x, b1.y};
#pragma unroll
            for (int i = 0; i < 8; i++)
#pragma unroll
                for (int j = 0; j < 4; j++) ffma2(acc[i][j], ap[i], bp[j]);
        }
        __syncthreads();
    }

    float4 bv0, bv1;
    if (BIAS) {
        const float* bp = bias + bx * 128 + tx * 8;
        bv0 = *(const float4*)(bp);
        bv1 = *(const float4*)(bp + 4);
    }
#pragma unroll
    for (int i = 0; i < 8; i++) {
        float f[8];
#pragma unroll
        for (int j = 0; j < 4; j++) unpack2(acc[i][j], f[2 * j], f[2 * j + 1]);
        if (BIAS) {
            f[0] += bv0.x; f[1] += bv0.y; f[2] += bv0.z; f[3] += bv0.w;
            f[4] += bv1.x; f[5] += bv1.y; f[6] += bv1.z; f[7] += bv1.w;
        }
        float* cp = C + (size_t)(by * 128 + ty * 8 + i) * N + bx * 128 + tx * 8;
        *(float4*)cp       = make_float4(f[0], f[1], f[2], f[3]);
        *(float4*)(cp + 4) = make_float4(f[4], f[5], f[6], f[7]);
    }
}

// ---------------- CSR aggregate: out[n] = sum_{s in adj(n)} h[s]*isq[s]*isq[n]
//                   + h[n]*isq[n]^2 + bias (+relu) ----------------
template <int D, int RELU>
__global__ void conv_agg(const float* __restrict__ hin,
                         const float* __restrict__ bias,
                         float* __restrict__ hout)
{
    int warp = (blockIdx.x * blockDim.x + threadIdx.x) >> 5;
    int lane = threadIdx.x & 31;
    if (warp >= NN) return;
    const int R = D / 32;
    int n = warp;
    float iq = g_isq[n];
    float acc[R];
    {
        float w = iq * iq;
        const float* hp = hin + (size_t)n * D;
#pragma unroll
        for (int i = 0; i < R; i++) acc[i] = hp[lane + 32 * i] * w;
    }
    int beg = g_rowptr[n], end = g_rowptr[n + 1];
    for (int k = beg; k < end; k++) {
        int s = g_adj[k];
        float w = g_isq[s] * iq;
        const float* hs = hin + (size_t)s * D;
#pragma unroll
        for (int i = 0; i < R; i++) acc[i] += hs[lane + 32 * i] * w;
    }
    float* op = hout + (size_t)n * D;
#pragma unroll
    for (int i = 0; i < R; i++) {
        float v = acc[i] + bias[lane + 32 * i];
        if (RELU) v = fmaxf(v, 0.0f);
        op[lane + 32 * i] = v;
    }
}

// ---------------- batched bilinear scores + Linear(1,2) epilogue ----------
// grid: 1024 blocks = 256 chunks x 4 quadrants of 128x128.
// scores[b,i,j] = sum_k T[b*256+i, k] * e[b*256+j, k]   (NT, K=128)
__global__ __launch_bounds__(256, 2) void k_scores(
    const float* __restrict__ Tm, const float* __restrict__ Em,
    const float* __restrict__ lw, const float* __restrict__ lb,
    float* __restrict__ out)
{
    __shared__ __align__(16) float Ts2[16][260];  // duplicated i-side
    __shared__ __align__(16) float Es[16][132];

    int bchunk = blockIdx.x >> 2;
    int quad = blockIdx.x & 3;
    int i0 = bchunk * 256 + (quad >> 1) * 128;
    int j0 = bchunk * 256 + (quad & 1) * 128;
    int tid = threadIdx.x;
    int ty = tid >> 4, tx = tid & 15;

    unsigned long long acc[8][4];
#pragma unroll
    for (int i = 0; i < 8; i++)
#pragma unroll
        for (int j = 0; j < 4; j++) acc[i][j] = 0ull;

    for (int k0 = 0; k0 < DOUTD; k0 += 16) {
#pragma unroll
        for (int r = 0; r < 2; r++) {
            int id = tid + 256 * r;
            int row = id >> 2;
            int c4 = (id & 3) * 4;
            float4 tv = *(const float4*)&Tm[(size_t)(i0 + row) * DOUTD + k0 + c4];
            *(float2*)&Ts2[c4 + 0][2 * row] = make_float2(tv.x, tv.x);
            *(float2*)&Ts2[c4 + 1][2 * row] = make_float2(tv.y, tv.y);
            *(float2*)&Ts2[c4 + 2][2 * row] = make_float2(tv.z, tv.z);
            *(float2*)&Ts2[c4 + 3][2 * row] = make_float2(tv.w, tv.w);
            float4 ev = *(const float4*)&Em[(size_t)(j0 + row) * DOUTD + k0 + c4];
            Es[c4 + 0][row] = ev.x;
            Es[c4 + 1][row] = ev.y;
            Es[c4 + 2][row] = ev.z;
            Es[c4 + 3][row] = ev.w;
        }
        __syncthreads();
#pragma unroll
        for (int k = 0; k < 16; k++) {
            ulonglong2 a0 = *(const ulonglong2*)&Ts2[k][ty * 16 + 0];
            ulonglong2 a1 = *(const ulonglong2*)&Ts2[k][ty * 16 + 4];
            ulonglong2 a2 = *(const ulonglong2*)&Ts2[k][ty * 16 + 8];
            ulonglong2 a3 = *(const ulonglong2*)&Ts2[k][ty * 16 + 12];
            ulonglong2 b0 = *(const ulonglong2*)&Es[k][tx * 8 + 0];
            ulonglong2 b1 = *(const ulonglong2*)&Es[k][tx * 8 + 4];
            unsigned long long ap[8] = {a0.x, a0.y, a1.x, a1.y, a2.x, a2.y, a3.x, a3.y};
            unsigned long long bp[4] = {b0.x, b0.y, b1.x, b1.y};
#pragma unroll
            for (int i = 0; i < 8; i++)
#pragma unroll
                for (int j = 0; j < 4; j++) ffma2(acc[i][j], ap[i], bp[j]);
        }
        __syncthreads();
    }

    float w0 = lw[0], w1 = lw[1], c0 = lb[0], c1 = lb[1];
#pragma unroll
    for (int i = 0; i < 8; i++) {
        int iloc = (quad >> 1) * 128 + ty * 8 + i;
        int jbase = (quad & 1) * 128 + tx * 8;
        size_t sidx = ((size_t)bchunk * 256 + iloc) * 256 + jbase;  // score index
        float4* op = (float4*)(out + sidx * 2);
#pragma unroll
        for (int p = 0; p < 4; p++) {
            float s0, s1;
            unpack2(acc[i][p], s0, s1);
            op[p] = make_float4(s0 * w0 + c0, s0 * w1 + c1,
                                s1 * w0 + c0, s1 * w1 + c1);
        }
    }
}

// ---------------- host launch ----------------
extern "C" void kernel_launch(void* const* d_in, const int* in_sizes, int n_in,
                              void* d_out, int out_size)
{
    const float* x      = (const float*)d_in[0];
    const float* Wt1    = (const float*)d_in[1];
    const float* bt1    = (const float*)d_in[2];
    const float* Wt2    = (const float*)d_in[3];
    const float* bt2    = (const float*)d_in[4];
    const float* W1     = (const float*)d_in[5];
    const float* b1     = (const float*)d_in[6];
    const float* W2     = (const float*)d_in[7];
    const float* b2     = (const float*)d_in[8];
    const float* matrix = (const float*)d_in[9];
    const float* lw     = (const float*)d_in[10];
    const float* lb     = (const float*)d_in[11];
    const void*  ei     = d_in[12];
    float* out = (float*)d_out;

    float *pWcat, *pbcat, *ph0, *pt1, *ph2a, *ph2b;
    cudaGetSymbolAddress((void**)&pWcat, g_Wcat);
    cudaGetSymbolAddress((void**)&pbcat, g_bcat);
    cudaGetSymbolAddress((void**)&ph0,  g_h0);
    cudaGetSymbolAddress((void**)&pt1,  g_t1);
    cudaGetSymbolAddress((void**)&ph2a, g_h2a);
    cudaGetSymbolAddress((void**)&ph2b, g_h2b);

    // graph prep (CSR build) + weight concat
    k_detect<<<1, 32>>>((const int*)ei);
    k_zero_cnt<<<NN / 256, 256>>>();
    k_wcat<<<(KIN * D1) / 256, 256>>>(Wt1, Wt2);
    k_bcat<<<2, 256>>>(bt1, bt2);
    k_count<<<EE / 256, 256>>>(ei);
    k_isq<<<NN / 256, 256>>>();
    k_scanA<<<256, 256>>>();
    k_scanB<<<1, 256>>>();
    k_scanC<<<256, 256>>>();
    k_fill<<<EE / 256, 256>>>(ei);

    // h0 = x @ Wcat + bcat        [65536,1024]@[1024,512]
    sgemm_k<1><<<dim3(4, 512), 256>>>(x, pWcat, pbcat, ph0, NN, D1, KIN);
    // t1 = h0 @ W1                [65536,512]@[512,512]
    sgemm_k<0><<<dim3(4, 512), 256>>>(ph0, W1, nullptr, pt1, NN, D1, D1);
    // h1 = relu(aggregate(t1) + b1)  -> reuse g_h0
    conv_agg<512, 1><<<(NN * 32) / 256, 256>>>(pt1, b1, ph0);
    // h2lin = h1 @ W2             [65536,512]@[512,128]
    sgemm_k<0><<<dim3(1, 512), 256>>>(ph0, W2, nullptr, ph2a, NN, DOUTD, D1);
    // h2 = aggregate(h2lin) + b2
    conv_agg<128, 0><<<(NN * 32) / 256, 256>>>(ph2a, b2, ph2b);
    // T = h2 @ matrix             [65536,128]@[128,128]  -> reuse g_h2a
    sgemm_k<0><<<dim3(1, 512), 256>>>(ph2b, matrix, nullptr, ph2a, NN, DOUTD, DOUTD);
    // scores + Linear(1,2)
    k_scores<<<1024, 256>>>(ph2a, ph2b, lw, lb, out);
}

// round 4
// speedup vs baseline: 3.6090x; 3.6090x over previous
#include <cuda_runtime.h>
#include <cuda_bf16.h>
#include <cstdint>

#define NN   65536
#define EE   1048576
#define D1   512
#define DOUTD 128
#define KIN  1024

// ---------------- device scratch (static: allocation-free) ----------------
__device__ __nv_bfloat16 g_xhi[(size_t)NN * KIN];     // 128 MB
__device__ __nv_bfloat16 g_xlo[(size_t)NN * KIN];     // 128 MB
__device__ __nv_bfloat16 g_WcatThi[D1 * KIN];
__device__ __nv_bfloat16 g_WcatTlo[D1 * KIN];
__device__ __nv_bfloat16 g_W1Thi[D1 * D1];
__device__ __nv_bfloat16 g_W1Tlo[D1 * D1];
__device__ __nv_bfloat16 g_W2Thi[DOUTD * D1];
__device__ __nv_bfloat16 g_W2Tlo[DOUTD * D1];
__device__ float g_bcat[D1];
__device__ __nv_bfloat16 g_h0hi[(size_t)NN * D1];     // 64 MB
__device__ __nv_bfloat16 g_h0lo[(size_t)NN * D1];     // 64 MB
__device__ float g_t1[(size_t)NN * D1];               // 128 MB
__device__ __nv_bfloat16 g_h1hi[(size_t)NN * D1];     // 64 MB
__device__ __nv_bfloat16 g_h1lo[(size_t)NN * D1];     // 64 MB
__device__ float g_h2lin[(size_t)NN * DOUTD];         // 32 MB
__device__ float g_h2[(size_t)NN * DOUTD];            // 32 MB
__device__ float g_Tm[(size_t)NN * DOUTD];            // 32 MB
__device__ float g_isq[NN];
__device__ int   g_cnt[NN];
__device__ int   g_rowptr[NN + 1];
__device__ int   g_cursor[NN];
__device__ int   g_bsum[256];
__device__ int   g_boff[256];
__device__ int   g_adj[EE];
__device__ int   g_is64;

// ---------------- tiny helpers ----------------
__device__ __forceinline__ unsigned pk(__nv_bfloat16 a, __nv_bfloat16 b) {
    return (unsigned)__bfloat16_as_ushort(a) | ((unsigned)__bfloat16_as_ushort(b) << 16);
}
__device__ __forceinline__ uint32_t smem_u32(const void* p) {
    uint32_t a;
    asm("{ .reg .u64 t; cvta.to.shared.u64 t, %1; cvt.u32.u64 %0, t; }" : "=r"(a) : "l"(p));
    return a;
}
__device__ __forceinline__ void ffma2(unsigned long long& d, unsigned long long a, unsigned long long b) {
    asm("fma.rn.f32x2 %0, %1, %2, %0;" : "+l"(d) : "l"(a), "l"(b));
}
__device__ __forceinline__ void unpack2(unsigned long long v, float& lo, float& hi) {
    asm("mov.b64 {%0, %1}, %2;" : "=f"(lo), "=f"(hi) : "l"(v));
}

#define LDSM_X4(r, ad) \
    asm volatile("ldmatrix.sync.aligned.m8n8.x4.shared.b16 {%0,%1,%2,%3}, [%4];" \
                 : "=r"((r)[0]), "=r"((r)[1]), "=r"((r)[2]), "=r"((r)[3]) : "r"(ad))
#define LDSM_X2(r, ad) \
    asm volatile("ldmatrix.sync.aligned.m8n8.x2.shared.b16 {%0,%1}, [%2];" \
                 : "=r"((r)[0]), "=r"((r)[1]) : "r"(ad))
#define MMA16816(c, a, b) \
    asm volatile("mma.sync.aligned.m16n8k16.row.col.f32.bf16.bf16.f32 " \
                 "{%0,%1,%2,%3}, {%4,%5,%6,%7}, {%8,%9}, {%0,%1,%2,%3};" \
                 : "+f"((c)[0]), "+f"((c)[1]), "+f"((c)[2]), "+f"((c)[3]) \
                 : "r"((a)[0]), "r"((a)[1]), "r"((a)[2]), "r"((a)[3]), \
                   "r"((b)[0]), "r"((b)[1]))

// edge_index dtype detect (JAX may hand us int32 despite int64 in source)
__global__ void k_detect(const int* __restrict__ ei) {
    if (blockIdx.x == 0 && threadIdx.x == 0) {
        int ok = 1;
#pragma unroll 1
        for (int i = 1; i < 512; i += 2)
            if (ei[i] != 0) { ok = 0; break; }
        g_is64 = ok;
    }
}
__device__ __forceinline__ int edge_at(const void* eiv, int idx) {
    if (g_is64) return (int)((const long long*)eiv)[idx];
    return ((const int*)eiv)[idx];
}

// ---------------- conversion / prep kernels ----------------
__global__ void k_convert_x(const float* __restrict__ x) {
    size_t i = ((size_t)blockIdx.x * 256 + threadIdx.x) * 4;
    float4 v = *(const float4*)(x + i);
    __nv_bfloat16 h0 = __float2bfloat16(v.x), h1 = __float2bfloat16(v.y);
    __nv_bfloat16 h2 = __float2bfloat16(v.z), h3 = __float2bfloat16(v.w);
    uint2 hv = { pk(h0, h1), pk(h2, h3) };
    __nv_bfloat16 l0 = __float2bfloat16(v.x - __bfloat162float(h0));
    __nv_bfloat16 l1 = __float2bfloat16(v.y - __bfloat162float(h1));
    __nv_bfloat16 l2 = __float2bfloat16(v.z - __bfloat162float(h2));
    __nv_bfloat16 l3 = __float2bfloat16(v.w - __bfloat162float(h3));
    uint2 lv = { pk(l0, l1), pk(l2, l3) };
    *(uint2*)(g_xhi + i) = hv;
    *(uint2*)(g_xlo + i) = lv;
}
__device__ __forceinline__ void split_store(float v, __nv_bfloat16* hi, __nv_bfloat16* lo, size_t i) {
    __nv_bfloat16 h = __float2bfloat16(v);
    hi[i] = h;
    lo[i] = __float2bfloat16(v - __bfloat162float(h));
}
__global__ void k_wcatT(const float* __restrict__ Wt1, const float* __restrict__ Wt2) {
    int idx = blockIdx.x * 256 + threadIdx.x;     // over [512 n][1024 k]
    int n = idx >> 10, k = idx & 1023;
    float v = (k < 256) ? Wt1[k * D1 + n] : Wt2[(k - 256) * D1 + n];
    split_store(v, g_WcatThi, g_WcatTlo, idx);
}
__global__ void k_w1T(const float* __restrict__ W1) {
    int idx = blockIdx.x * 256 + threadIdx.x;     // over [512 n][512 k]
    int n = idx >> 9, k = idx & 511;
    split_store(W1[k * D1 + n], g_W1Thi, g_W1Tlo, idx);
}
__global__ void k_w2T(const float* __restrict__ W2) {
    int idx = blockIdx.x * 256 + threadIdx.x;     // over [128 n][512 k]
    int n = idx >> 9, k = idx & 511;
    split_store(W2[k * DOUTD + n], g_W2Thi, g_W2Tlo, idx);
}
__global__ void k_bcat(const float* __restrict__ bt1, const float* __restrict__ bt2) {
    int j = blockIdx.x * blockDim.x + threadIdx.x;
    if (j < D1) g_bcat[j] = bt1[j] + bt2[j];
}
__global__ void k_zero_cnt() {
    int i = blockIdx.x * blockDim.x + threadIdx.x;
    if (i < NN) g_cnt[i] = 0;
}
__global__ void k_count(const void* __restrict__ eiv) {
    int e = blockIdx.x * blockDim.x + threadIdx.x;
    if (e >= EE) return;
    atomicAdd(&g_cnt[edge_at(eiv, EE + e)], 1);
}
__global__ void k_isq() {
    int i = blockIdx.x * blockDim.x + threadIdx.x;
    if (i < NN) g_isq[i] = rsqrtf((float)g_cnt[i] + 1.0f);
}
__global__ void k_scanA() {
    __shared__ int sh[256];
    int t = threadIdx.x, b = blockIdx.x;
    sh[t] = g_cnt[b * 256 + t];
    __syncthreads();
    for (int off = 128; off > 0; off >>= 1) {
        if (t < off) sh[t] += sh[t + off];
        __syncthreads();
    }
    if (t == 0) g_bsum[b] = sh[0];
}
__global__ void k_scanB() {
    __shared__ int sh[256];
    int t = threadIdx.x;
    int v = g_bsum[t];
    sh[t] = v;
    __syncthreads();
    for (int off = 1; off < 256; off <<= 1) {
        int x = (t >= off) ? sh[t - off] : 0;
        __syncthreads();
        sh[t] += x;
        __syncthreads();
    }
    g_boff[t] = sh[t] - v;
    if (t == 255) g_rowptr[NN] = sh[255];
}
__global__ void k_scanC() {
    __shared__ int sh[256];
    int t = threadIdx.x, b = blockIdx.x;
    int i = b * 256 + t;
    int v = g_cnt[i];
    sh[t] = v;
    __syncthreads();
    for (int off = 1; off < 256; off <<= 1) {
        int x = (t >= off) ? sh[t - off] : 0;
        __syncthreads();
        sh[t] += x;
        __syncthreads();
    }
    int excl = sh[t] - v + g_boff[b];
    g_rowptr[i] = excl;
    g_cursor[i] = excl;
}
__global__ void k_fill(const void* __restrict__ eiv) {
    int e = blockIdx.x * blockDim.x + threadIdx.x;
    if (e >= EE) return;
    int s = edge_at(eiv, e);
    int d = edge_at(eiv, EE + e);
    g_adj[atomicAdd(&g_cursor[d], 1)] = s;
}

// ---------------- warp-MMA bf16-split GEMM (base-ISA: ldmatrix + mma.sync) ----
// C[M,N] = (Ah+Al)[M,K] @ (Bh+Bl)^T[N,K] via 3 bf16 terms, fp32 accumulate.
// BM=64, BN=128, BK=64. 256 threads, 8 warps (2 m x 4 n), warp tile 32x32.
static constexpr uint32_t SOFF_AH = 0, SOFF_AL = 8192, SOFF_BH = 16384, SOFF_BL = 32768;
#define GEMM_SMEM 49152

template <int OUT_HILO, int BIAS>
__global__ __launch_bounds__(256, 2) void mma_gemm(
    const __nv_bfloat16* __restrict__ Ahi, const __nv_bfloat16* __restrict__ Alo,
    const __nv_bfloat16* __restrict__ Bhi, const __nv_bfloat16* __restrict__ Blo,
    const float* __restrict__ bias,
    float* __restrict__ Cf, __nv_bfloat16* __restrict__ Chi, __nv_bfloat16* __restrict__ Clo,
    int N, int K)
{
    extern __shared__ char sm[];
    uint32_t smb = smem_u32(sm);
    const int tid = threadIdx.x, wid = tid >> 5, lane = tid & 31;
    const int wm = wid & 1, wn = wid >> 1;
    const int m0 = blockIdx.y * 64, n0 = blockIdx.x * 128;

    float acc[2][4][4];
#pragma unroll
    for (int mi = 0; mi < 2; mi++)
#pragma unroll
        for (int ni = 0; ni < 4; ni++)
#pragma unroll
            for (int q = 0; q < 4; q++) acc[mi][ni][q] = 0.0f;

    // precomputed global-load indexing
    const int arow = tid >> 3, ac = tid & 7;     // + 256 stride per rep
    // precomputed ldmatrix addresses (offsets within tile, swizzled)
    uint32_t a_off[2], b_off[4];
#pragma unroll
    for (int mi = 0; mi < 2; mi++) {
        int row = wm * 32 + mi * 16 + (lane & 15);
        int kc = (lane >> 4) * 8;
        uint32_t off = (uint32_t)(row * 128 + kc * 2);
        a_off[mi] = off ^ ((off >> 3) & 0x70);
    }
#pragma unroll
    for (int ni = 0; ni < 4; ni++) {
        int row = wn * 32 + ni * 8 + (lane & 7);
        int kc = ((lane >> 3) & 1) * 8;
        uint32_t off = (uint32_t)(row * 128 + kc * 2);
        b_off[ni] = off ^ ((off >> 3) & 0x70);
    }

    for (int kt = 0; kt < K; kt += 64) {
        __syncthreads();
        {
            // A tiles: 64 rows x 128B -> 512 uint4, 2 per thread
#pragma unroll
            for (int r = 0; r < 2; r++) {
                int row = arow + 32 * r;
                uint32_t off = (uint32_t)(row * 128 + ac * 16);
                off ^= (off >> 3) & 0x70;
                const size_t gi = (size_t)(m0 + row) * K + kt + ac * 8;
                *(uint4*)(sm + SOFF_AH + off) = *(const uint4*)(Ahi + gi);
                *(uint4*)(sm + SOFF_AL + off) = *(const uint4*)(Alo + gi);
            }
            // B tiles: 128 rows -> 1024 uint4, 4 per thread
#pragma unroll
            for (int r = 0; r < 4; r++) {
                int row = arow + 32 * r;
                uint32_t off = (uint32_t)(row * 128 + ac * 16);
                off ^= (off >> 3) & 0x70;
                const size_t gi = (size_t)(n0 + row) * K + kt + ac * 8;
                *(uint4*)(sm + SOFF_BH + off) = *(const uint4*)(Bhi + gi);
                *(uint4*)(sm + SOFF_BL + off) = *(const uint4*)(Blo + gi);
            }
        }
        __syncthreads();
#pragma unroll
        for (int ks = 0; ks < 4; ks++) {
            const uint32_t kso = (uint32_t)(ks * 32);  // 16 bf16 = 32 bytes; swizzle preserves [4:0] and [6:5]^... (k within row: bits <7) — ks*32 only touches bits 5,6 which ARE swizzled
            // NOTE: k-offset bits 5..6 participate in swizzle; recompute properly:
            uint32_t ah[2][4], al[2][4], bh[4][2], bl[4][2];
#pragma unroll
            for (int mi = 0; mi < 2; mi++) {
                uint32_t off = a_off[mi] ^ 0;  // placeholder
                // recompute full: base row term constant, add ks*32 then swizzle delta
                // easiest: recompute from scratch
                int row = wm * 32 + mi * 16 + (lane & 15);
                int kc = ks * 16 + (lane >> 4) * 8;
                uint32_t o = (uint32_t)(row * 128 + kc * 2);
                o ^= (o >> 3) & 0x70;
                LDSM_X4(ah[mi], smb + SOFF_AH + o);
                LDSM_X4(al[mi], smb + SOFF_AL + o);
                (void)off; (void)kso;
            }
#pragma unroll
            for (int ni = 0; ni < 4; ni++) {
                int row = wn * 32 + ni * 8 + (lane & 7);
                int kc = ks * 16 + ((lane >> 3) & 1) * 8;
                uint32_t o = (uint32_t)(row * 128 + kc * 2);
                o ^= (o >> 3) & 0x70;
                LDSM_X2(bh[ni], smb + SOFF_BH + o);
                LDSM_X2(bl[ni], smb + SOFF_BL + o);
            }
#pragma unroll
            for (int mi = 0; mi < 2; mi++)
#pragma unroll
                for (int ni = 0; ni < 4; ni++) {
                    MMA16816(acc[mi][ni], ah[mi], bh[ni]);
                    MMA16816(acc[mi][ni], ah[mi], bl[ni]);
                    MMA16816(acc[mi][ni], al[mi], bh[ni]);
                }
        }
    }

    // epilogue: thread holds rows r, r+8; cols cq, cq+1 per (mi, ni)
    const int r = lane >> 2, cq = (lane & 3) * 2;
#pragma unroll
    for (int mi = 0; mi < 2; mi++) {
        const int mbase = m0 + wm * 32 + mi * 16 + r;
#pragma unroll
        for (int ni = 0; ni < 4; ni++) {
            const int col = n0 + wn * 32 + ni * 8 + cq;
            float b0 = 0.0f, b1 = 0.0f;
            if (BIAS) { float2 bb = *(const float2*)(bias + col); b0 = bb.x; b1 = bb.y; }
#pragma unroll
            for (int h = 0; h < 2; h++) {
                const int m = mbase + 8 * h;
                float v0 = acc[mi][ni][2 * h + 0] + b0;
                float v1 = acc[mi][ni][2 * h + 1] + b1;
                if (OUT_HILO) {
                    __nv_bfloat16 h0 = __float2bfloat16(v0), h1 = __float2bfloat16(v1);
                    *(unsigned*)(Chi + (size_t)m * N + col) = pk(h0, h1);
                    *(unsigned*)(Clo + (size_t)m * N + col) =
                        pk(__float2bfloat16(v0 - __bfloat162float(h0)),
                           __float2bfloat16(v1 - __bfloat162float(h1)));
                } else {
                    *(float2*)(Cf + (size_t)m * N + col) = make_float2(v0, v1);
                }
            }
        }
    }
}

// ---------------- CSR aggregate (float2 lanes) ----------------
// out[n] = sum_{s in adj(n)} h[s]*isq[s]*isq[n] + h[n]*isq[n]^2 + bias (+relu)
template <int D, int RELU, int OUT_HILO>
__global__ void conv_agg(const float* __restrict__ hin, const float* __restrict__ bias,
                         float* __restrict__ fout,
                         __nv_bfloat16* __restrict__ ohi, __nv_bfloat16* __restrict__ olo)
{
    int n = (blockIdx.x * blockDim.x + threadIdx.x) >> 5;
    int lane = threadIdx.x & 31;
    if (n >= NN) return;
    const int R = D / 64;
    float iq = g_isq[n];
    float2 acc[R];
    {
        float w = iq * iq;
        const float2* hp = (const float2*)(hin + (size_t)n * D);
#pragma unroll
        for (int i = 0; i < R; i++) {
            float2 v = hp[lane + 32 * i];
            acc[i].x = v.x * w; acc[i].y = v.y * w;
        }
    }
    int beg = g_rowptr[n], end = g_rowptr[n + 1];
    for (int k = beg; k < end; k++) {
        int s = g_adj[k];
        float w = g_isq[s] * iq;
        const float2* hs = (const float2*)(hin + (size_t)s * D);
#pragma unroll
        for (int i = 0; i < R; i++) {
            float2 v = hs[lane + 32 * i];
            acc[i].x += v.x * w; acc[i].y += v.y * w;
        }
    }
    const float2* bp = (const float2*)bias;
#pragma unroll
    for (int i = 0; i < R; i++) {
        float2 bb = bp[lane + 32 * i];
        float v0 = acc[i].x + bb.x, v1 = acc[i].y + bb.y;
        if (RELU) { v0 = fmaxf(v0, 0.0f); v1 = fmaxf(v1, 0.0f); }
        size_t col = 2 * (size_t)(lane + 32 * i);
        if (OUT_HILO) {
            __nv_bfloat16 h0 = __float2bfloat16(v0), h1 = __float2bfloat16(v1);
            *(unsigned*)(ohi + (size_t)n * D + col) = pk(h0, h1);
            *(unsigned*)(olo + (size_t)n * D + col) =
                pk(__float2bfloat16(v0 - __bfloat162float(h0)),
                   __float2bfloat16(v1 - __bfloat162float(h1)));
        } else {
            *(float2*)(fout + (size_t)n * D + col) = make_float2(v0, v1);
        }
    }
}

// ---------------- f32x2 SGEMM (small GEMM4) ----------------
template <int BIAS>
__global__ __launch_bounds__(256, 2) void sgemm_k(
    const float* __restrict__ A, const float* __restrict__ B,
    const float* __restrict__ bias, float* __restrict__ C,
    int M, int N, int K)
{
    __shared__ __align__(16) float As2[8][268];
    __shared__ __align__(16) float Bs[8][128];
    int tid = threadIdx.x;
    int bx = blockIdx.x, by = blockIdx.y;
    int ty = tid >> 4, tx = tid & 15;
    int arow = tid >> 1, acol4 = (tid & 1) * 4;
    int brow = tid >> 5, bcol4 = (tid & 31) * 4;
    const float* Ap = A + (size_t)(by * 128 + arow) * K;
    const float* Bp = B + (size_t)brow * N + bx * 128 + bcol4;
    unsigned long long acc[8][4];
#pragma unroll
    for (int i = 0; i < 8; i++)
#pragma unroll
        for (int j = 0; j < 4; j++) acc[i][j] = 0ull;
    for (int kt = 0; kt < K; kt += 8) {
        float4 av = *(const float4*)(Ap + kt + acol4);
        *(float2*)&As2[acol4 + 0][2 * arow] = make_float2(av.x, av.x);
        *(float2*)&As2[acol4 + 1][2 * arow] = make_float2(av.y, av.y);
        *(float2*)&As2[acol4 + 2][2 * arow] = make_float2(av.z, av.z);
        *(float2*)&As2[acol4 + 3][2 * arow] = make_float2(av.w, av.w);
        *(float4*)&Bs[brow][bcol4] = *(const float4*)(Bp + (size_t)kt * N);
        __syncthreads();
#pragma unroll
        for (int k = 0; k < 8; k++) {
            ulonglong2 a0 = *(const ulonglong2*)&As2[k][ty * 16 + 0];
            ulonglong2 a1 = *(const ulonglong2*)&As2[k][ty * 16 + 4];
            ulonglong2 a2 = *(const ulonglong2*)&As2[k][ty * 16 + 8];
            ulonglong2 a3 = *(const ulonglong2*)&As2[k][ty * 16 + 12];
            ulonglong2 b0 = *(const ulonglong2*)&Bs[k][tx * 8 + 0];
            ulonglong2 b1 = *(const ulonglong2*)&Bs[k][tx * 8 + 4];
            unsigned long long ap[8] = {a0.x, a0.y, a1.x, a1.y, a2.x, a2.y, a3.x, a3.y};
            unsigned long long bp[4] = {b0.x, b0.y, b1.x, b1.y};
#pragma unroll
            for (int i = 0; i < 8; i++)
#pragma unroll
                for (int j = 0; j < 4; j++) ffma2(acc[i][j], ap[i], bp[j]);
        }
        __syncthreads();
    }
#pragma unroll
    for (int i = 0; i < 8; i++) {
        float f[8];
#pragma unroll
        for (int j = 0; j < 4; j++) unpack2(acc[i][j], f[2 * j], f[2 * j + 1]);
        float* cp = C + (size_t)(by * 128 + ty * 8 + i) * N + bx * 128 + tx * 8;
        *(float4*)cp       = make_float4(f[0], f[1], f[2], f[3]);
        *(float4*)(cp + 4) = make_float4(f[4], f[5], f[6], f[7]);
    }
}

// ---------------- batched bilinear scores + Linear(1,2) ----------
__global__ __launch_bounds__(256, 2) void k_scores(
    const float* __restrict__ Tm, const float* __restrict__ Em,
    const float* __restrict__ lw, const float* __restrict__ lb,
    float* __restrict__ out)
{
    __shared__ __align__(16) float Ts2[16][260];
    __shared__ __align__(16) float Es[16][132];
    int bchunk = blockIdx.x >> 2;
    int quad = blockIdx.x & 3;
    int i0 = bchunk * 256 + (quad >> 1) * 128;
    int j0 = bchunk * 256 + (quad & 1) * 128;
    int tid = threadIdx.x;
    int ty = tid >> 4, tx = tid & 15;
    unsigned long long acc[8][4];
#pragma unroll
    for (int i = 0; i < 8; i++)
#pragma unroll
        for (int j = 0; j < 4; j++) acc[i][j] = 0ull;
    for (int k0 = 0; k0 < DOUTD; k0 += 16) {
#pragma unroll
        for (int r = 0; r < 2; r++) {
            int id = tid + 256 * r;
            int row = id >> 2;
            int c4 = (id & 3) * 4;
            float4 tv = *(const float4*)&Tm[(size_t)(i0 + row) * DOUTD + k0 + c4];
            *(float2*)&Ts2[c4 + 0][2 * row] = make_float2(tv.x, tv.x);
            *(float2*)&Ts2[c4 + 1][2 * row] = make_float2(tv.y, tv.y);
            *(float2*)&Ts2[c4 + 2][2 * row] = make_float2(tv.z, tv.z);
            *(float2*)&Ts2[c4 + 3][2 * row] = make_float2(tv.w, tv.w);
            float4 ev = *(const float4*)&Em[(size_t)(j0 + row) * DOUTD + k0 + c4];
            Es[c4 + 0][row] = ev.x;
            Es[c4 + 1][row] = ev.y;
            Es[c4 + 2][row] = ev.z;
            Es[c4 + 3][row] = ev.w;
        }
        __syncthreads();
#pragma unroll
        for (int k = 0; k < 16; k++) {
            ulonglong2 a0 = *(const ulonglong2*)&Ts2[k][ty * 16 + 0];
            ulonglong2 a1 = *(const ulonglong2*)&Ts2[k][ty * 16 + 4];
            ulonglong2 a2 = *(const ulonglong2*)&Ts2[k][ty * 16 + 8];
            ulonglong2 a3 = *(const ulonglong2*)&Ts2[k][ty * 16 + 12];
            ulonglong2 b0 = *(const ulonglong2*)&Es[k][tx * 8 + 0];
            ulonglong2 b1 = *(const ulonglong2*)&Es[k][tx * 8 + 4];
            unsigned long long ap[8] = {a0.x, a0.y, a1.x, a1.y, a2.x, a2.y, a3.x, a3.y};
            unsigned long long bp[4] = {b0.x, b0.y, b1.x, b1.y};
#pragma unroll
            for (int i = 0; i < 8; i++)
#pragma unroll
                for (int j = 0; j < 4; j++) ffma2(acc[i][j], ap[i], bp[j]);
        }
        __syncthreads();
    }
    float w0 = lw[0], w1 = lw[1], c0 = lb[0], c1 = lb[1];
#pragma unroll
    for (int i = 0; i < 8; i++) {
        int iloc = (quad >> 1) * 128 + ty * 8 + i;
        int jbase = (quad & 1) * 128 + tx * 8;
        size_t sidx = ((size_t)bchunk * 256 + iloc) * 256 + jbase;
        float4* op = (float4*)(out + sidx * 2);
#pragma unroll
        for (int p = 0; p < 4; p++) {
            float s0, s1;
            unpack2(acc[i][p], s0, s1);
            op[p] = make_float4(s0 * w0 + c0, s0 * w1 + c1,
                                s1 * w0 + c0, s1 * w1 + c1);
        }
    }
}

// ---------------- host launch ----------------
extern "C" void kernel_launch(void* const* d_in, const int* in_sizes, int n_in,
                              void* d_out, int out_size)
{
    const float* x      = (const float*)d_in[0];
    const float* Wt1    = (const float*)d_in[1];
    const float* bt1    = (const float*)d_in[2];
    const float* Wt2    = (const float*)d_in[3];
    const float* bt2    = (const float*)d_in[4];
    const float* W1     = (const float*)d_in[5];
    const float* b1     = (const float*)d_in[6];
    const float* W2     = (const float*)d_in[7];
    const float* b2     = (const float*)d_in[8];
    const float* matrix = (const float*)d_in[9];
    const float* lw     = (const float*)d_in[10];
    const float* lb     = (const float*)d_in[11];
    const void*  ei     = d_in[12];
    float* out = (float*)d_out;

    cudaFuncSetAttribute(mma_gemm<1, 1>, cudaFuncAttributeMaxDynamicSharedMemorySize, GEMM_SMEM);
    cudaFuncSetAttribute(mma_gemm<0, 0>, cudaFuncAttributeMaxDynamicSharedMemorySize, GEMM_SMEM);

    __nv_bfloat16 *pxhi, *pxlo, *pWchi, *pWclo, *pW1hi, *pW1lo, *pW2hi, *pW2lo;
    __nv_bfloat16 *ph0hi, *ph0lo, *ph1hi, *ph1lo;
    float *pbcat, *pt1, *ph2lin, *ph2, *pTm;
    cudaGetSymbolAddress((void**)&pxhi, g_xhi);
    cudaGetSymbolAddress((void**)&pxlo, g_xlo);
    cudaGetSymbolAddress((void**)&pWchi, g_WcatThi);
    cudaGetSymbolAddress((void**)&pWclo, g_WcatTlo);
    cudaGetSymbolAddress((void**)&pW1hi, g_W1Thi);
    cudaGetSymbolAddress((void**)&pW1lo, g_W1Tlo);
    cudaGetSymbolAddress((void**)&pW2hi, g_W2Thi);
    cudaGetSymbolAddress((void**)&pW2lo, g_W2Tlo);
    cudaGetSymbolAddress((void**)&ph0hi, g_h0hi);
    cudaGetSymbolAddress((void**)&ph0lo, g_h0lo);
    cudaGetSymbolAddress((void**)&ph1hi, g_h1hi);
    cudaGetSymbolAddress((void**)&ph1lo, g_h1lo);
    cudaGetSymbolAddress((void**)&pbcat, g_bcat);
    cudaGetSymbolAddress((void**)&pt1, g_t1);
    cudaGetSymbolAddress((void**)&ph2lin, g_h2lin);
    cudaGetSymbolAddress((void**)&ph2, g_h2);
    cudaGetSymbolAddress((void**)&pTm, g_Tm);

    // ordered so that ncu -s 5 -c 1 profiles the big GEMM1
    k_detect<<<1, 32>>>((const int*)ei);                         // 1
    k_convert_x<<<65536, 256>>>(x);                              // 2
    k_wcatT<<<2048, 256>>>(Wt1, Wt2);                            // 3
    k_bcat<<<2, 256>>>(bt1, bt2);                                // 4
    k_zero_cnt<<<256, 256>>>();                                  // 5
    // h0 = x @ Wcat + bcat  -> bf16 hi/lo                        // 6 (profiled)
    mma_gemm<1, 1><<<dim3(4, 1024), 256, GEMM_SMEM>>>(
        pxhi, pxlo, pWchi, pWclo, pbcat, nullptr, ph0hi, ph0lo, D1, KIN);
    k_w1T<<<1024, 256>>>(W1);
    k_w2T<<<256, 256>>>(W2);
    k_count<<<EE / 256, 256>>>(ei);
    k_isq<<<256, 256>>>();
    k_scanA<<<256, 256>>>();
    k_scanB<<<1, 256>>>();
    k_scanC<<<256, 256>>>();
    k_fill<<<EE / 256, 256>>>(ei);
    // t1 = h0 @ W1 (fp32)
    mma_gemm<0, 0><<<dim3(4, 1024), 256, GEMM_SMEM>>>(
        ph0hi, ph0lo, pW1hi, pW1lo, nullptr, pt1, nullptr, nullptr, D1, D1);
    // h1 = relu(agg(t1) + b1) -> bf16 hi/lo
    conv_agg<D1, 1, 1><<<NN * 32 / 256, 256>>>(pt1, b1, nullptr, ph1hi, ph1lo);
    // h2lin = h1 @ W2 (fp32)
    mma_gemm<0, 0><<<dim3(1, 1024), 256, GEMM_SMEM>>>(
        ph1hi, ph1lo, pW2hi, pW2lo, nullptr, ph2lin, nullptr, nullptr, DOUTD, D1);
    // h2 = agg(h2lin) + b2
    conv_agg<DOUTD, 0, 0><<<NN * 32 / 256, 256>>>(ph2lin, b2, ph2, nullptr, nullptr);
    // T = h2 @ matrix
    sgemm_k<0><<<dim3(1, 512), 256>>>(ph2, matrix, nullptr, pTm, NN, DOUTD, DOUTD);
    // scores + Linear(1,2)
    k_scores<<<1024, 256>>>(pTm, ph2, lw, lb, out);
}

// round 7
// speedup vs baseline: 4.5433x; 1.2589x over previous
#include <cuda_runtime.h>
#include <cuda_bf16.h>
#include <cstdint>

#define NN   65536
#define EE   1048576
#define D1   512
#define DOUTD 128
#define KIN  1024

// ---------------- device scratch (static: allocation-free) ----------------
__device__ __nv_bfloat16 g_xhi[(size_t)NN * KIN];     // 128 MB
__device__ __nv_bfloat16 g_xlo[(size_t)NN * KIN];     // 128 MB
__device__ __nv_bfloat16 g_WcatThi[D1 * KIN];
__device__ __nv_bfloat16 g_WcatTlo[D1 * KIN];
__device__ __nv_bfloat16 g_W1Thi[D1 * D1];
__device__ __nv_bfloat16 g_W1Tlo[D1 * D1];
__device__ __nv_bfloat16 g_W2Thi[DOUTD * D1];
__device__ __nv_bfloat16 g_W2Tlo[DOUTD * D1];
__device__ __nv_bfloat16 g_WmThi[DOUTD * DOUTD];
__device__ __nv_bfloat16 g_WmTlo[DOUTD * DOUTD];
__device__ float g_bcat[D1];
__device__ __nv_bfloat16 g_h0hi[(size_t)NN * D1];     // 64 MB
__device__ __nv_bfloat16 g_h0lo[(size_t)NN * D1];     // 64 MB
__device__ float g_t1[(size_t)NN * D1];               // 128 MB
__device__ __nv_bfloat16 g_h1hi[(size_t)NN * D1];     // 64 MB
__device__ __nv_bfloat16 g_h1lo[(size_t)NN * D1];     // 64 MB
__device__ float g_h2lin[(size_t)NN * DOUTD];         // 32 MB
__device__ __nv_bfloat16 g_h2hi[(size_t)NN * DOUTD];  // 16 MB
__device__ __nv_bfloat16 g_h2lo[(size_t)NN * DOUTD];  // 16 MB
__device__ __nv_bfloat16 g_Thi[(size_t)NN * DOUTD];   // 16 MB
__device__ __nv_bfloat16 g_Tlo[(size_t)NN * DOUTD];   // 16 MB
__device__ float g_isq[NN];
__device__ int   g_cnt[NN];
__device__ int   g_rowptr[NN + 1];
__device__ int   g_cursor[NN];
__device__ int   g_bsum[256];
__device__ int   g_boff[256];
__device__ int   g_adj[EE];
__device__ int   g_is64;

// ---------------- tiny helpers ----------------
__device__ __forceinline__ unsigned pk(__nv_bfloat16 a, __nv_bfloat16 b) {
    return (unsigned)__bfloat16_as_ushort(a) | ((unsigned)__bfloat16_as_ushort(b) << 16);
}
__device__ __forceinline__ uint32_t smem_u32(const void* p) {
    uint32_t a;
    asm("{ .reg .u64 t; cvta.to.shared.u64 t, %1; cvt.u32.u64 %0, t; }" : "=r"(a) : "l"(p));
    return a;
}

#define LDSM_X4(r, ad) \
    asm volatile("ldmatrix.sync.aligned.m8n8.x4.shared.b16 {%0,%1,%2,%3}, [%4];" \
                 : "=r"((r)[0]), "=r"((r)[1]), "=r"((r)[2]), "=r"((r)[3]) : "r"(ad))
#define LDSM_X2(r, ad) \
    asm volatile("ldmatrix.sync.aligned.m8n8.x2.shared.b16 {%0,%1}, [%2];" \
                 : "=r"((r)[0]), "=r"((r)[1]) : "r"(ad))
#define MMA16816(c, a, b) \
    asm volatile("mma.sync.aligned.m16n8k16.row.col.f32.bf16.bf16.f32 " \
                 "{%0,%1,%2,%3}, {%4,%5,%6,%7}, {%8,%9}, {%0,%1,%2,%3};" \
                 : "+f"((c)[0]), "+f"((c)[1]), "+f"((c)[2]), "+f"((c)[3]) \
                 : "r"((a)[0]), "r"((a)[1]), "r"((a)[2]), "r"((a)[3]), \
                   "r"((b)[0]), "r"((b)[1]))
#define CP16(sa, gp) \
    asm volatile("cp.async.cg.shared.global [%0], [%1], 16;" :: "r"(sa), "l"(gp))
#define CP_COMMIT() asm volatile("cp.async.commit_group;" ::: "memory")
#define CP_WAIT1()  asm volatile("cp.async.wait_group 1;" ::: "memory")
#define CP_WAIT0()  asm volatile("cp.async.wait_group 0;" ::: "memory")

__device__ __forceinline__ uint32_t swz(uint32_t o) { return o ^ ((o >> 3) & 0x70); }

// edge_index dtype detect: int64 values < 65536 have all odd 32-bit words zero.
__global__ void k_detect(const int* __restrict__ ei) {
    int lane = threadIdx.x;
    int bad = 0;
#pragma unroll
    for (int i = lane; i < 256; i += 32) bad |= (ei[2 * i + 1] != 0);
    unsigned m = __ballot_sync(0xFFFFFFFF, bad);
    if (lane == 0) g_is64 = (m == 0) ? 1 : 0;
}
__device__ __forceinline__ int edge_at(const void* eiv, int idx) {
    if (g_is64) return (int)((const long long*)eiv)[idx];
    return ((const int*)eiv)[idx];
}

// ---------------- conversion / prep kernels ----------------
__global__ void k_convert_x(const float* __restrict__ x) {
    size_t i = ((size_t)blockIdx.x * 256 + threadIdx.x) * 4;
    float4 v = *(const float4*)(x + i);
    __nv_bfloat16 h0 = __float2bfloat16(v.x), h1 = __float2bfloat16(v.y);
    __nv_bfloat16 h2 = __float2bfloat16(v.z), h3 = __float2bfloat16(v.w);
    uint2 hv = { pk(h0, h1), pk(h2, h3) };
    __nv_bfloat16 l0 = __float2bfloat16(v.x - __bfloat162float(h0));
    __nv_bfloat16 l1 = __float2bfloat16(v.y - __bfloat162float(h1));
    __nv_bfloat16 l2 = __float2bfloat16(v.z - __bfloat162float(h2));
    __nv_bfloat16 l3 = __float2bfloat16(v.w - __bfloat162float(h3));
    uint2 lv = { pk(l0, l1), pk(l2, l3) };
    *(uint2*)(g_xhi + i) = hv;
    *(uint2*)(g_xlo + i) = lv;
}
__device__ __forceinline__ void split_store(float v, __nv_bfloat16* hi, __nv_bfloat16* lo, size_t i) {
    __nv_bfloat16 h = __float2bfloat16(v);
    hi[i] = h;
    lo[i] = __float2bfloat16(v - __bfloat162float(h));
}
__global__ void k_wcatT(const float* __restrict__ Wt1, const float* __restrict__ Wt2) {
    int idx = blockIdx.x * 256 + threadIdx.x;     // [512 n][1024 k]
    int n = idx >> 10, k = idx & 1023;
    float v = (k < 256) ? Wt1[k * D1 + n] : Wt2[(k - 256) * D1 + n];
    split_store(v, g_WcatThi, g_WcatTlo, idx);
}
__global__ void k_w1T(const float* __restrict__ W1) {
    int idx = blockIdx.x * 256 + threadIdx.x;     // [512 n][512 k]
    int n = idx >> 9, k = idx & 511;
    split_store(W1[k * D1 + n], g_W1Thi, g_W1Tlo, idx);
}
__global__ void k_w2T(const float* __restrict__ W2) {
    int idx = blockIdx.x * 256 + threadIdx.x;     // [128 n][512 k]
    int n = idx >> 9, k = idx & 511;
    split_store(W2[k * DOUTD + n], g_W2Thi, g_W2Tlo, idx);
}
__global__ void k_wmT(const float* __restrict__ Wm) {
    int idx = blockIdx.x * 256 + threadIdx.x;     // [128 n][128 k]
    int n = idx >> 7, k = idx & 127;
    split_store(Wm[k * DOUTD + n], g_WmThi, g_WmTlo, idx);
}
__global__ void k_bcat(const float* __restrict__ bt1, const float* __restrict__ bt2) {
    int j = blockIdx.x * blockDim.x + threadIdx.x;
    if (j < D1) g_bcat[j] = bt1[j] + bt2[j];
}
__global__ void k_zero_cnt() {
    int i = blockIdx.x * blockDim.x + threadIdx.x;
    if (i < NN) g_cnt[i] = 0;
}
__global__ void k_count(const void* __restrict__ eiv) {
    int e = blockIdx.x * blockDim.x + threadIdx.x;
    if (e >= EE) return;
    atomicAdd(&g_cnt[edge_at(eiv, EE + e)], 1);
}
__global__ void k_isq() {
    int i = blockIdx.x * blockDim.x + threadIdx.x;
    if (i < NN) g_isq[i] = rsqrtf((float)g_cnt[i] + 1.0f);
}
__global__ void k_scanA() {
    __shared__ int sh[256];
    int t = threadIdx.x, b = blockIdx.x;
    sh[t] = g_cnt[b * 256 + t];
    __syncthreads();
    for (int off = 128; off > 0; off >>= 1) {
        if (t < off) sh[t] += sh[t + off];
        __syncthreads();
    }
    if (t == 0) g_bsum[b] = sh[0];
}
__global__ void k_scanB() {
    __shared__ int sh[256];
    int t = threadIdx.x;
    int v = g_bsum[t];
    sh[t] = v;
    __syncthreads();
    for (int off = 1; off < 256; off <<= 1) {
        int x = (t >= off) ? sh[t - off] : 0;
        __syncthreads();
        sh[t] += x;
        __syncthreads();
    }
    g_boff[t] = sh[t] - v;
    if (t == 255) g_rowptr[NN] = sh[255];
}
__global__ void k_scanC() {
    __shared__ int sh[256];
    int t = threadIdx.x, b = blockIdx.x;
    int i = b * 256 + t;
    int v = g_cnt[i];
    sh[t] = v;
    __syncthreads();
    for (int off = 1; off < 256; off <<= 1) {
        int x = (t >= off) ? sh[t - off] : 0;
        __syncthreads();
        sh[t] += x;
        __syncthreads();
    }
    int excl = sh[t] - v + g_boff[b];
    g_rowptr[i] = excl;
    g_cursor[i] = excl;
}
__global__ void k_fill(const void* __restrict__ eiv) {
    int e = blockIdx.x * blockDim.x + threadIdx.x;
    if (e >= EE) return;
    int s = edge_at(eiv, e);
    int d = edge_at(eiv, EE + e);
    g_adj[atomicAdd(&g_cursor[d], 1)] = s;
}

// ---------------- warp-MMA bf16-split GEMM, cp.async double-buffered ----------
// C[M,N] = (Ah+Al)[M,K] @ (Bh+Bl)^T[N,K] via 3 bf16 terms, fp32 accumulate.
// BM=64, BN=128, BK=64. 256 threads, 8 warps (2 m x 4 n), warp tile 32x32.
static constexpr uint32_t SOFF_AH = 0, SOFF_AL = 8192, SOFF_BH = 16384, SOFF_BL = 32768;
static constexpr uint32_t BUFSTRIDE = 49152;
#define GEMM_SMEM 98304

template <int OUT_HILO, int BIAS>
__global__ __launch_bounds__(256, 2) void mma_gemm(
    const __nv_bfloat16* __restrict__ Ahi, const __nv_bfloat16* __restrict__ Alo,
    const __nv_bfloat16* __restrict__ Bhi, const __nv_bfloat16* __restrict__ Blo,
    const float* __restrict__ bias,
    float* __restrict__ Cf, __nv_bfloat16* __restrict__ Chi, __nv_bfloat16* __restrict__ Clo,
    int N, int K)
{
    extern __shared__ char sm[];
    uint32_t smb = smem_u32(sm);
    const int tid = threadIdx.x, wid = tid >> 5, lane = tid & 31;
    const int wm = wid & 1, wn = wid >> 1;
    const int m0 = blockIdx.y * 64, n0 = blockIdx.x * 128;

    float acc[2][4][4];
#pragma unroll
    for (int mi = 0; mi < 2; mi++)
#pragma unroll
        for (int ni = 0; ni < 4; ni++)
#pragma unroll
            for (int q = 0; q < 4; q++) acc[mi][ni][q] = 0.0f;

    const int arow = tid >> 3, ac = tid & 7;
    const uint32_t soff = swz((uint32_t)(arow * 128 + ac * 16));

    auto issue = [&](int buf, int kt) {
        uint32_t sb = smb + (uint32_t)buf * BUFSTRIDE;
#pragma unroll
        for (int r = 0; r < 2; r++) {
            int row = arow + 32 * r;
            uint32_t off = soff + (uint32_t)(r * 32 * 128);
            const size_t gi = (size_t)(m0 + row) * K + kt + ac * 8;
            CP16(sb + SOFF_AH + off, Ahi + gi);
            CP16(sb + SOFF_AL + off, Alo + gi);
        }
#pragma unroll
        for (int r = 0; r < 4; r++) {
            int row = arow + 32 * r;
            uint32_t off = soff + (uint32_t)(r * 32 * 128);
            const size_t gi = (size_t)(n0 + row) * K + kt + ac * 8;
            CP16(sb + SOFF_BH + off, Bhi + gi);
            CP16(sb + SOFF_BL + off, Blo + gi);
        }
        CP_COMMIT();
    };

    issue(0, 0);
    const int C = K / 64;
    for (int c = 0; c < C; c++) {
        if (c + 1 < C) { issue((c + 1) & 1, (c + 1) * 64); CP_WAIT1(); }
        else CP_WAIT0();
        __syncthreads();
        uint32_t sbase = smb + (uint32_t)(c & 1) * BUFSTRIDE;
#pragma unroll
        for (int ks = 0; ks < 4; ks++) {
            uint32_t ah[2][4], al[2][4], bh[4][2], bl[4][2];
#pragma unroll
            for (int mi = 0; mi < 2; mi++) {
                int row = wm * 32 + mi * 16 + (lane & 15);
                int kc = ks * 16 + (lane >> 4) * 8;
                uint32_t o = swz((uint32_t)(row * 128 + kc * 2));
                LDSM_X4(ah[mi], sbase + SOFF_AH + o);
                LDSM_X4(al[mi], sbase + SOFF_AL + o);
            }
#pragma unroll
            for (int ni = 0; ni < 4; ni++) {
                int row = wn * 32 + ni * 8 + (lane & 7);
                int kc = ks * 16 + ((lane >> 3) & 1) * 8;
                uint32_t o = swz((uint32_t)(row * 128 + kc * 2));
                LDSM_X2(bh[ni], sbase + SOFF_BH + o);
                LDSM_X2(bl[ni], sbase + SOFF_BL + o);
            }
#pragma unroll
            for (int mi = 0; mi < 2; mi++)
#pragma unroll
                for (int ni = 0; ni < 4; ni++) {
                    MMA16816(acc[mi][ni], ah[mi], bh[ni]);
                    MMA16816(acc[mi][ni], ah[mi], bl[ni]);
                    MMA16816(acc[mi][ni], al[mi], bh[ni]);
                }
        }
        __syncthreads();
    }

    const int r = lane >> 2, cq = (lane & 3) * 2;
#pragma unroll
    for (int mi = 0; mi < 2; mi++) {
        const int mbase = m0 + wm * 32 + mi * 16 + r;
#pragma unroll
        for (int ni = 0; ni < 4; ni++) {
            const int col = n0 + wn * 32 + ni * 8 + cq;
            float b0 = 0.0f, b1 = 0.0f;
            if (BIAS) { float2 bb = *(const float2*)(bias + col); b0 = bb.x; b1 = bb.y; }
#pragma unroll
            for (int h = 0; h < 2; h++) {
                const int m = mbase + 8 * h;
                float v0 = acc[mi][ni][2 * h + 0] + b0;
                float v1 = acc[mi][ni][2 * h + 1] + b1;
                if (OUT_HILO) {
                    __nv_bfloat16 h0 = __float2bfloat16(v0), h1 = __float2bfloat16(v1);
                    *(unsigned*)(Chi + (size_t)m * N + col) = pk(h0, h1);
                    *(unsigned*)(Clo + (size_t)m * N + col) =
                        pk(__float2bfloat16(v0 - __bfloat162float(h0)),
                           __float2bfloat16(v1 - __bfloat162float(h1)));
                } else {
                    *(float2*)(Cf + (size_t)m * N + col) = make_float2(v0, v1);
                }
            }
        }
    }
}

// ---------------- bilinear scores via warp-MMA + Linear(1,2) ----------------
// per chunk b: S_b[256,256] = T_b[256,128] @ E_b[256,128]^T (bf16 3-term split)
// grid.x = 256 chunks * 8 subtiles (4 m-blocks x 2 n-blocks of 64x128)
__global__ __launch_bounds__(256, 2) void k_scores_mma(
    const __nv_bfloat16* __restrict__ Thi, const __nv_bfloat16* __restrict__ Tlo,
    const __nv_bfloat16* __restrict__ Ehi, const __nv_bfloat16* __restrict__ Elo,
    const float* __restrict__ lw, const float* __restrict__ lb,
    float* __restrict__ out)
{
    extern __shared__ char sm[];
    uint32_t smb = smem_u32(sm);
    const int tid = threadIdx.x, wid = tid >> 5, lane = tid & 31;
    const int wm = wid & 1, wn = wid >> 1;
    const int blk = blockIdx.x;
    const int chunk = blk >> 3, sub = blk & 7;
    const int mblk = sub >> 1, nblk = sub & 1;
    const int m0 = chunk * 256 + mblk * 64;
    const int n0 = chunk * 256 + nblk * 128;
    const int K = DOUTD;

    float acc[2][4][4];
#pragma unroll
    for (int mi = 0; mi < 2; mi++)
#pragma unroll
        for (int ni = 0; ni < 4; ni++)
#pragma unroll
            for (int q = 0; q < 4; q++) acc[mi][ni][q] = 0.0f;

    const int arow = tid >> 3, ac = tid & 7;
    const uint32_t soff = swz((uint32_t)(arow * 128 + ac * 16));

    for (int kt = 0; kt < K; kt += 64) {
        __syncthreads();
#pragma unroll
        for (int r = 0; r < 2; r++) {
            int row = arow + 32 * r;
            uint32_t off = soff + (uint32_t)(r * 32 * 128);
            const size_t gi = (size_t)(m0 + row) * K + kt + ac * 8;
            *(uint4*)(sm + SOFF_AH + off) = *(const uint4*)(Thi + gi);
            *(uint4*)(sm + SOFF_AL + off) = *(const uint4*)(Tlo + gi);
        }
#pragma unroll
        for (int r = 0; r < 4; r++) {
            int row = arow + 32 * r;
            uint32_t off = soff + (uint32_t)(r * 32 * 128);
            const size_t gi = (size_t)(n0 + row) * K + kt + ac * 8;
            *(uint4*)(sm + SOFF_BH + off) = *(const uint4*)(Ehi + gi);
            *(uint4*)(sm + SOFF_BL + off) = *(const uint4*)(Elo + gi);
        }
        __syncthreads();
#pragma unroll
        for (int ks = 0; ks < 4; ks++) {
            uint32_t ah[2][4], al[2][4], bh[4][2], bl[4][2];
#pragma unroll
            for (int mi = 0; mi < 2; mi++) {
                int row = wm * 32 + mi * 16 + (lane & 15);
                int kc = ks * 16 + (lane >> 4) * 8;
                uint32_t o = swz((uint32_t)(row * 128 + kc * 2));
                LDSM_X4(ah[mi], smb + SOFF_AH + o);
                LDSM_X4(al[mi], smb + SOFF_AL + o);
            }
#pragma unroll
            for (int ni = 0; ni < 4; ni++) {
                int row = wn * 32 + ni * 8 + (lane & 7);
                int kc = ks * 16 + ((lane >> 3) & 1) * 8;
                uint32_t o = swz((uint32_t)(row * 128 + kc * 2));
                LDSM_X2(bh[ni], smb + SOFF_BH + o);
                LDSM_X2(bl[ni], smb + SOFF_BL + o);
            }
#pragma unroll
            for (int mi = 0; mi < 2; mi++)
#pragma unroll
                for (int ni = 0; ni < 4; ni++) {
                    MMA16816(acc[mi][ni], ah[mi], bh[ni]);
                    MMA16816(acc[mi][ni], ah[mi], bl[ni]);
                    MMA16816(acc[mi][ni], al[mi], bh[ni]);
                }
        }
    }

    const float w0 = lw[0], w1 = lw[1], c0 = lb[0], c1 = lb[1];
    const int r = lane >> 2, cq = (lane & 3) * 2;
#pragma unroll
    for (int mi = 0; mi < 2; mi++) {
        const int irow = mblk * 64 + wm * 32 + mi * 16 + r;   // row within chunk
#pragma unroll
        for (int ni = 0; ni < 4; ni++) {
            const int jcol = nblk * 128 + wn * 32 + ni * 8 + cq;
#pragma unroll
            for (int h = 0; h < 2; h++) {
                float s0 = acc[mi][ni][2 * h + 0];
                float s1 = acc[mi][ni][2 * h + 1];
                size_t o = (((size_t)chunk * 256 + irow + 8 * h) * 256 + jcol) * 2;
                *(float4*)(out + o) = make_float4(s0 * w0 + c0, s0 * w1 + c1,
                                                  s1 * w0 + c0, s1 * w1 + c1);
            }
        }
    }
}

// ---------------- CSR aggregate (float2 lanes) ----------------
template <int D, int RELU, int OUT_HILO>
__global__ void conv_agg(const float* __restrict__ hin, const float* __restrict__ bias,
                         float* __restrict__ fout,
                         __nv_bfloat16* __restrict__ ohi, __nv_bfloat16* __restrict__ olo)
{
    int n = (blockIdx.x * blockDim.x + threadIdx.x) >> 5;
    int lane = threadIdx.x & 31;
    if (n >= NN) return;
    const int R = D / 64;
    float iq = g_isq[n];
    float2 acc[R];
    {
        float w = iq * iq;
        const float2* hp = (const float2*)(hin + (size_t)n * D);
#pragma unroll
        for (int i = 0; i < R; i++) {
            float2 v = hp[lane + 32 * i];
            acc[i].x = v.x * w; acc[i].y = v.y * w;
        }
    }
    int beg = g_rowptr[n], end = g_rowptr[n + 1];
    for (int k = beg; k < end; k++) {
        int s = g_adj[k];
        float w = g_isq[s] * iq;
        const float2* hs = (const float2*)(hin + (size_t)s * D);
#pragma unroll
        for (int i = 0; i < R; i++) {
            float2 v = hs[lane + 32 * i];
            acc[i].x += v.x * w; acc[i].y += v.y * w;
        }
    }
    const float2* bp = (const float2*)bias;
#pragma unroll
    for (int i = 0; i < R; i++) {
        float2 bb = bp[lane + 32 * i];
        float v0 = acc[i].x + bb.x, v1 = acc[i].y + bb.y;
        if (RELU) { v0 = fmaxf(v0, 0.0f); v1 = fmaxf(v1, 0.0f); }
        size_t col = 2 * (size_t)(lane + 32 * i);
        if (OUT_HILO) {
            __nv_bfloat16 h0 = __float2bfloat16(v0), h1 = __float2bfloat16(v1);
            *(unsigned*)(ohi + (size_t)n * D + col) = pk(h0, h1);
            *(unsigned*)(olo + (size_t)n * D + col) =
                pk(__float2bfloat16(v0 - __bfloat162float(h0)),
                   __float2bfloat16(v1 - __bfloat162float(h1)));
        } else {
            *(float2*)(fout + (size_t)n * D + col) = make_float2(v0, v1);
        }
    }
}

// ---------------- host launch ----------------
extern "C" void kernel_launch(void* const* d_in, const int* in_sizes, int n_in,
                              void* d_out, int out_size)
{
    const float* x      = (const float*)d_in[0];
    const float* Wt1    = (const float*)d_in[1];
    const float* bt1    = (const float*)d_in[2];
    const float* Wt2    = (const float*)d_in[3];
    const float* bt2    = (const float*)d_in[4];
    const float* W1     = (const float*)d_in[5];
    const float* b1     = (const float*)d_in[6];
    const float* W2     = (const float*)d_in[7];
    const float* b2     = (const float*)d_in[8];
    const float* matrix = (const float*)d_in[9];
    const float* lw     = (const float*)d_in[10];
    const float* lb     = (const float*)d_in[11];
    const void*  ei     = d_in[12];
    float* out = (float*)d_out;

    cudaFuncSetAttribute(mma_gemm<1, 1>, cudaFuncAttributeMaxDynamicSharedMemorySize, GEMM_SMEM);
    cudaFuncSetAttribute(mma_gemm<0, 0>, cudaFuncAttributeMaxDynamicSharedMemorySize, GEMM_SMEM);
    cudaFuncSetAttribute(mma_gemm<1, 0>, cudaFuncAttributeMaxDynamicSharedMemorySize, GEMM_SMEM);
    cudaFuncSetAttribute(k_scores_mma, cudaFuncAttributeMaxDynamicSharedMemorySize, BUFSTRIDE);

    __nv_bfloat16 *pxhi, *pxlo, *pWchi, *pWclo, *pW1hi, *pW1lo, *pW2hi, *pW2lo, *pWmhi, *pWmlo;
    __nv_bfloat16 *ph0hi, *ph0lo, *ph1hi, *ph1lo, *ph2hi, *ph2lo, *pThi, *pTlo;
    float *pbcat, *pt1, *ph2lin;
    cudaGetSymbolAddress((void**)&pxhi, g_xhi);
    cudaGetSymbolAddress((void**)&pxlo, g_xlo);
    cudaGetSymbolAddress((void**)&pWchi, g_WcatThi);
    cudaGetSymbolAddress((void**)&pWclo, g_WcatTlo);
    cudaGetSymbolAddress((void**)&pW1hi, g_W1Thi);
    cudaGetSymbolAddress((void**)&pW1lo, g_W1Tlo);
    cudaGetSymbolAddress((void**)&pW2hi, g_W2Thi);
    cudaGetSymbolAddress((void**)&pW2lo, g_W2Tlo);
    cudaGetSymbolAddress((void**)&pWmhi, g_WmThi);
    cudaGetSymbolAddress((void**)&pWmlo, g_WmTlo);
    cudaGetSymbolAddress((void**)&ph0hi, g_h0hi);
    cudaGetSymbolAddress((void**)&ph0lo, g_h0lo);
    cudaGetSymbolAddress((void**)&ph1hi, g_h1hi);
    cudaGetSymbolAddress((void**)&ph1lo, g_h1lo);
    cudaGetSymbolAddress((void**)&ph2hi, g_h2hi);
    cudaGetSymbolAddress((void**)&ph2lo, g_h2lo);
    cudaGetSymbolAddress((void**)&pThi, g_Thi);
    cudaGetSymbolAddress((void**)&pTlo, g_Tlo);
    cudaGetSymbolAddress((void**)&pbcat, g_bcat);
    cudaGetSymbolAddress((void**)&pt1, g_t1);
    cudaGetSymbolAddress((void**)&ph2lin, g_h2lin);

    // GEMM1 placed 4th so ncu (-s 5, with ~2 harness-injected launches) lands on it
    k_convert_x<<<65536, 256>>>(x);                              // 1
    k_wcatT<<<2048, 256>>>(Wt1, Wt2);                            // 2
    k_bcat<<<2, 256>>>(bt1, bt2);                                // 3
    // h0 = x @ Wcat + bcat -> bf16 hi/lo                        // 4 (profiled?)
    mma_gemm<1, 1><<<dim3(4, 1024), 256, GEMM_SMEM>>>(
        pxhi, pxlo, pWchi, pWclo, pbcat, nullptr, ph0hi, ph0lo, D1, KIN);
    k_detect<<<1, 32>>>((const int*)ei);
    k_w1T<<<1024, 256>>>(W1);
    k_w2T<<<256, 256>>>(W2);
    k_wmT<<<64, 256>>>(matrix);
    k_zero_cnt<<<256, 256>>>();
    k_count<<<EE / 256, 256>>>(ei);
    k_isq<<<256, 256>>>();
    k_scanA<<<256, 256>>>();
    k_scanB<<<1, 256>>>();
    k_scanC<<<256, 256>>>();
    k_fill<<<EE / 256, 256>>>(ei);
    // t1 = h0 @ W1 (fp32)
    mma_gemm<0, 0><<<dim3(4, 1024), 256, GEMM_SMEM>>>(
        ph0hi, ph0lo, pW1hi, pW1lo, nullptr, pt1, nullptr, nullptr, D1, D1);
    // h1 = relu(agg(t1) + b1) -> bf16 hi/lo
    conv_agg<D1, 1, 1><<<NN * 32 / 256, 256>>>(pt1, b1, nullptr, ph1hi, ph1lo);
    // h2lin = h1 @ W2 (fp32)
    mma_gemm<0, 0><<<dim3(1, 1024), 256, GEMM_SMEM>>>(
        ph1hi, ph1lo, pW2hi, pW2lo, nullptr, ph2lin, nullptr, nullptr, DOUTD, D1);
    // h2 = agg(h2lin) + b2 -> bf16 hi/lo
    conv_agg<DOUTD, 0, 1><<<NN * 32 / 256, 256>>>(ph2lin, b2, nullptr, ph2hi, ph2lo);
    // T = h2 @ matrix -> bf16 hi/lo
    mma_gemm<1, 0><<<dim3(1, 1024), 256, GEMM_SMEM>>>(
        ph2hi, ph2lo, pWmhi, pWmlo, nullptr, nullptr, pThi, pTlo, DOUTD, DOUTD);
    // scores + Linear(1,2)
    k_scores_mma<<<2048, 256, BUFSTRIDE>>>(pThi, pTlo, ph2hi, ph2lo, lw, lb, out);
}

// round 9
// speedup vs baseline: 5.1479x; 1.1331x over previous
#include <cuda_runtime.h>
#include <cuda_bf16.h>
#include <cstdint>

#define NN   65536
#define EE   1048576
#define D1   512
#define DOUTD 128
#define KIN  1024

// ---------------- device scratch (static: allocation-free) ----------------
__device__ __nv_bfloat16 g_xhi[(size_t)NN * KIN];     // 128 MB
__device__ __nv_bfloat16 g_xlo[(size_t)NN * KIN];     // 128 MB
__device__ float g_Wcatf[KIN * D1];                   // 2 MB fp32 concat [Wt1;Wt2]
__device__ float g_Wp[KIN * D1];                      // 2 MB fp32 W' = Wcat@W1
__device__ __nv_bfloat16 g_WpThi[D1 * KIN];           // 1 MB  W'^T split
__device__ __nv_bfloat16 g_WpTlo[D1 * KIN];
__device__ float g_bcat[D1];
__device__ float g_bprime[D1];
__device__ __nv_bfloat16 g_W2Thi[DOUTD * D1];
__device__ __nv_bfloat16 g_W2Tlo[DOUTD * D1];
__device__ __nv_bfloat16 g_WmThi[DOUTD * DOUTD];
__device__ __nv_bfloat16 g_WmTlo[DOUTD * DOUTD];
__device__ float g_t1[(size_t)NN * D1];               // 128 MB
__device__ __nv_bfloat16 g_h1hi[(size_t)NN * D1];     // 64 MB
__device__ __nv_bfloat16 g_h1lo[(size_t)NN * D1];     // 64 MB
__device__ float g_h2lin[(size_t)NN * DOUTD];         // 32 MB
__device__ __nv_bfloat16 g_h2hi[(size_t)NN * DOUTD];  // 16 MB
__device__ __nv_bfloat16 g_h2lo[(size_t)NN * DOUTD];  // 16 MB
__device__ __nv_bfloat16 g_Thi[(size_t)NN * DOUTD];   // 16 MB
__device__ __nv_bfloat16 g_Tlo[(size_t)NN * DOUTD];   // 16 MB
__device__ float g_isq[NN];
__device__ int   g_cnt[NN];
__device__ int   g_rowptr[NN + 1];
__device__ int   g_cursor[NN];
__device__ int   g_bsum[256];
__device__ int   g_boff[256];
__device__ int   g_adj[EE];
__device__ int   g_is64;

// ---------------- tiny helpers ----------------
__device__ __forceinline__ unsigned pk(__nv_bfloat16 a, __nv_bfloat16 b) {
    return (unsigned)__bfloat16_as_ushort(a) | ((unsigned)__bfloat16_as_ushort(b) << 16);
}
__device__ __forceinline__ uint32_t smem_u32(const void* p) {
    uint32_t a;
    asm("{ .reg .u64 t; cvta.to.shared.u64 t, %1; cvt.u32.u64 %0, t; }" : "=r"(a) : "l"(p));
    return a;
}
__device__ __forceinline__ void ffma2(unsigned long long& d, unsigned long long a, unsigned long long b) {
    asm("fma.rn.f32x2 %0, %1, %2, %0;" : "+l"(d) : "l"(a), "l"(b));
}
__device__ __forceinline__ void unpack2(unsigned long long v, float& lo, float& hi) {
    asm("mov.b64 {%0, %1}, %2;" : "=f"(lo), "=f"(hi) : "l"(v));
}

#define LDSM_X4(r, ad) \
    asm volatile("ldmatrix.sync.aligned.m8n8.x4.shared.b16 {%0,%1,%2,%3}, [%4];" \
                 : "=r"((r)[0]), "=r"((r)[1]), "=r"((r)[2]), "=r"((r)[3]) : "r"(ad))
#define LDSM_X2(r, ad) \
    asm volatile("ldmatrix.sync.aligned.m8n8.x2.shared.b16 {%0,%1}, [%2];" \
                 : "=r"((r)[0]), "=r"((r)[1]) : "r"(ad))
#define MMA16816(c, a, b) \
    asm volatile("mma.sync.aligned.m16n8k16.row.col.f32.bf16.bf16.f32 " \
                 "{%0,%1,%2,%3}, {%4,%5,%6,%7}, {%8,%9}, {%0,%1,%2,%3};" \
                 : "+f"((c)[0]), "+f"((c)[1]), "+f"((c)[2]), "+f"((c)[3]) \
                 : "r"((a)[0]), "r"((a)[1]), "r"((a)[2]), "r"((a)[3]), \
                   "r"((b)[0]), "r"((b)[1]))
#define CP16(sa, gp) \
    asm volatile("cp.async.cg.shared.global [%0], [%1], 16;" :: "r"(sa), "l"(gp))
#define CP_COMMIT() asm volatile("cp.async.commit_group;" ::: "memory")
#define CP_WAIT1()  asm volatile("cp.async.wait_group 1;" ::: "memory")
#define CP_WAIT0()  asm volatile("cp.async.wait_group 0;" ::: "memory")

__device__ __forceinline__ uint32_t swz(uint32_t o) { return o ^ ((o >> 3) & 0x70); }

// edge_index dtype detect: int64 values < 65536 have all odd 32-bit words zero.
__global__ void k_detect(const int* __restrict__ ei) {
    int lane = threadIdx.x;
    int bad = 0;
#pragma unroll
    for (int i = lane; i < 256; i += 32) bad |= (ei[2 * i + 1] != 0);
    unsigned m = __ballot_sync(0xFFFFFFFF, bad);
    if (lane == 0) g_is64 = (m == 0) ? 1 : 0;
}
__device__ __forceinline__ int edge_at(const void* eiv, int idx) {
    if (g_is64) return (int)((const long long*)eiv)[idx];
    return ((const int*)eiv)[idx];
}

__device__ __forceinline__ void split_store(float v, __nv_bfloat16* hi, __nv_bfloat16* lo, size_t i) {
    __nv_bfloat16 h = __float2bfloat16(v);
    hi[i] = h;
    lo[i] = __float2bfloat16(v - __bfloat162float(h));
}

// ---------------- fused prep 1: convert x to hi/lo, build fp32 Wcat, bcat ----
__global__ void k_prep1(const float* __restrict__ x,
                        const float* __restrict__ Wt1, const float* __restrict__ Wt2,
                        const float* __restrict__ bt1, const float* __restrict__ bt2)
{
    int b = blockIdx.x;
    if (b < 65536) {
        size_t i = ((size_t)b * 256 + threadIdx.x) * 4;
        float4 v = *(const float4*)(x + i);
        __nv_bfloat16 h0 = __float2bfloat16(v.x), h1 = __float2bfloat16(v.y);
        __nv_bfloat16 h2 = __float2bfloat16(v.z), h3 = __float2bfloat16(v.w);
        uint2 hv = { pk(h0, h1), pk(h2, h3) };
        __nv_bfloat16 l0 = __float2bfloat16(v.x - __bfloat162float(h0));
        __nv_bfloat16 l1 = __float2bfloat16(v.y - __bfloat162float(h1));
        __nv_bfloat16 l2 = __float2bfloat16(v.z - __bfloat162float(h2));
        __nv_bfloat16 l3 = __float2bfloat16(v.w - __bfloat162float(h3));
        uint2 lv = { pk(l0, l1), pk(l2, l3) };
        *(uint2*)(g_xhi + i) = hv;
        *(uint2*)(g_xlo + i) = lv;
    } else if (b < 65536 + 2048) {
        int idx = (b - 65536) * 256 + threadIdx.x;   // [1024 k][512 n] row-major
        int k = idx >> 9, n = idx & 511;
        g_Wcatf[idx] = (k < 256) ? Wt1[k * D1 + n] : Wt2[(k - 256) * D1 + n];
    } else {
#pragma unroll
        for (int r = 0; r < 2; r++) {
            int j = threadIdx.x + 256 * r;
            g_bcat[j] = bt1[j] + bt2[j];
        }
    }
}

// ---------------- prep 3: W'^T split hi/lo + b' = bcat@W1 ----------------
__global__ void k_prep3(const float* __restrict__ W1) {
    int b = blockIdx.x;
    if (b < 2048) {
        int idx = b * 256 + threadIdx.x;             // [512 n][1024 k]
        int k = idx & 1023;
        int n = idx >> 10;
        split_store(g_Wp[k * D1 + n], g_WpThi, g_WpTlo, (size_t)idx);
    } else {
#pragma unroll
        for (int r = 0; r < 2; r++) {
            int j = threadIdx.x + 256 * r;
            float s = 0.0f;
#pragma unroll 4
            for (int i = 0; i < D1; i++) s += g_bcat[i] * W1[i * D1 + j];
            g_bprime[j] = s;
        }
    }
}

__global__ void k_w2T(const float* __restrict__ W2) {
    int idx = blockIdx.x * 256 + threadIdx.x;     // [128 n][512 k]
    int n = idx >> 9, k = idx & 511;
    split_store(W2[k * DOUTD + n], g_W2Thi, g_W2Tlo, idx);
}
__global__ void k_wmT(const float* __restrict__ Wm) {
    int idx = blockIdx.x * 256 + threadIdx.x;     // [128 n][128 k]
    int n = idx >> 7, k = idx & 127;
    split_store(Wm[k * DOUTD + n], g_WmThi, g_WmTlo, idx);
}
__global__ void k_zero_cnt() {
    int i = blockIdx.x * blockDim.x + threadIdx.x;
    if (i < NN) g_cnt[i] = 0;
}
__global__ void k_count(const void* __restrict__ eiv) {
    int e = blockIdx.x * blockDim.x + threadIdx.x;
    if (e >= EE) return;
    atomicAdd(&g_cnt[edge_at(eiv, EE + e)], 1);
}
__global__ void k_isq() {
    int i = blockIdx.x * blockDim.x + threadIdx.x;
    if (i < NN) g_isq[i] = rsqrtf((float)g_cnt[i] + 1.0f);
}
__global__ void k_scanA() {
    __shared__ int sh[256];
    int t = threadIdx.x, b = blockIdx.x;
    sh[t] = g_cnt[b * 256 + t];
    __syncthreads();
    for (int off = 128; off > 0; off >>= 1) {
        if (t < off) sh[t] += sh[t + off];
        __syncthreads();
    }
    if (t == 0) g_bsum[b] = sh[0];
}
__global__ void k_scanB() {
    __shared__ int sh[256];
    int t = threadIdx.x;
    int v = g_bsum[t];
    sh[t] = v;
    __syncthreads();
    for (int off = 1; off < 256; off <<= 1) {
        int x = (t >= off) ? sh[t - off] : 0;
        __syncthreads();
        sh[t] += x;
        __syncthreads();
    }
    g_boff[t] = sh[t] - v;
    if (t == 255) g_rowptr[NN] = sh[255];
}
__global__ void k_scanC() {
    __shared__ int sh[256];
    int t = threadIdx.x, b = blockIdx.x;
    int i = b * 256 + t;
    int v = g_cnt[i];
    sh[t] = v;
    __syncthreads();
    for (int off = 1; off < 256; off <<= 1) {
        int x = (t >= off) ? sh[t - off] : 0;
        __syncthreads();
        sh[t] += x;
        __syncthreads();
    }
    int excl = sh[t] - v + g_boff[b];
    g_rowptr[i] = excl;
    g_cursor[i] = excl;
}
__global__ void k_fill(const void* __restrict__ eiv) {
    int e = blockIdx.x * blockDim.x + threadIdx.x;
    if (e >= EE) return;
    int s = edge_at(eiv, e);
    int d = edge_at(eiv, EE + e);
    g_adj[atomicAdd(&g_cursor[d], 1)] = s;
}

// ---------------- warp-MMA bf16-split GEMM, cp.async double-buffered ----------
// C[M,N] = (Ah+Al)[M,K] @ (Bh+Bl)^T[N,K] via 3 bf16 terms, fp32 accumulate.
// BM=64, BN=128, BK=64. 256 threads, 8 warps (2 m x 4 n), warp tile 32x32.
static constexpr uint32_t SOFF_AH = 0, SOFF_AL = 8192, SOFF_BH = 16384, SOFF_BL = 32768;
static constexpr uint32_t BUFSTRIDE = 49152;
#define GEMM_SMEM 98304

template <int OUT_HILO, int BIAS>
__global__ __launch_bounds__(256, 2) void mma_gemm(
    const __nv_bfloat16* __restrict__ Ahi, const __nv_bfloat16* __restrict__ Alo,
    const __nv_bfloat16* __restrict__ Bhi, const __nv_bfloat16* __restrict__ Blo,
    const float* __restrict__ bias,
    float* __restrict__ Cf, __nv_bfloat16* __restrict__ Chi, __nv_bfloat16* __restrict__ Clo,
    int N, int K)
{
    extern __shared__ char sm[];
    uint32_t smb = smem_u32(sm);
    const int tid = threadIdx.x, wid = tid >> 5, lane = tid & 31;
    const int wm = wid & 1, wn = wid >> 1;
    const int m0 = blockIdx.y * 64, n0 = blockIdx.x * 128;

    float acc[2][4][4];
#pragma unroll
    for (int mi = 0; mi < 2; mi++)
#pragma unroll
        for (int ni = 0; ni < 4; ni++)
#pragma unroll
            for (int q = 0; q < 4; q++) acc[mi][ni][q] = 0.0f;

    const int arow = tid >> 3, ac = tid & 7;
    const uint32_t soff = swz((uint32_t)(arow * 128 + ac * 16));

    auto issue = [&](int buf, int kt) {
        uint32_t sb = smb + (uint32_t)buf * BUFSTRIDE;
#pragma unroll
        for (int r = 0; r < 2; r++) {
            int row = arow + 32 * r;
            uint32_t off = soff + (uint32_t)(r * 32 * 128);
            const size_t gi = (size_t)(m0 + row) * K + kt + ac * 8;
            CP16(sb + SOFF_AH + off, Ahi + gi);
            CP16(sb + SOFF_AL + off, Alo + gi);
        }
#pragma unroll
        for (int r = 0; r < 4; r++) {
            int row = arow + 32 * r;
            uint32_t off = soff + (uint32_t)(r * 32 * 128);
            const size_t gi = (size_t)(n0 + row) * K + kt + ac * 8;
            CP16(sb + SOFF_BH + off, Bhi + gi);
            CP16(sb + SOFF_BL + off, Blo + gi);
        }
        CP_COMMIT();
    };

    issue(0, 0);
    const int C = K / 64;
    for (int c = 0; c < C; c++) {
        if (c + 1 < C) { issue((c + 1) & 1, (c + 1) * 64); CP_WAIT1(); }
        else CP_WAIT0();
        __syncthreads();
        uint32_t sbase = smb + (uint32_t)(c & 1) * BUFSTRIDE;
#pragma unroll
        for (int ks = 0; ks < 4; ks++) {
            uint32_t ah[2][4], al[2][4], bh[4][2], bl[4][2];
#pragma unroll
            for (int mi = 0; mi < 2; mi++) {
                int row = wm * 32 + mi * 16 + (lane & 15);
                int kc = ks * 16 + (lane >> 4) * 8;
                uint32_t o = swz((uint32_t)(row * 128 + kc * 2));
                LDSM_X4(ah[mi], sbase + SOFF_AH + o);
                LDSM_X4(al[mi], sbase + SOFF_AL + o);
            }
#pragma unroll
            for (int ni = 0; ni < 4; ni++) {
                int row = wn * 32 + ni * 8 + (lane & 7);
                int kc = ks * 16 + ((lane >> 3) & 1) * 8;
                uint32_t o = swz((uint32_t)(row * 128 + kc * 2));
                LDSM_X2(bh[ni], sbase + SOFF_BH + o);
                LDSM_X2(bl[ni], sbase + SOFF_BL + o);
            }
#pragma unroll
            for (int mi = 0; mi < 2; mi++)
#pragma unroll
                for (int ni = 0; ni < 4; ni++) {
                    MMA16816(acc[mi][ni], ah[mi], bh[ni]);
                    MMA16816(acc[mi][ni], ah[mi], bl[ni]);
                    MMA16816(acc[mi][ni], al[mi], bh[ni]);
                }
        }
        __syncthreads();
    }

    const int r = lane >> 2, cq = (lane & 3) * 2;
#pragma unroll
    for (int mi = 0; mi < 2; mi++) {
        const int mbase = m0 + wm * 32 + mi * 16 + r;
#pragma unroll
        for (int ni = 0; ni < 4; ni++) {
            const int col = n0 + wn * 32 + ni * 8 + cq;
            float b0 = 0.0f, b1 = 0.0f;
            if (BIAS) { float2 bb = *(const float2*)(bias + col); b0 = bb.x; b1 = bb.y; }
#pragma unroll
            for (int h = 0; h < 2; h++) {
                const int m = mbase + 8 * h;
                float v0 = acc[mi][ni][2 * h + 0] + b0;
                float v1 = acc[mi][ni][2 * h + 1] + b1;
                if (OUT_HILO) {
                    __nv_bfloat16 h0 = __float2bfloat16(v0), h1 = __float2bfloat16(v1);
                    *(unsigned*)(Chi + (size_t)m * N + col) = pk(h0, h1);
                    *(unsigned*)(Clo + (size_t)m * N + col) =
                        pk(__float2bfloat16(v0 - __bfloat162float(h0)),
                           __float2bfloat16(v1 - __bfloat162float(h1)));
                } else {
                    *(float2*)(Cf + (size_t)m * N + col) = make_float2(v0, v1);
                }
            }
        }
    }
}

// ---------------- bilinear scores via warp-MMA + Linear(1,2) ----------------
__global__ __launch_bounds__(256, 2) void k_scores_mma(
    const __nv_bfloat16* __restrict__ Thi, const __nv_bfloat16* __restrict__ Tlo,
    const __nv_bfloat16* __restrict__ Ehi, const __nv_bfloat16* __restrict__ Elo,
    const float* __restrict__ lw, const float* __restrict__ lb,
    float* __restrict__ out)
{
    extern __shared__ char sm[];
    uint32_t smb = smem_u32(sm);
    const int tid = threadIdx.x, wid = tid >> 5, lane = tid & 31;
    const int wm = wid & 1, wn = wid >> 1;
    const int blk = blockIdx.x;
    const int chunk = blk >> 3, sub = blk & 7;
    const int mblk = sub >> 1, nblk = sub & 1;
    const int m0 = chunk * 256 + mblk * 64;
    const int n0 = chunk * 256 + nblk * 128;
    const int K = DOUTD;

    float acc[2][4][4];
#pragma unroll
    for (int mi = 0; mi < 2; mi++)
#pragma unroll
        for (int ni = 0; ni < 4; ni++)
#pragma unroll
            for (int q = 0; q < 4; q++) acc[mi][ni][q] = 0.0f;

    const int arow = tid >> 3, ac = tid & 7;
    const uint32_t soff = swz((uint32_t)(arow * 128 + ac * 16));

    for (int kt = 0; kt < K; kt += 64) {
        __syncthreads();
#pragma unroll
        for (int r = 0; r < 2; r++) {
            int row = arow + 32 * r;
            uint32_t off = soff + (uint32_t)(r * 32 * 128);
            const size_t gi = (size_t)(m0 + row) * K + kt + ac * 8;
            *(uint4*)(sm + SOFF_AH + off) = *(const uint4*)(Thi + gi);
            *(uint4*)(sm + SOFF_AL + off) = *(const uint4*)(Tlo + gi);
        }
#pragma unroll
        for (int r = 0; r < 4; r++) {
            int row = arow + 32 * r;
            uint32_t off = soff + (uint32_t)(r * 32 * 128);
            const size_t gi = (size_t)(n0 + row) * K + kt + ac * 8;
            *(uint4*)(sm + SOFF_BH + off) = *(const uint4*)(Ehi + gi);
            *(uint4*)(sm + SOFF_BL + off) = *(const uint4*)(Elo + gi);
        }
        __syncthreads();
#pragma unroll
        for (int ks = 0; ks < 4; ks++) {
            uint32_t ah[2][4], al[2][4], bh[4][2], bl[4][2];
#pragma unroll
            for (int mi = 0; mi < 2; mi++) {
                int row = wm * 32 + mi * 16 + (lane & 15);
                int kc = ks * 16 + (lane >> 4) * 8;
                uint32_t o = swz((uint32_t)(row * 128 + kc * 2));
                LDSM_X4(ah[mi], smb + SOFF_AH + o);
                LDSM_X4(al[mi], smb + SOFF_AL + o);
            }
#pragma unroll
            for (int ni = 0; ni < 4; ni++) {
                int row = wn * 32 + ni * 8 + (lane & 7);
                int kc = ks * 16 + ((lane >> 3) & 1) * 8;
                uint32_t o = swz((uint32_t)(row * 128 + kc * 2));
                LDSM_X2(bh[ni], smb + SOFF_BH + o);
                LDSM_X2(bl[ni], smb + SOFF_BL + o);
            }
#pragma unroll
            for (int mi = 0; mi < 2; mi++)
#pragma unroll
                for (int ni = 0; ni < 4; ni++) {
                    MMA16816(acc[mi][ni], ah[mi], bh[ni]);
                    MMA16816(acc[mi][ni], ah[mi], bl[ni]);
                    MMA16816(acc[mi][ni], al[mi], bh[ni]);
                }
        }
    }

    const float w0 = lw[0], w1 = lw[1], c0 = lb[0], c1 = lb[1];
    const int r = lane >> 2, cq = (lane & 3) * 2;
#pragma unroll
    for (int mi = 0; mi < 2; mi++) {
        const int irow = mblk * 64 + wm * 32 + mi * 16 + r;
#pragma unroll
        for (int ni = 0; ni < 4; ni++) {
            const int jcol = nblk * 128 + wn * 32 + ni * 8 + cq;
#pragma unroll
            for (int h = 0; h < 2; h++) {
                float s0 = acc[mi][ni][2 * h + 0];
                float s1 = acc[mi][ni][2 * h + 1];
                size_t o = (((size_t)chunk * 256 + irow + 8 * h) * 256 + jcol) * 2;
                *(float4*)(out + o) = make_float4(s0 * w0 + c0, s0 * w1 + c1,
                                                  s1 * w0 + c0, s1 * w1 + c1);
            }
        }
    }
}

// ---------------- CSR aggregate, column-panel version (L2 resident) ----------
// out[n, col0:col0+DSUB] over full row stride D.
template <int D, int DSUB, int RELU, int OUT_HILO>
__global__ void conv_agg(const float* __restrict__ hin, const float* __restrict__ bias,
                         float* __restrict__ fout,
                         __nv_bfloat16* __restrict__ ohi, __nv_bfloat16* __restrict__ olo,
                         int col0)
{
    int n = (blockIdx.x * blockDim.x + threadIdx.x) >> 5;
    int lane = threadIdx.x & 31;
    if (n >= NN) return;
    const int R = DSUB / 64;
    float iq = g_isq[n];
    float2 acc[R];
    {
        float w = iq * iq;
        const float2* hp = (const float2*)(hin + (size_t)n * D + col0);
#pragma unroll
        for (int i = 0; i < R; i++) {
            float2 v = hp[lane + 32 * i];
            acc[i].x = v.x * w; acc[i].y = v.y * w;
        }
    }
    int beg = g_rowptr[n], end = g_rowptr[n + 1];
    for (int k = beg; k < end; k++) {
        int s = g_adj[k];
        float w = g_isq[s] * iq;
        const float2* hs = (const float2*)(hin + (size_t)s * D + col0);
#pragma unroll
        for (int i = 0; i < R; i++) {
            float2 v = hs[lane + 32 * i];
            acc[i].x += v.x * w; acc[i].y += v.y * w;
        }
    }
    const float2* bp = (const float2*)(bias + col0);
#pragma unroll
    for (int i = 0; i < R; i++) {
        float2 bb = bp[lane + 32 * i];
        float v0 = acc[i].x + bb.x, v1 = acc[i].y + bb.y;
        if (RELU) { v0 = fmaxf(v0, 0.0f); v1 = fmaxf(v1, 0.0f); }
        size_t col = (size_t)col0 + 2 * (size_t)(lane + 32 * i);
        if (OUT_HILO) {
            __nv_bfloat16 h0 = __float2bfloat16(v0), h1 = __float2bfloat16(v1);
            *(unsigned*)(ohi + (size_t)n * D + col) = pk(h0, h1);
            *(unsigned*)(olo + (size_t)n * D + col) =
                pk(__float2bfloat16(v0 - __bfloat162float(h0)),
                   __float2bfloat16(v1 - __bfloat162float(h1)));
        } else {
            *(float2*)(fout + (size_t)n * D + col) = make_float2(v0, v1);
        }
    }
}

// ---------------- f32x2 SGEMM (W' = Wcat@W1, tiny) ----------------
__global__ __launch_bounds__(256, 2) void sgemm_k(
    const float* __restrict__ A, const float* __restrict__ B,
    float* __restrict__ C, int M, int N, int K)
{
    __shared__ __align__(16) float As2[8][268];
    __shared__ __align__(16) float Bs[8][128];
    int tid = threadIdx.x;
    int bx = blockIdx.x, by = blockIdx.y;
    int ty = tid >> 4, tx = tid & 15;
    int arow = tid >> 1, acol4 = (tid & 1) * 4;
    int brow = tid >> 5, bcol4 = (tid & 31) * 4;
    const float* Ap = A + (size_t)(by * 128 + arow) * K;
    const float* Bp = B + (size_t)brow * N + bx * 128 + bcol4;
    unsigned long long acc[8][4];
#pragma unroll
    for (int i = 0; i < 8; i++)
#pragma unroll
        for (int j = 0; j < 4; j++) acc[i][j] = 0ull;
    for (int kt = 0; kt < K; kt += 8) {
        float4 av = *(const float4*)(Ap + kt + acol4);
        *(float2*)&As2[acol4 + 0][2 * arow] = make_float2(av.x, av.x);
        *(float2*)&As2[acol4 + 1][2 * arow] = make_float2(av.y, av.y);
        *(float2*)&As2[acol4 + 2][2 * arow] = make_float2(av.z, av.z);
        *(float2*)&As2[acol4 + 3][2 * arow] = make_float2(av.w, av.w);
        *(float4*)&Bs[brow][bcol4] = *(const float4*)(Bp + (size_t)kt * N);
        __syncthreads();
#pragma unroll
        for (int k = 0; k < 8; k++) {
            ulonglong2 a0 = *(const ulonglong2*)&As2[k][ty * 16 + 0];
            ulonglong2 a1 = *(const ulonglong2*)&As2[k][ty * 16 + 4];
            ulonglong2 a2 = *(const ulonglong2*)&As2[k][ty * 16 + 8];
            ulonglong2 a3 = *(const ulonglong2*)&As2[k][ty * 16 + 12];
            ulonglong2 b0 = *(const ulonglong2*)&Bs[k][tx * 8 + 0];
            ulonglong2 b1 = *(const ulonglong2*)&Bs[k][tx * 8 + 4];
            unsigned long long ap[8] = {a0.x, a0.y, a1.x, a1.y, a2.x, a2.y, a3.x, a3.y};
            unsigned long long bp[4] = {b0.x, b0.y, b1.x, b1.y};
#pragma unroll
            for (int i = 0; i < 8; i++)
#pragma unroll
                for (int j = 0; j < 4; j++) ffma2(acc[i][j], ap[i], bp[j]);
        }
        __syncthreads();
    }
#pragma unroll
    for (int i = 0; i < 8; i++) {
        float f[8];
#pragma unroll
        for (int j = 0; j < 4; j++) unpack2(acc[i][j], f[2 * j], f[2 * j + 1]);
        float* cp = C + (size_t)(by * 128 + ty * 8 + i) * N + bx * 128 + tx * 8;
        *(float4*)cp       = make_float4(f[0], f[1], f[2], f[3]);
        *(float4*)(cp + 4) = make_float4(f[4], f[5], f[6], f[7]);
    }
}

// ---------------- host launch ----------------
extern "C" void kernel_launch(void* const* d_in, const int* in_sizes, int n_in,
                              void* d_out, int out_size)
{
    const float* x      = (const float*)d_in[0];
    const float* Wt1    = (const float*)d_in[1];
    const float* bt1    = (const float*)d_in[2];
    const float* Wt2    = (const float*)d_in[3];
    const float* bt2    = (const float*)d_in[4];
    const float* W1     = (const float*)d_in[5];
    const float* b1     = (const float*)d_in[6];
    const float* W2     = (const float*)d_in[7];
    const float* b2     = (const float*)d_in[8];
    const float* matrix = (const float*)d_in[9];
    const float* lw     = (const float*)d_in[10];
    const float* lb     = (const float*)d_in[11];
    const void*  ei     = d_in[12];
    float* out = (float*)d_out;

    cudaFuncSetAttribute(mma_gemm<0, 1>, cudaFuncAttributeMaxDynamicSharedMemorySize, GEMM_SMEM);
    cudaFuncSetAttribute(mma_gemm<0, 0>, cudaFuncAttributeMaxDynamicSharedMemorySize, GEMM_SMEM);
    cudaFuncSetAttribute(mma_gemm<1, 0>, cudaFuncAttributeMaxDynamicSharedMemorySize, GEMM_SMEM);
    cudaFuncSetAttribute(k_scores_mma, cudaFuncAttributeMaxDynamicSharedMemorySize, BUFSTRIDE);

    __nv_bfloat16 *pxhi, *pxlo, *pWphi, *pWplo, *pW2hi, *pW2lo, *pWmhi, *pWmlo;
    __nv_bfloat16 *ph1hi, *ph1lo, *ph2hi, *ph2lo, *pThi, *pTlo;
    float *pWcatf, *pWp, *pbprime, *pt1, *ph2lin;
    cudaGetSymbolAddress((void**)&pxhi, g_xhi);
    cudaGetSymbolAddress((void**)&pxlo, g_xlo);
    cudaGetSymbolAddress((void**)&pWcatf, g_Wcatf);
    cudaGetSymbolAddress((void**)&pWp, g_Wp);
    cudaGetSymbolAddress((void**)&pWphi, g_WpThi);
    cudaGetSymbolAddress((void**)&pWplo, g_WpTlo);
    cudaGetSymbolAddress((void**)&pbprime, g_bprime);
    cudaGetSymbolAddress((void**)&pW2hi, g_W2Thi);
    cudaGetSymbolAddress((void**)&pW2lo, g_W2Tlo);
    cudaGetSymbolAddress((void**)&pWmhi, g_WmThi);
    cudaGetSymbolAddress((void**)&pWmlo, g_WmTlo);
    cudaGetSymbolAddress((void**)&ph1hi, g_h1hi);
    cudaGetSymbolAddress((void**)&ph1lo, g_h1lo);
    cudaGetSymbolAddress((void**)&ph2hi, g_h2hi);
    cudaGetSymbolAddress((void**)&ph2lo, g_h2lo);
    cudaGetSymbolAddress((void**)&pThi, g_Thi);
    cudaGetSymbolAddress((void**)&pTlo, g_Tlo);
    cudaGetSymbolAddress((void**)&pt1, g_t1);
    cudaGetSymbolAddress((void**)&ph2lin, g_h2lin);

    // 1: convert x + Wcat fp32 + bcat (fused)
    k_prep1<<<65536 + 2048 + 1, 256>>>(x, Wt1, Wt2, bt1, bt2);
    // 2: W' = Wcat @ W1 (fp32, exact)
    sgemm_k<<<dim3(4, 8), 256>>>(pWcatf, W1, pWp, KIN, D1, D1);
    // 3: split W'^T -> hi/lo, b' = bcat @ W1
    k_prep3<<<2049, 256>>>(W1);
    // 4 (profiled): t1 = x @ W' + b'   [65536,1024]@[1024,512] (replaces GEMM1+GEMM2)
    mma_gemm<0, 1><<<dim3(4, 1024), 256, GEMM_SMEM>>>(
        pxhi, pxlo, pWphi, pWplo, pbprime, pt1, nullptr, nullptr, D1, KIN);
    // graph prep (CSR) + remaining weight splits, overlap-friendly
    k_detect<<<1, 32>>>((const int*)ei);
    k_w2T<<<256, 256>>>(W2);
    k_wmT<<<64, 256>>>(matrix);
    k_zero_cnt<<<256, 256>>>();
    k_count<<<EE / 256, 256>>>(ei);
    k_isq<<<256, 256>>>();
    k_scanA<<<256, 256>>>();
    k_scanB<<<1, 256>>>();
    k_scanC<<<256, 256>>>();
    k_fill<<<EE / 256, 256>>>(ei);
    // h1 = relu(agg(t1) + b1) -> bf16 hi/lo, two L2-resident column passes
    conv_agg<D1, 256, 1, 1><<<NN * 32 / 256, 256>>>(pt1, b1, nullptr, ph1hi, ph1lo, 0);
    conv_agg<D1, 256, 1, 1><<<NN * 32 / 256, 256>>>(pt1, b1, nullptr, ph1hi, ph1lo, 256);
    // h2lin = h1 @ W2 (fp32)
    mma_gemm<0, 0><<<dim3(1, 1024), 256, GEMM_SMEM>>>(
        ph1hi, ph1lo, pW2hi, pW2lo, nullptr, ph2lin, nullptr, nullptr, DOUTD, D1);
    // h2 = agg(h2lin) + b2 -> bf16 hi/lo (32 MB working set, single pass)
    conv_agg<DOUTD, 128, 0, 1><<<NN * 32 / 256, 256>>>(ph2lin, b2, nullptr, ph2hi, ph2lo, 0);
    // T = h2 @ matrix -> bf16 hi/lo
    mma_gemm<1, 0><<<dim3(1, 1024), 256, GEMM_SMEM>>>(
        ph2hi, ph2lo, pWmhi, pWmlo, nullptr, nullptr, pThi, pTlo, DOUTD, DOUTD);
    // scores + Linear(1,2)
    k_scores_mma<<<2048, 256, BUFSTRIDE>>>(pThi, pTlo, ph2hi, ph2lo, lw, lb, out);
}

// round 10
// speedup vs baseline: 5.5833x; 1.0846x over previous
#include <cuda_runtime.h>
#include <cuda_bf16.h>
#include <cuda_fp16.h>
#include <cstdint>

#define NN   65536
#define EE   1048576
#define D1   512
#define DOUTD 128
#define KIN  1024

// ---------------- device scratch (static: allocation-free) ----------------
__device__ __nv_bfloat16 g_xhi[(size_t)NN * KIN];     // 128 MB
__device__ __nv_bfloat16 g_xlo[(size_t)NN * KIN];     // 128 MB
__device__ float g_Wcatf[KIN * D1];                   // 2 MB fp32 concat [Wt1;Wt2]
__device__ float g_Wp[KIN * D1];                      // 2 MB fp32 W' = Wcat@W1
__device__ __nv_bfloat16 g_WpThi[D1 * KIN];           // 1 MB  W'^T split
__device__ __nv_bfloat16 g_WpTlo[D1 * KIN];
__device__ float g_bcat[D1];
__device__ float g_bprime[D1];
__device__ __nv_bfloat16 g_W2Thi[DOUTD * D1];
__device__ __nv_bfloat16 g_W2Tlo[DOUTD * D1];
__device__ __nv_bfloat16 g_WmThi[DOUTD * DOUTD];
__device__ __nv_bfloat16 g_WmTlo[DOUTD * DOUTD];
__device__ __half g_t1h[(size_t)NN * D1];             // 64 MB fp16 t1
__device__ __nv_bfloat16 g_h1hi[(size_t)NN * D1];     // 64 MB
__device__ __nv_bfloat16 g_h1lo[(size_t)NN * D1];     // 64 MB
__device__ __half g_h2linh[(size_t)NN * DOUTD];       // 16 MB fp16 h2lin
__device__ __nv_bfloat16 g_h2hi[(size_t)NN * DOUTD];  // 16 MB
__device__ __nv_bfloat16 g_h2lo[(size_t)NN * DOUTD];  // 16 MB
__device__ __nv_bfloat16 g_Thi[(size_t)NN * DOUTD];   // 16 MB
__device__ __nv_bfloat16 g_Tlo[(size_t)NN * DOUTD];   // 16 MB
__device__ float g_isq[NN];
__device__ int   g_cnt[NN];
__device__ int   g_rowptr[NN + 1];
__device__ int   g_cursor[NN];
__device__ int   g_bsum[256];
__device__ int   g_boff[256];
__device__ int   g_adj[EE];
__device__ int   g_is64;

// ---------------- tiny helpers ----------------
__device__ __forceinline__ unsigned pk(__nv_bfloat16 a, __nv_bfloat16 b) {
    return (unsigned)__bfloat16_as_ushort(a) | ((unsigned)__bfloat16_as_ushort(b) << 16);
}
__device__ __forceinline__ uint32_t smem_u32(const void* p) {
    uint32_t a;
    asm("{ .reg .u64 t; cvta.to.shared.u64 t, %1; cvt.u32.u64 %0, t; }" : "=r"(a) : "l"(p));
    return a;
}
__device__ __forceinline__ void ffma2(unsigned long long& d, unsigned long long a, unsigned long long b) {
    asm("fma.rn.f32x2 %0, %1, %2, %0;" : "+l"(d) : "l"(a), "l"(b));
}
__device__ __forceinline__ void unpack2(unsigned long long v, float& lo, float& hi) {
    asm("mov.b64 {%0, %1}, %2;" : "=f"(lo), "=f"(hi) : "l"(v));
}

#define LDSM_X4(r, ad) \
    asm volatile("ldmatrix.sync.aligned.m8n8.x4.shared.b16 {%0,%1,%2,%3}, [%4];" \
                 : "=r"((r)[0]), "=r"((r)[1]), "=r"((r)[2]), "=r"((r)[3]) : "r"(ad))
#define LDSM_X2(r, ad) \
    asm volatile("ldmatrix.sync.aligned.m8n8.x2.shared.b16 {%0,%1}, [%2];" \
                 : "=r"((r)[0]), "=r"((r)[1]) : "r"(ad))
#define MMA16816(c, a, b) \
    asm volatile("mma.sync.aligned.m16n8k16.row.col.f32.bf16.bf16.f32 " \
                 "{%0,%1,%2,%3}, {%4,%5,%6,%7}, {%8,%9}, {%0,%1,%2,%3};" \
                 : "+f"((c)[0]), "+f"((c)[1]), "+f"((c)[2]), "+f"((c)[3]) \
                 : "r"((a)[0]), "r"((a)[1]), "r"((a)[2]), "r"((a)[3]), \
                   "r"((b)[0]), "r"((b)[1]))
#define CP16(sa, gp) \
    asm volatile("cp.async.cg.shared.global [%0], [%1], 16;" :: "r"(sa), "l"(gp))
#define CP_COMMIT() asm volatile("cp.async.commit_group;" ::: "memory")
#define CP_WAIT1()  asm volatile("cp.async.wait_group 1;" ::: "memory")
#define CP_WAIT0()  asm volatile("cp.async.wait_group 0;" ::: "memory")

__device__ __forceinline__ uint32_t swz(uint32_t o) { return o ^ ((o >> 3) & 0x70); }

__device__ __forceinline__ int edge_at(const void* eiv, int idx) {
    if (g_is64) return (int)((const long long*)eiv)[idx];
    return ((const int*)eiv)[idx];
}
__device__ __forceinline__ void split_store(float v, __nv_bfloat16* hi, __nv_bfloat16* lo, size_t i) {
    __nv_bfloat16 h = __float2bfloat16(v);
    hi[i] = h;
    lo[i] = __float2bfloat16(v - __bfloat162float(h));
}

// ---------------- fused prep 1: convert x to hi/lo, build fp32 Wcat, bcat ----
__global__ void k_prep1(const float* __restrict__ x,
                        const float* __restrict__ Wt1, const float* __restrict__ Wt2,
                        const float* __restrict__ bt1, const float* __restrict__ bt2)
{
    int b = blockIdx.x;
    if (b < 65536) {
        size_t i = ((size_t)b * 256 + threadIdx.x) * 4;
        float4 v = *(const float4*)(x + i);
        __nv_bfloat16 h0 = __float2bfloat16(v.x), h1 = __float2bfloat16(v.y);
        __nv_bfloat16 h2 = __float2bfloat16(v.z), h3 = __float2bfloat16(v.w);
        uint2 hv = { pk(h0, h1), pk(h2, h3) };
        __nv_bfloat16 l0 = __float2bfloat16(v.x - __bfloat162float(h0));
        __nv_bfloat16 l1 = __float2bfloat16(v.y - __bfloat162float(h1));
        __nv_bfloat16 l2 = __float2bfloat16(v.z - __bfloat162float(h2));
        __nv_bfloat16 l3 = __float2bfloat16(v.w - __bfloat162float(h3));
        uint2 lv = { pk(l0, l1), pk(l2, l3) };
        *(uint2*)(g_xhi + i) = hv;
        *(uint2*)(g_xlo + i) = lv;
    } else if (b < 65536 + 2048) {
        int idx = (b - 65536) * 256 + threadIdx.x;   // [1024 k][512 n] row-major
        int k = idx >> 9, n = idx & 511;
        g_Wcatf[idx] = (k < 256) ? Wt1[k * D1 + n] : Wt2[(k - 256) * D1 + n];
    } else {
#pragma unroll
        for (int r = 0; r < 2; r++) {
            int j = threadIdx.x + 256 * r;
            g_bcat[j] = bt1[j] + bt2[j];
        }
    }
}

// ---------------- prep 3: W'^T split hi/lo + b' = bcat@W1 ----------------
__global__ void k_prep3(const float* __restrict__ W1) {
    int b = blockIdx.x;
    if (b < 2048) {
        int idx = b * 256 + threadIdx.x;             // [512 n][1024 k]
        int k = idx & 1023;
        int n = idx >> 10;
        split_store(g_Wp[k * D1 + n], g_WpThi, g_WpTlo, (size_t)idx);
    } else {
#pragma unroll
        for (int r = 0; r < 2; r++) {
            int j = threadIdx.x + 256 * r;
            float s = 0.0f;
#pragma unroll 4
            for (int i = 0; i < D1; i++) s += g_bcat[i] * W1[i * D1 + j];
            g_bprime[j] = s;
        }
    }
}

// ---------------- fused misc prep: detect + zero_cnt + W2^T + Wm^T ----------
__global__ void k_misc(const int* __restrict__ ei,
                       const float* __restrict__ W2, const float* __restrict__ Wm)
{
    int b = blockIdx.x;
    if (b == 0) {
        if (threadIdx.x < 32) {
            int lane = threadIdx.x;
            int bad = 0;
#pragma unroll
            for (int i = lane; i < 256; i += 32) bad |= (ei[2 * i + 1] != 0);
            unsigned m = __ballot_sync(0xFFFFFFFF, bad);
            if (lane == 0) g_is64 = (m == 0) ? 1 : 0;
        }
    } else if (b < 257) {
        g_cnt[(b - 1) * 256 + threadIdx.x] = 0;
    } else if (b < 513) {
        int idx = (b - 257) * 256 + threadIdx.x;     // [128 n][512 k]
        int n = idx >> 9, k = idx & 511;
        split_store(W2[k * DOUTD + n], g_W2Thi, g_W2Tlo, idx);
    } else {
        int idx = (b - 513) * 256 + threadIdx.x;     // [128 n][128 k]
        int n = idx >> 7, k = idx & 127;
        split_store(Wm[k * DOUTD + n], g_WmThi, g_WmTlo, idx);
    }
}

__global__ void k_count(const void* __restrict__ eiv) {
    int e = blockIdx.x * blockDim.x + threadIdx.x;
    if (e >= EE) return;
    atomicAdd(&g_cnt[edge_at(eiv, EE + e)], 1);
}
__global__ void k_isq() {
    int i = blockIdx.x * blockDim.x + threadIdx.x;
    if (i < NN) g_isq[i] = rsqrtf((float)g_cnt[i] + 1.0f);
}
__global__ void k_scanA() {
    __shared__ int sh[256];
    int t = threadIdx.x, b = blockIdx.x;
    sh[t] = g_cnt[b * 256 + t];
    __syncthreads();
    for (int off = 128; off > 0; off >>= 1) {
        if (t < off) sh[t] += sh[t + off];
        __syncthreads();
    }
    if (t == 0) g_bsum[b] = sh[0];
}
__global__ void k_scanB() {
    __shared__ int sh[256];
    int t = threadIdx.x;
    int v = g_bsum[t];
    sh[t] = v;
    __syncthreads();
    for (int off = 1; off < 256; off <<= 1) {
        int x = (t >= off) ? sh[t - off] : 0;
        __syncthreads();
        sh[t] += x;
        __syncthreads();
    }
    g_boff[t] = sh[t] - v;
    if (t == 255) g_rowptr[NN] = sh[255];
}
__global__ void k_scanC() {
    __shared__ int sh[256];
    int t = threadIdx.x, b = blockIdx.x;
    int i = b * 256 + t;
    int v = g_cnt[i];
    sh[t] = v;
    __syncthreads();
    for (int off = 1; off < 256; off <<= 1) {
        int x = (t >= off) ? sh[t - off] : 0;
        __syncthreads();
        sh[t] += x;
        __syncthreads();
    }
    int excl = sh[t] - v + g_boff[b];
    g_rowptr[i] = excl;
    g_cursor[i] = excl;
}
__global__ void k_fill(const void* __restrict__ eiv) {
    int e = blockIdx.x * blockDim.x + threadIdx.x;
    if (e >= EE) return;
    int s = edge_at(eiv, e);
    int d = edge_at(eiv, EE + e);
    g_adj[atomicAdd(&g_cursor[d], 1)] = s;
}

// ---------------- warp-MMA bf16-split GEMM, cp.async double-buffered ----------
// OUT: 0 = fp32, 1 = bf16 hi/lo, 2 = fp16
static constexpr uint32_t SOFF_AH = 0, SOFF_AL = 8192, SOFF_BH = 16384, SOFF_BL = 32768;
static constexpr uint32_t BUFSTRIDE = 49152;
#define GEMM_SMEM 98304

template <int OUT, int BIAS>
__global__ __launch_bounds__(256, 2) void mma_gemm(
    const __nv_bfloat16* __restrict__ Ahi, const __nv_bfloat16* __restrict__ Alo,
    const __nv_bfloat16* __restrict__ Bhi, const __nv_bfloat16* __restrict__ Blo,
    const float* __restrict__ bias,
    float* __restrict__ Cf, __nv_bfloat16* __restrict__ Chi, __nv_bfloat16* __restrict__ Clo,
    __half* __restrict__ Ch, int N, int K)
{
    extern __shared__ char sm[];
    uint32_t smb = smem_u32(sm);
    const int tid = threadIdx.x, wid = tid >> 5, lane = tid & 31;
    const int wm = wid & 1, wn = wid >> 1;
    const int m0 = blockIdx.y * 64, n0 = blockIdx.x * 128;

    float acc[2][4][4];
#pragma unroll
    for (int mi = 0; mi < 2; mi++)
#pragma unroll
        for (int ni = 0; ni < 4; ni++)
#pragma unroll
            for (int q = 0; q < 4; q++) acc[mi][ni][q] = 0.0f;

    const int arow = tid >> 3, ac = tid & 7;
    const uint32_t soff = swz((uint32_t)(arow * 128 + ac * 16));

    auto issue = [&](int buf, int kt) {
        uint32_t sb = smb + (uint32_t)buf * BUFSTRIDE;
#pragma unroll
        for (int r = 0; r < 2; r++) {
            int row = arow + 32 * r;
            uint32_t off = soff + (uint32_t)(r * 32 * 128);
            const size_t gi = (size_t)(m0 + row) * K + kt + ac * 8;
            CP16(sb + SOFF_AH + off, Ahi + gi);
            CP16(sb + SOFF_AL + off, Alo + gi);
        }
#pragma unroll
        for (int r = 0; r < 4; r++) {
            int row = arow + 32 * r;
            uint32_t off = soff + (uint32_t)(r * 32 * 128);
            const size_t gi = (size_t)(n0 + row) * K + kt + ac * 8;
            CP16(sb + SOFF_BH + off, Bhi + gi);
            CP16(sb + SOFF_BL + off, Blo + gi);
        }
        CP_COMMIT();
    };

    issue(0, 0);
    const int C = K / 64;
    for (int c = 0; c < C; c++) {
        if (c + 1 < C) { issue((c + 1) & 1, (c + 1) * 64); CP_WAIT1(); }
        else CP_WAIT0();
        __syncthreads();
        uint32_t sbase = smb + (uint32_t)(c & 1) * BUFSTRIDE;
#pragma unroll
        for (int ks = 0; ks < 4; ks++) {
            uint32_t ah[2][4], al[2][4], bh[4][2], bl[4][2];
#pragma unroll
            for (int mi = 0; mi < 2; mi++) {
                int row = wm * 32 + mi * 16 + (lane & 15);
                int kc = ks * 16 + (lane >> 4) * 8;
                uint32_t o = swz((uint32_t)(row * 128 + kc * 2));
                LDSM_X4(ah[mi], sbase + SOFF_AH + o);
                LDSM_X4(al[mi], sbase + SOFF_AL + o);
            }
#pragma unroll
            for (int ni = 0; ni < 4; ni++) {
                int row = wn * 32 + ni * 8 + (lane & 7);
                int kc = ks * 16 + ((lane >> 3) & 1) * 8;
                uint32_t o = swz((uint32_t)(row * 128 + kc * 2));
                LDSM_X2(bh[ni], sbase + SOFF_BH + o);
                LDSM_X2(bl[ni], sbase + SOFF_BL + o);
            }
#pragma unroll
            for (int mi = 0; mi < 2; mi++)
#pragma unroll
                for (int ni = 0; ni < 4; ni++) {
                    MMA16816(acc[mi][ni], ah[mi], bh[ni]);
                    MMA16816(acc[mi][ni], ah[mi], bl[ni]);
                    MMA16816(acc[mi][ni], al[mi], bh[ni]);
                }
        }
        __syncthreads();
    }

    const int r = lane >> 2, cq = (lane & 3) * 2;
#pragma unroll
    for (int mi = 0; mi < 2; mi++) {
        const int mbase = m0 + wm * 32 + mi * 16 + r;
#pragma unroll
        for (int ni = 0; ni < 4; ni++) {
            const int col = n0 + wn * 32 + ni * 8 + cq;
            float b0 = 0.0f, b1 = 0.0f;
            if (BIAS) { float2 bb = *(const float2*)(bias + col); b0 = bb.x; b1 = bb.y; }
#pragma unroll
            for (int h = 0; h < 2; h++) {
                const int m = mbase + 8 * h;
                float v0 = acc[mi][ni][2 * h + 0] + b0;
                float v1 = acc[mi][ni][2 * h + 1] + b1;
                if (OUT == 1) {
                    __nv_bfloat16 h0 = __float2bfloat16(v0), h1 = __float2bfloat16(v1);
                    *(unsigned*)(Chi + (size_t)m * N + col) = pk(h0, h1);
                    *(unsigned*)(Clo + (size_t)m * N + col) =
                        pk(__float2bfloat16(v0 - __bfloat162float(h0)),
                           __float2bfloat16(v1 - __bfloat162float(h1)));
                } else if (OUT == 2) {
                    *(__half2*)(Ch + (size_t)m * N + col) = __floats2half2_rn(v0, v1);
                } else {
                    *(float2*)(Cf + (size_t)m * N + col) = make_float2(v0, v1);
                }
            }
        }
    }
}

// ---------------- bilinear scores via warp-MMA + Linear(1,2) ----------------
__global__ __launch_bounds__(256, 2) void k_scores_mma(
    const __nv_bfloat16* __restrict__ Thi, const __nv_bfloat16* __restrict__ Tlo,
    const __nv_bfloat16* __restrict__ Ehi, const __nv_bfloat16* __restrict__ Elo,
    const float* __restrict__ lw, const float* __restrict__ lb,
    float* __restrict__ out)
{
    extern __shared__ char sm[];
    uint32_t smb = smem_u32(sm);
    const int tid = threadIdx.x, wid = tid >> 5, lane = tid & 31;
    const int wm = wid & 1, wn = wid >> 1;
    const int blk = blockIdx.x;
    const int chunk = blk >> 3, sub = blk & 7;
    const int mblk = sub >> 1, nblk = sub & 1;
    const int m0 = chunk * 256 + mblk * 64;
    const int n0 = chunk * 256 + nblk * 128;
    const int K = DOUTD;

    float acc[2][4][4];
#pragma unroll
    for (int mi = 0; mi < 2; mi++)
#pragma unroll
        for (int ni = 0; ni < 4; ni++)
#pragma unroll
            for (int q = 0; q < 4; q++) acc[mi][ni][q] = 0.0f;

    const int arow = tid >> 3, ac = tid & 7;
    const uint32_t soff = swz((uint32_t)(arow * 128 + ac * 16));

    for (int kt = 0; kt < K; kt += 64) {
        __syncthreads();
#pragma unroll
        for (int r = 0; r < 2; r++) {
            int row = arow + 32 * r;
            uint32_t off = soff + (uint32_t)(r * 32 * 128);
            const size_t gi = (size_t)(m0 + row) * K + kt + ac * 8;
            *(uint4*)(sm + SOFF_AH + off) = *(const uint4*)(Thi + gi);
            *(uint4*)(sm + SOFF_AL + off) = *(const uint4*)(Tlo + gi);
        }
#pragma unroll
        for (int r = 0; r < 4; r++) {
            int row = arow + 32 * r;
            uint32_t off = soff + (uint32_t)(r * 32 * 128);
            const size_t gi = (size_t)(n0 + row) * K + kt + ac * 8;
            *(uint4*)(sm + SOFF_BH + off) = *(const uint4*)(Ehi + gi);
            *(uint4*)(sm + SOFF_BL + off) = *(const uint4*)(Elo + gi);
        }
        __syncthreads();
#pragma unroll
        for (int ks = 0; ks < 4; ks++) {
            uint32_t ah[2][4], al[2][4], bh[4][2], bl[4][2];
#pragma unroll
            for (int mi = 0; mi < 2; mi++) {
                int row = wm * 32 + mi * 16 + (lane & 15);
                int kc = ks * 16 + (lane >> 4) * 8;
                uint32_t o = swz((uint32_t)(row * 128 + kc * 2));
                LDSM_X4(ah[mi], smb + SOFF_AH + o);
                LDSM_X4(al[mi], smb + SOFF_AL + o);
            }
#pragma unroll
            for (int ni = 0; ni < 4; ni++) {
                int row = wn * 32 + ni * 8 + (lane & 7);
                int kc = ks * 16 + ((lane >> 3) & 1) * 8;
                uint32_t o = swz((uint32_t)(row * 128 + kc * 2));
                LDSM_X2(bh[ni], smb + SOFF_BH + o);
                LDSM_X2(bl[ni], smb + SOFF_BL + o);
            }
#pragma unroll
            for (int mi = 0; mi < 2; mi++)
#pragma unroll
                for (int ni = 0; ni < 4; ni++) {
                    MMA16816(acc[mi][ni], ah[mi], bh[ni]);
                    MMA16816(acc[mi][ni], ah[mi], bl[ni]);
                    MMA16816(acc[mi][ni], al[mi], bh[ni]);
                }
        }
    }

    const float w0 = lw[0], w1 = lw[1], c0 = lb[0], c1 = lb[1];
    const int r = lane >> 2, cq = (lane & 3) * 2;
#pragma unroll
    for (int mi = 0; mi < 2; mi++) {
        const int irow = mblk * 64 + wm * 32 + mi * 16 + r;
#pragma unroll
        for (int ni = 0; ni < 4; ni++) {
            const int jcol = nblk * 128 + wn * 32 + ni * 8 + cq;
#pragma unroll
            for (int h = 0; h < 2; h++) {
                float s0 = acc[mi][ni][2 * h + 0];
                float s1 = acc[mi][ni][2 * h + 1];
                size_t o = (((size_t)chunk * 256 + irow + 8 * h) * 256 + jcol) * 2;
                *(float4*)(out + o) = make_float4(s0 * w0 + c0, s0 * w1 + c1,
                                                  s1 * w0 + c0, s1 * w1 + c1);
            }
        }
    }
}

// ---------------- CSR aggregate over fp16 input, bf16 hi/lo output ----------
// out[n] = sum_{s in adj(n)} h[s]*isq[s]*isq[n] + h[n]*isq[n]^2 + bias (+relu)
template <int D, int RELU>
__global__ void conv_aggf(const __half* __restrict__ hin, const float* __restrict__ bias,
                          __nv_bfloat16* __restrict__ ohi, __nv_bfloat16* __restrict__ olo)
{
    int n = (blockIdx.x * blockDim.x + threadIdx.x) >> 5;
    int lane = threadIdx.x & 31;
    if (n >= NN) return;
    const int RV = D / 128;          // uint2 (4 halfs) per lane
    float iq = g_isq[n];
    float acc[RV][4];
    {
        float w = iq * iq;
        const uint2* hp = (const uint2*)(hin + (size_t)n * D);
#pragma unroll
        for (int i = 0; i < RV; i++) {
            uint2 v = hp[lane + 32 * i];
            float2 f0 = __half22float2(*(const __half2*)&v.x);
            float2 f1 = __half22float2(*(const __half2*)&v.y);
            acc[i][0] = f0.x * w; acc[i][1] = f0.y * w;
            acc[i][2] = f1.x * w; acc[i][3] = f1.y * w;
        }
    }
    int beg = g_rowptr[n], end = g_rowptr[n + 1];
    for (int k = beg; k < end; k++) {
        int s = g_adj[k];
        float w = g_isq[s] * iq;
        const uint2* hs = (const uint2*)(hin + (size_t)s * D);
#pragma unroll
        for (int i = 0; i < RV; i++) {
            uint2 v = hs[lane + 32 * i];
            float2 f0 = __half22float2(*(const __half2*)&v.x);
            float2 f1 = __half22float2(*(const __half2*)&v.y);
            acc[i][0] += f0.x * w; acc[i][1] += f0.y * w;
            acc[i][2] += f1.x * w; acc[i][3] += f1.y * w;
        }
    }
#pragma unroll
    for (int i = 0; i < RV; i++) {
        int col = i * 128 + lane * 4;
        float4 bb = *(const float4*)(bias + col);
        float v0 = acc[i][0] + bb.x, v1 = acc[i][1] + bb.y;
        float v2 = acc[i][2] + bb.z, v3 = acc[i][3] + bb.w;
        if (RELU) {
            v0 = fmaxf(v0, 0.0f); v1 = fmaxf(v1, 0.0f);
            v2 = fmaxf(v2, 0.0f); v3 = fmaxf(v3, 0.0f);
        }
        __nv_bfloat16 h0 = __float2bfloat16(v0), h1 = __float2bfloat16(v1);
        __nv_bfloat16 h2 = __float2bfloat16(v2), h3 = __float2bfloat16(v3);
        uint2 hv = { pk(h0, h1), pk(h2, h3) };
        uint2 lv = { pk(__float2bfloat16(v0 - __bfloat162float(h0)),
                       __float2bfloat16(v1 - __bfloat162float(h1))),
                     pk(__float2bfloat16(v2 - __bfloat162float(h2)),
                       __float2bfloat16(v3 - __bfloat162float(h3))) };
        *(uint2*)(ohi + (size_t)n * D + col) = hv;
        *(uint2*)(olo + (size_t)n * D + col) = lv;
    }
}

// ---------------- f32x2 SGEMM (W' = Wcat@W1, tiny) ----------------
__global__ __launch_bounds__(256, 2) void sgemm_k(
    const float* __restrict__ A, const float* __restrict__ B,
    float* __restrict__ C, int M, int N, int K)
{
    __shared__ __align__(16) float As2[8][268];
    __shared__ __align__(16) float Bs[8][128];
    int tid = threadIdx.x;
    int bx = blockIdx.x, by = blockIdx.y;
    int ty = tid >> 4, tx = tid & 15;
    int arow = tid >> 1, acol4 = (tid & 1) * 4;
    int brow = tid >> 5, bcol4 = (tid & 31) * 4;
    const float* Ap = A + (size_t)(by * 128 + arow) * K;
    const float* Bp = B + (size_t)brow * N + bx * 128 + bcol4;
    unsigned long long acc[8][4];
#pragma unroll
    for (int i = 0; i < 8; i++)
#pragma unroll
        for (int j = 0; j < 4; j++) acc[i][j] = 0ull;
    for (int kt = 0; kt < K; kt += 8) {
        float4 av = *(const float4*)(Ap + kt + acol4);
        *(float2*)&As2[acol4 + 0][2 * arow] = make_float2(av.x, av.x);
        *(float2*)&As2[acol4 + 1][2 * arow] = make_float2(av.y, av.y);
        *(float2*)&As2[acol4 + 2][2 * arow] = make_float2(av.z, av.z);
        *(float2*)&As2[acol4 + 3][2 * arow] = make_float2(av.w, av.w);
        *(float4*)&Bs[brow][bcol4] = *(const float4*)(Bp + (size_t)kt * N);
        __syncthreads();
#pragma unroll
        for (int k = 0; k < 8; k++) {
            ulonglong2 a0 = *(const ulonglong2*)&As2[k][ty * 16 + 0];
            ulonglong2 a1 = *(const ulonglong2*)&As2[k][ty * 16 + 4];
            ulonglong2 a2 = *(const ulonglong2*)&As2[k][ty * 16 + 8];
            ulonglong2 a3 = *(const ulonglong2*)&As2[k][ty * 16 + 12];
            ulonglong2 b0 = *(const ulonglong2*)&Bs[k][tx * 8 + 0];
            ulonglong2 b1 = *(const ulonglong2*)&Bs[k][tx * 8 + 4];
            unsigned long long ap[8] = {a0.x, a0.y, a1.x, a1.y, a2.x, a2.y, a3.x, a3.y};
            unsigned long long bp[4] = {b0.x, b0.y, b1.x, b1.y};
#pragma unroll
            for (int i = 0; i < 8; i++)
#pragma unroll
                for (int j = 0; j < 4; j++) ffma2(acc[i][j], ap[i], bp[j]);
        }
        __syncthreads();
    }
#pragma unroll
    for (int i = 0; i < 8; i++) {
        float f[8];
#pragma unroll
        for (int j = 0; j < 4; j++) unpack2(acc[i][j], f[2 * j], f[2 * j + 1]);
        float* cp = C + (size_t)(by * 128 + ty * 8 + i) * N + bx * 128 + tx * 8;
        *(float4*)cp       = make_float4(f[0], f[1], f[2], f[3]);
        *(float4*)(cp + 4) = make_float4(f[4], f[5], f[6], f[7]);
    }
}

// ---------------- host launch ----------------
extern "C" void kernel_launch(void* const* d_in, const int* in_sizes, int n_in,
                              void* d_out, int out_size)
{
    const float* x      = (const float*)d_in[0];
    const float* Wt1    = (const float*)d_in[1];
    const float* bt1    = (const float*)d_in[2];
    const float* Wt2    = (const float*)d_in[3];
    const float* bt2    = (const float*)d_in[4];
    const float* W1     = (const float*)d_in[5];
    const float* b1     = (const float*)d_in[6];
    const float* W2     = (const float*)d_in[7];
    const float* b2     = (const float*)d_in[8];
    const float* matrix = (const float*)d_in[9];
    const float* lw     = (const float*)d_in[10];
    const float* lb     = (const float*)d_in[11];
    const void*  ei     = d_in[12];
    float* out = (float*)d_out;

    cudaFuncSetAttribute(mma_gemm<2, 1>, cudaFuncAttributeMaxDynamicSharedMemorySize, GEMM_SMEM);
    cudaFuncSetAttribute(mma_gemm<2, 0>, cudaFuncAttributeMaxDynamicSharedMemorySize, GEMM_SMEM);
    cudaFuncSetAttribute(mma_gemm<1, 0>, cudaFuncAttributeMaxDynamicSharedMemorySize, GEMM_SMEM);
    cudaFuncSetAttribute(k_scores_mma, cudaFuncAttributeMaxDynamicSharedMemorySize, BUFSTRIDE);

    __nv_bfloat16 *pxhi, *pxlo, *pWphi, *pWplo, *pW2hi, *pW2lo, *pWmhi, *pWmlo;
    __nv_bfloat16 *ph1hi, *ph1lo, *ph2hi, *ph2lo, *pThi, *pTlo;
    float *pWcatf, *pWp, *pbprime;
    __half *pt1h, *ph2linh;
    cudaGetSymbolAddress((void**)&pxhi, g_xhi);
    cudaGetSymbolAddress((void**)&pxlo, g_xlo);
    cudaGetSymbolAddress((void**)&pWcatf, g_Wcatf);
    cudaGetSymbolAddress((void**)&pWp, g_Wp);
    cudaGetSymbolAddress((void**)&pWphi, g_WpThi);
    cudaGetSymbolAddress((void**)&pWplo, g_WpTlo);
    cudaGetSymbolAddress((void**)&pbprime, g_bprime);
    cudaGetSymbolAddress((void**)&pW2hi, g_W2Thi);
    cudaGetSymbolAddress((void**)&pW2lo, g_W2Tlo);
    cudaGetSymbolAddress((void**)&pWmhi, g_WmThi);
    cudaGetSymbolAddress((void**)&pWmlo, g_WmTlo);
    cudaGetSymbolAddress((void**)&ph1hi, g_h1hi);
    cudaGetSymbolAddress((void**)&ph1lo, g_h1lo);
    cudaGetSymbolAddress((void**)&ph2hi, g_h2hi);
    cudaGetSymbolAddress((void**)&ph2lo, g_h2lo);
    cudaGetSymbolAddress((void**)&pThi, g_Thi);
    cudaGetSymbolAddress((void**)&pTlo, g_Tlo);
    cudaGetSymbolAddress((void**)&pt1h, g_t1h);
    cudaGetSymbolAddress((void**)&ph2linh, g_h2linh);

    // 1: convert x + Wcat fp32 + bcat (fused)
    k_prep1<<<65536 + 2048 + 1, 256>>>(x, Wt1, Wt2, bt1, bt2);
    // 2: W' = Wcat @ W1 (fp32, exact)
    sgemm_k<<<dim3(4, 8), 256>>>(pWcatf, W1, pWp, KIN, D1, D1);
    // 3: split W'^T -> hi/lo, b' = bcat @ W1
    k_prep3<<<2049, 256>>>(W1);
    // 4 (profiled): t1 = x @ W' + b'  -> fp16   (fuses GEMM1+GEMM2)
    mma_gemm<2, 1><<<dim3(4, 1024), 256, GEMM_SMEM>>>(
        pxhi, pxlo, pWphi, pWplo, pbprime, nullptr, nullptr, nullptr, pt1h, D1, KIN);
    // 5: fused misc (detect + zero_cnt + W2T + WmT)
    k_misc<<<577, 256>>>((const int*)ei, W2, matrix);
    k_count<<<EE / 256, 256>>>(ei);
    k_isq<<<256, 256>>>();
    k_scanA<<<256, 256>>>();
    k_scanB<<<1, 256>>>();
    k_scanC<<<256, 256>>>();
    k_fill<<<EE / 256, 256>>>(ei);
    // h1 = relu(agg(t1) + b1) -> bf16 hi/lo, single L2-resident pass (64 MB)
    conv_aggf<D1, 1><<<NN * 32 / 256, 256>>>(pt1h, b1, ph1hi, ph1lo);
    // h2lin = h1 @ W2 -> fp16
    mma_gemm<2, 0><<<dim3(1, 1024), 256, GEMM_SMEM>>>(
        ph1hi, ph1lo, pW2hi, pW2lo, nullptr, nullptr, nullptr, nullptr, ph2linh, DOUTD, D1);
    // h2 = agg(h2lin) + b2 -> bf16 hi/lo
    conv_aggf<DOUTD, 0><<<NN * 32 / 256, 256>>>(ph2linh, b2, ph2hi, ph2lo);
    // T = h2 @ matrix -> bf16 hi/lo
    mma_gemm<1, 0><<<dim3(1, 1024), 256, GEMM_SMEM>>>(
        ph2hi, ph2lo, pWmhi, pWmlo, nullptr, nullptr, pThi, pTlo, nullptr, DOUTD, DOUTD);
    // scores + Linear(1,2)
    k_scores_mma<<<2048, 256, BUFSTRIDE>>>(pThi, pTlo, ph2hi, ph2lo, lw, lb, out);
}

// round 11
// speedup vs baseline: 8.0541x; 1.4425x over previous
#include <cuda_runtime.h>
#include <cuda_bf16.h>
#include <cuda_fp16.h>
#include <cstdint>

#define NN   65536
#define EE   1048576
#define D1   512
#define DOUTD 128
#define KIN  1024

// ---------------- device scratch (static: allocation-free) ----------------
__device__ __half g_xh[(size_t)NN * KIN];             // 128 MB fp16 x
__device__ float g_Wcatf[KIN * D1];                   // 2 MB fp32 concat [Wt1;Wt2]
__device__ float g_Wp[KIN * D1];                      // 2 MB fp32 W' = Wcat@W1
__device__ __half g_WpTh[D1 * KIN];                   // 1 MB  W'^T fp16
__device__ float g_bcat[D1];
__device__ float g_bprime[D1];
__device__ __half g_W2Th[DOUTD * D1];                 // fp16 W2^T
__device__ __nv_bfloat16 g_WmThi[DOUTD * DOUTD];
__device__ __nv_bfloat16 g_WmTlo[DOUTD * DOUTD];
__device__ __half g_t1h[(size_t)NN * D1];             // 64 MB fp16 t1
__device__ __half g_h1h[(size_t)NN * D1];             // 64 MB fp16 h1
__device__ __half g_h2linh[(size_t)NN * DOUTD];       // 16 MB fp16 h2lin
__device__ __nv_bfloat16 g_h2hi[(size_t)NN * DOUTD];  // 16 MB
__device__ __nv_bfloat16 g_h2lo[(size_t)NN * DOUTD];  // 16 MB
__device__ __nv_bfloat16 g_Thi[(size_t)NN * DOUTD];   // 16 MB
__device__ __nv_bfloat16 g_Tlo[(size_t)NN * DOUTD];   // 16 MB
__device__ float g_isq[NN];
__device__ int   g_cnt[NN];
__device__ int   g_rowptr[NN + 1];
__device__ int   g_cursor[NN];
__device__ int   g_bsum[256];
__device__ int   g_boff[256];
__device__ int   g_adj[EE];
__device__ int   g_is64;

// ---------------- tiny helpers ----------------
__device__ __forceinline__ unsigned pk(__nv_bfloat16 a, __nv_bfloat16 b) {
    return (unsigned)__bfloat16_as_ushort(a) | ((unsigned)__bfloat16_as_ushort(b) << 16);
}
__device__ __forceinline__ unsigned pkh(__half2 h) {
    return *(unsigned*)&h;
}
__device__ __forceinline__ uint32_t smem_u32(const void* p) {
    uint32_t a;
    asm("{ .reg .u64 t; cvta.to.shared.u64 t, %1; cvt.u32.u64 %0, t; }" : "=r"(a) : "l"(p));
    return a;
}
__device__ __forceinline__ void ffma2(unsigned long long& d, unsigned long long a, unsigned long long b) {
    asm("fma.rn.f32x2 %0, %1, %2, %0;" : "+l"(d) : "l"(a), "l"(b));
}
__device__ __forceinline__ void unpack2(unsigned long long v, float& lo, float& hi) {
    asm("mov.b64 {%0, %1}, %2;" : "=f"(lo), "=f"(hi) : "l"(v));
}

#define LDSM_X4(r, ad) \
    asm volatile("ldmatrix.sync.aligned.m8n8.x4.shared.b16 {%0,%1,%2,%3}, [%4];" \
                 : "=r"((r)[0]), "=r"((r)[1]), "=r"((r)[2]), "=r"((r)[3]) : "r"(ad))
#define LDSM_X2(r, ad) \
    asm volatile("ldmatrix.sync.aligned.m8n8.x2.shared.b16 {%0,%1}, [%2];" \
                 : "=r"((r)[0]), "=r"((r)[1]) : "r"(ad))
#define MMA16816(c, a, b) \
    asm volatile("mma.sync.aligned.m16n8k16.row.col.f32.bf16.bf16.f32 " \
                 "{%0,%1,%2,%3}, {%4,%5,%6,%7}, {%8,%9}, {%0,%1,%2,%3};" \
                 : "+f"((c)[0]), "+f"((c)[1]), "+f"((c)[2]), "+f"((c)[3]) \
                 : "r"((a)[0]), "r"((a)[1]), "r"((a)[2]), "r"((a)[3]), \
                   "r"((b)[0]), "r"((b)[1]))
#define MMAH16816(c, a, b) \
    asm volatile("mma.sync.aligned.m16n8k16.row.col.f32.f16.f16.f32 " \
                 "{%0,%1,%2,%3}, {%4,%5,%6,%7}, {%8,%9}, {%0,%1,%2,%3};" \
                 : "+f"((c)[0]), "+f"((c)[1]), "+f"((c)[2]), "+f"((c)[3]) \
                 : "r"((a)[0]), "r"((a)[1]), "r"((a)[2]), "r"((a)[3]), \
                   "r"((b)[0]), "r"((b)[1]))
#define CP16(sa, gp) \
    asm volatile("cp.async.cg.shared.global [%0], [%1], 16;" :: "r"(sa), "l"(gp))
#define CP_COMMIT() asm volatile("cp.async.commit_group;" ::: "memory")
#define CP_WAIT2()  asm volatile("cp.async.wait_group 2;" ::: "memory")
#define CP_WAIT1()  asm volatile("cp.async.wait_group 1;" ::: "memory")
#define CP_WAIT0()  asm volatile("cp.async.wait_group 0;" ::: "memory")

__device__ __forceinline__ uint32_t swz(uint32_t o) { return o ^ ((o >> 3) & 0x70); }

__device__ __forceinline__ int edge_at(const void* eiv, int idx) {
    if (g_is64) return (int)((const long long*)eiv)[idx];
    return ((const int*)eiv)[idx];
}
__device__ __forceinline__ void split_store(float v, __nv_bfloat16* hi, __nv_bfloat16* lo, size_t i) {
    __nv_bfloat16 h = __float2bfloat16(v);
    hi[i] = h;
    lo[i] = __float2bfloat16(v - __bfloat162float(h));
}

// ---------------- fused prep 1: x -> fp16, build fp32 Wcat, bcat ----------
__global__ void k_prep1(const float* __restrict__ x,
                        const float* __restrict__ Wt1, const float* __restrict__ Wt2,
                        const float* __restrict__ bt1, const float* __restrict__ bt2)
{
    int b = blockIdx.x;
    if (b < 65536) {
        size_t i = ((size_t)b * 256 + threadIdx.x) * 4;
        float4 v = *(const float4*)(x + i);
        uint2 hv = { pkh(__floats2half2_rn(v.x, v.y)), pkh(__floats2half2_rn(v.z, v.w)) };
        *(uint2*)(g_xh + i) = hv;
    } else if (b < 65536 + 2048) {
        int idx = (b - 65536) * 256 + threadIdx.x;   // [1024 k][512 n] row-major
        int k = idx >> 9, n = idx & 511;
        g_Wcatf[idx] = (k < 256) ? Wt1[k * D1 + n] : Wt2[(k - 256) * D1 + n];
    } else {
#pragma unroll
        for (int r = 0; r < 2; r++) {
            int j = threadIdx.x + 256 * r;
            g_bcat[j] = bt1[j] + bt2[j];
        }
    }
}

// ---------------- prep 3: W'^T -> fp16 + b' = bcat@W1 ----------------
__global__ void k_prep3(const float* __restrict__ W1) {
    int b = blockIdx.x;
    if (b < 2048) {
        int idx = b * 256 + threadIdx.x;             // [512 n][1024 k]
        int k = idx & 1023;
        int n = idx >> 10;
        g_WpTh[idx] = __float2half(g_Wp[k * D1 + n]);
    } else {
#pragma unroll
        for (int r = 0; r < 2; r++) {
            int j = threadIdx.x + 256 * r;
            float s = 0.0f;
#pragma unroll 4
            for (int i = 0; i < D1; i++) s += g_bcat[i] * W1[i * D1 + j];
            g_bprime[j] = s;
        }
    }
}

// ---------------- fused misc prep: detect + zero_cnt + W2^T + Wm^T ----------
__global__ void k_misc(const int* __restrict__ ei,
                       const float* __restrict__ W2, const float* __restrict__ Wm)
{
    int b = blockIdx.x;
    if (b == 0) {
        if (threadIdx.x < 32) {
            int lane = threadIdx.x;
            int bad = 0;
#pragma unroll
            for (int i = lane; i < 256; i += 32) bad |= (ei[2 * i + 1] != 0);
            unsigned m = __ballot_sync(0xFFFFFFFF, bad);
            if (lane == 0) g_is64 = (m == 0) ? 1 : 0;
        }
    } else if (b < 257) {
        g_cnt[(b - 1) * 256 + threadIdx.x] = 0;
    } else if (b < 513) {
        int idx = (b - 257) * 256 + threadIdx.x;     // [128 n][512 k]
        int n = idx >> 9, k = idx & 511;
        g_W2Th[idx] = __float2half(W2[k * DOUTD + n]);
    } else {
        int idx = (b - 513) * 256 + threadIdx.x;     // [128 n][128 k]
        int n = idx >> 7, k = idx & 127;
        split_store(Wm[k * DOUTD + n], g_WmThi, g_WmTlo, idx);
    }
}

__global__ void k_count(const void* __restrict__ eiv) {
    int e = blockIdx.x * blockDim.x + threadIdx.x;
    if (e >= EE) return;
    atomicAdd(&g_cnt[edge_at(eiv, EE + e)], 1);
}
__global__ void k_isq() {
    int i = blockIdx.x * blockDim.x + threadIdx.x;
    if (i < NN) g_isq[i] = rsqrtf((float)g_cnt[i] + 1.0f);
}
__global__ void k_scanA() {
    __shared__ int sh[256];
    int t = threadIdx.x, b = blockIdx.x;
    sh[t] = g_cnt[b * 256 + t];
    __syncthreads();
    for (int off = 128; off > 0; off >>= 1) {
        if (t < off) sh[t] += sh[t + off];
        __syncthreads();
    }
    if (t == 0) g_bsum[b] = sh[0];
}
__global__ void k_scanB() {
    __shared__ int sh[256];
    int t = threadIdx.x;
    int v = g_bsum[t];
    sh[t] = v;
    __syncthreads();
    for (int off = 1; off < 256; off <<= 1) {
        int x = (t >= off) ? sh[t - off] : 0;
        __syncthreads();
        sh[t] += x;
        __syncthreads();
    }
    g_boff[t] = sh[t] - v;
    if (t == 255) g_rowptr[NN] = sh[255];
}
__global__ void k_scanC() {
    __shared__ int sh[256];
    int t = threadIdx.x, b = blockIdx.x;
    int i = b * 256 + t;
    int v = g_cnt[i];
    sh[t] = v;
    __syncthreads();
    for (int off = 1; off < 256; off <<= 1) {
        int x = (t >= off) ? sh[t - off] : 0;
        __syncthreads();
        sh[t] += x;
        __syncthreads();
    }
    int excl = sh[t] - v + g_boff[b];
    g_rowptr[i] = excl;
    g_cursor[i] = excl;
}
__global__ void k_fill(const void* __restrict__ eiv) {
    int e = blockIdx.x * blockDim.x + threadIdx.x;
    if (e >= EE) return;
    int s = edge_at(eiv, e);
    int d = edge_at(eiv, EE + e);
    g_adj[atomicAdd(&g_cursor[d], 1)] = s;
}

// ---------------- single-term fp16 warp-MMA GEMM, triple-buffered ----------
// C[M,N] = A[M,K] @ B^T[N,K], fp16 in, fp32 accumulate, fp16 out.
// BM=64, BN=128, BK=64. 256 threads, 8 warps (2 m x 4 n), warp tile 32x32.
static constexpr uint32_t HOFF_A = 0, HOFF_B = 8192;
static constexpr uint32_t HBUF = 24576;
#define HGEMM_SMEM 73728

template <int BIAS>
__global__ __launch_bounds__(256, 2) void hgemm(
    const __half* __restrict__ A, const __half* __restrict__ B,
    const float* __restrict__ bias, __half* __restrict__ C, int N, int K)
{
    extern __shared__ char sm[];
    uint32_t smb = smem_u32(sm);
    const int tid = threadIdx.x, wid = tid >> 5, lane = tid & 31;
    const int wm = wid & 1, wn = wid >> 1;
    const int m0 = blockIdx.y * 64, n0 = blockIdx.x * 128;

    float acc[2][4][4];
#pragma unroll
    for (int mi = 0; mi < 2; mi++)
#pragma unroll
        for (int ni = 0; ni < 4; ni++)
#pragma unroll
            for (int q = 0; q < 4; q++) acc[mi][ni][q] = 0.0f;

    const int arow = tid >> 3, ac = tid & 7;
    const uint32_t soff = swz((uint32_t)(arow * 128 + ac * 16));

    auto issue = [&](int buf, int kt) {
        uint32_t sb = smb + (uint32_t)buf * HBUF;
#pragma unroll
        for (int r = 0; r < 2; r++) {
            int row = arow + 32 * r;
            uint32_t off = soff + (uint32_t)(r * 32 * 128);
            const size_t gi = (size_t)(m0 + row) * K + kt + ac * 8;
            CP16(sb + HOFF_A + off, A + gi);
        }
#pragma unroll
        for (int r = 0; r < 4; r++) {
            int row = arow + 32 * r;
            uint32_t off = soff + (uint32_t)(r * 32 * 128);
            const size_t gi = (size_t)(n0 + row) * K + kt + ac * 8;
            CP16(sb + HOFF_B + off, B + gi);
        }
        CP_COMMIT();
    };

    const int Cn = K / 64;
    issue(0, 0);
    issue(1, 64);
    for (int c = 0; c < Cn; c++) {
        if (c + 2 < Cn) { issue((c + 2) % 3, (c + 2) * 64); CP_WAIT2(); }
        else if (c + 1 < Cn) CP_WAIT1();
        else CP_WAIT0();
        __syncthreads();
        uint32_t sbase = smb + (uint32_t)(c % 3) * HBUF;
#pragma unroll
        for (int ks = 0; ks < 4; ks++) {
            uint32_t ah[2][4], bh[4][2];
#pragma unroll
            for (int mi = 0; mi < 2; mi++) {
                int row = wm * 32 + mi * 16 + (lane & 15);
                int kc = ks * 16 + (lane >> 4) * 8;
                uint32_t o = swz((uint32_t)(row * 128 + kc * 2));
                LDSM_X4(ah[mi], sbase + HOFF_A + o);
            }
#pragma unroll
            for (int ni = 0; ni < 4; ni++) {
                int row = wn * 32 + ni * 8 + (lane & 7);
                int kc = ks * 16 + ((lane >> 3) & 1) * 8;
                uint32_t o = swz((uint32_t)(row * 128 + kc * 2));
                LDSM_X2(bh[ni], sbase + HOFF_B + o);
            }
#pragma unroll
            for (int mi = 0; mi < 2; mi++)
#pragma unroll
                for (int ni = 0; ni < 4; ni++)
                    MMAH16816(acc[mi][ni], ah[mi], bh[ni]);
        }
        __syncthreads();
    }

    const int r = lane >> 2, cq = (lane & 3) * 2;
#pragma unroll
    for (int mi = 0; mi < 2; mi++) {
        const int mbase = m0 + wm * 32 + mi * 16 + r;
#pragma unroll
        for (int ni = 0; ni < 4; ni++) {
            const int col = n0 + wn * 32 + ni * 8 + cq;
            float b0 = 0.0f, b1 = 0.0f;
            if (BIAS) { float2 bb = *(const float2*)(bias + col); b0 = bb.x; b1 = bb.y; }
#pragma unroll
            for (int h = 0; h < 2; h++) {
                const int m = mbase + 8 * h;
                float v0 = acc[mi][ni][2 * h + 0] + b0;
                float v1 = acc[mi][ni][2 * h + 1] + b1;
                *(__half2*)(C + (size_t)m * N + col) = __floats2half2_rn(v0, v1);
            }
        }
    }
}

// ---------------- 3-term bf16-split warp-MMA GEMM (GEMM4 only) --------------
static constexpr uint32_t SOFF_AH = 0, SOFF_AL = 8192, SOFF_BH = 16384, SOFF_BL = 32768;
static constexpr uint32_t BUFSTRIDE = 49152;
#define GEMM_SMEM 98304

__global__ __launch_bounds__(256, 2) void mma_gemm_bf(
    const __nv_bfloat16* __restrict__ Ahi, const __nv_bfloat16* __restrict__ Alo,
    const __nv_bfloat16* __restrict__ Bhi, const __nv_bfloat16* __restrict__ Blo,
    __nv_bfloat16* __restrict__ Chi, __nv_bfloat16* __restrict__ Clo, int N, int K)
{
    extern __shared__ char sm[];
    uint32_t smb = smem_u32(sm);
    const int tid = threadIdx.x, wid = tid >> 5, lane = tid & 31;
    const int wm = wid & 1, wn = wid >> 1;
    const int m0 = blockIdx.y * 64, n0 = blockIdx.x * 128;

    float acc[2][4][4];
#pragma unroll
    for (int mi = 0; mi < 2; mi++)
#pragma unroll
        for (int ni = 0; ni < 4; ni++)
#pragma unroll
            for (int q = 0; q < 4; q++) acc[mi][ni][q] = 0.0f;

    const int arow = tid >> 3, ac = tid & 7;
    const uint32_t soff = swz((uint32_t)(arow * 128 + ac * 16));

    auto issue = [&](int buf, int kt) {
        uint32_t sb = smb + (uint32_t)buf * BUFSTRIDE;
#pragma unroll
        for (int r = 0; r < 2; r++) {
            int row = arow + 32 * r;
            uint32_t off = soff + (uint32_t)(r * 32 * 128);
            const size_t gi = (size_t)(m0 + row) * K + kt + ac * 8;
            CP16(sb + SOFF_AH + off, Ahi + gi);
            CP16(sb + SOFF_AL + off, Alo + gi);
        }
#pragma unroll
        for (int r = 0; r < 4; r++) {
            int row = arow + 32 * r;
            uint32_t off = soff + (uint32_t)(r * 32 * 128);
            const size_t gi = (size_t)(n0 + row) * K + kt + ac * 8;
            CP16(sb + SOFF_BH + off, Bhi + gi);
            CP16(sb + SOFF_BL + off, Blo + gi);
        }
        CP_COMMIT();
    };

    issue(0, 0);
    const int Cn = K / 64;
    for (int c = 0; c < Cn; c++) {
        if (c + 1 < Cn) { issue((c + 1) & 1, (c + 1) * 64); CP_WAIT1(); }
        else CP_WAIT0();
        __syncthreads();
        uint32_t sbase = smb + (uint32_t)(c & 1) * BUFSTRIDE;
#pragma unroll
        for (int ks = 0; ks < 4; ks++) {
            uint32_t ah[2][4], al[2][4], bh[4][2], bl[4][2];
#pragma unroll
            for (int mi = 0; mi < 2; mi++) {
                int row = wm * 32 + mi * 16 + (lane & 15);
                int kc = ks * 16 + (lane >> 4) * 8;
                uint32_t o = swz((uint32_t)(row * 128 + kc * 2));
                LDSM_X4(ah[mi], sbase + SOFF_AH + o);
                LDSM_X4(al[mi], sbase + SOFF_AL + o);
            }
#pragma unroll
            for (int ni = 0; ni < 4; ni++) {
                int row = wn * 32 + ni * 8 + (lane & 7);
                int kc = ks * 16 + ((lane >> 3) & 1) * 8;
                uint32_t o = swz((uint32_t)(row * 128 + kc * 2));
                LDSM_X2(bh[ni], sbase + SOFF_BH + o);
                LDSM_X2(bl[ni], sbase + SOFF_BL + o);
            }
#pragma unroll
            for (int mi = 0; mi < 2; mi++)
#pragma unroll
                for (int ni = 0; ni < 4; ni++) {
                    MMA16816(acc[mi][ni], ah[mi], bh[ni]);
                    MMA16816(acc[mi][ni], ah[mi], bl[ni]);
                    MMA16816(acc[mi][ni], al[mi], bh[ni]);
                }
        }
        __syncthreads();
    }

    const int r = lane >> 2, cq = (lane & 3) * 2;
#pragma unroll
    for (int mi = 0; mi < 2; mi++) {
        const int mbase = m0 + wm * 32 + mi * 16 + r;
#pragma unroll
        for (int ni = 0; ni < 4; ni++) {
            const int col = n0 + wn * 32 + ni * 8 + cq;
#pragma unroll
            for (int h = 0; h < 2; h++) {
                const int m = mbase + 8 * h;
                float v0 = acc[mi][ni][2 * h + 0];
                float v1 = acc[mi][ni][2 * h + 1];
                __nv_bfloat16 h0 = __float2bfloat16(v0), h1 = __float2bfloat16(v1);
                *(unsigned*)(Chi + (size_t)m * N + col) = pk(h0, h1);
                *(unsigned*)(Clo + (size_t)m * N + col) =
                    pk(__float2bfloat16(v0 - __bfloat162float(h0)),
                       __float2bfloat16(v1 - __bfloat162float(h1)));
            }
        }
    }
}

// ---------------- bilinear scores via warp-MMA + Linear(1,2) ----------------
__global__ __launch_bounds__(256, 2) void k_scores_mma(
    const __nv_bfloat16* __restrict__ Thi, const __nv_bfloat16* __restrict__ Tlo,
    const __nv_bfloat16* __restrict__ Ehi, const __nv_bfloat16* __restrict__ Elo,
    const float* __restrict__ lw, const float* __restrict__ lb,
    float* __restrict__ out)
{
    extern __shared__ char sm[];
    uint32_t smb = smem_u32(sm);
    const int tid = threadIdx.x, wid = tid >> 5, lane = tid & 31;
    const int wm = wid & 1, wn = wid >> 1;
    const int blk = blockIdx.x;
    const int chunk = blk >> 3, sub = blk & 7;
    const int mblk = sub >> 1, nblk = sub & 1;
    const int m0 = chunk * 256 + mblk * 64;
    const int n0 = chunk * 256 + nblk * 128;
    const int K = DOUTD;

    float acc[2][4][4];
#pragma unroll
    for (int mi = 0; mi < 2; mi++)
#pragma unroll
        for (int ni = 0; ni < 4; ni++)
#pragma unroll
            for (int q = 0; q < 4; q++) acc[mi][ni][q] = 0.0f;

    const int arow = tid >> 3, ac = tid & 7;
    const uint32_t soff = swz((uint32_t)(arow * 128 + ac * 16));

    for (int kt = 0; kt < K; kt += 64) {
        __syncthreads();
#pragma unroll
        for (int r = 0; r < 2; r++) {
            int row = arow + 32 * r;
            uint32_t off = soff + (uint32_t)(r * 32 * 128);
            const size_t gi = (size_t)(m0 + row) * K + kt + ac * 8;
            *(uint4*)(sm + SOFF_AH + off) = *(const uint4*)(Thi + gi);
            *(uint4*)(sm + SOFF_AL + off) = *(const uint4*)(Tlo + gi);
        }
#pragma unroll
        for (int r = 0; r < 4; r++) {
            int row = arow + 32 * r;
            uint32_t off = soff + (uint32_t)(r * 32 * 128);
            const size_t gi = (size_t)(n0 + row) * K + kt + ac * 8;
            *(uint4*)(sm + SOFF_BH + off) = *(const uint4*)(Ehi + gi);
            *(uint4*)(sm + SOFF_BL + off) = *(const uint4*)(Elo + gi);
        }
        __syncthreads();
#pragma unroll
        for (int ks = 0; ks < 4; ks++) {
            uint32_t ah[2][4], al[2][4], bh[4][2], bl[4][2];
#pragma unroll
            for (int mi = 0; mi < 2; mi++) {
                int row = wm * 32 + mi * 16 + (lane & 15);
                int kc = ks * 16 + (lane >> 4) * 8;
                uint32_t o = swz((uint32_t)(row * 128 + kc * 2));
                LDSM_X4(ah[mi], smb + SOFF_AH + o);
                LDSM_X4(al[mi], smb + SOFF_AL + o);
            }
#pragma unroll
            for (int ni = 0; ni < 4; ni++) {
                int row = wn * 32 + ni * 8 + (lane & 7);
                int kc = ks * 16 + ((lane >> 3) & 1) * 8;
                uint32_t o = swz((uint32_t)(row * 128 + kc * 2));
                LDSM_X2(bh[ni], smb + SOFF_BH + o);
                LDSM_X2(bl[ni], smb + SOFF_BL + o);
            }
#pragma unroll
            for (int mi = 0; mi < 2; mi++)
#pragma unroll
                for (int ni = 0; ni < 4; ni++) {
                    MMA16816(acc[mi][ni], ah[mi], bh[ni]);
                    MMA16816(acc[mi][ni], ah[mi], bl[ni]);
                    MMA16816(acc[mi][ni], al[mi], bh[ni]);
                }
        }
    }

    const float w0 = lw[0], w1 = lw[1], c0 = lb[0], c1 = lb[1];
    const int r = lane >> 2, cq = (lane & 3) * 2;
#pragma unroll
    for (int mi = 0; mi < 2; mi++) {
        const int irow = mblk * 64 + wm * 32 + mi * 16 + r;
#pragma unroll
        for (int ni = 0; ni < 4; ni++) {
            const int jcol = nblk * 128 + wn * 32 + ni * 8 + cq;
#pragma unroll
            for (int h = 0; h < 2; h++) {
                float s0 = acc[mi][ni][2 * h + 0];
                float s1 = acc[mi][ni][2 * h + 1];
                size_t o = (((size_t)chunk * 256 + irow + 8 * h) * 256 + jcol) * 2;
                *(float4*)(out + o) = make_float4(s0 * w0 + c0, s0 * w1 + c1,
                                                  s1 * w0 + c0, s1 * w1 + c1);
            }
        }
    }
}

// ---------------- CSR aggregate over fp16 input ----------------------------
// OUTH=1: fp16 single output; OUTH=0: bf16 hi/lo output
template <int D, int RELU, int OUTH>
__global__ void conv_aggf(const __half* __restrict__ hin, const float* __restrict__ bias,
                          __half* __restrict__ oh,
                          __nv_bfloat16* __restrict__ ohi, __nv_bfloat16* __restrict__ olo)
{
    int n = (blockIdx.x * blockDim.x + threadIdx.x) >> 5;
    int lane = threadIdx.x & 31;
    if (n >= NN) return;
    const int RV = D / 128;          // uint2 (4 halfs) per lane
    float iq = g_isq[n];
    float acc[RV][4];
    {
        float w = iq * iq;
        const uint2* hp = (const uint2*)(hin + (size_t)n * D);
#pragma unroll
        for (int i = 0; i < RV; i++) {
            uint2 v = hp[lane + 32 * i];
            float2 f0 = __half22float2(*(const __half2*)&v.x);
            float2 f1 = __half22float2(*(const __half2*)&v.y);
            acc[i][0] = f0.x * w; acc[i][1] = f0.y * w;
            acc[i][2] = f1.x * w; acc[i][3] = f1.y * w;
        }
    }
    int beg = g_rowptr[n], end = g_rowptr[n + 1];
    for (int k = beg; k < end; k++) {
        int s = g_adj[k];
        float w = g_isq[s] * iq;
        const uint2* hs = (const uint2*)(hin + (size_t)s * D);
#pragma unroll
        for (int i = 0; i < RV; i++) {
            uint2 v = hs[lane + 32 * i];
            float2 f0 = __half22float2(*(const __half2*)&v.x);
            float2 f1 = __half22float2(*(const __half2*)&v.y);
            acc[i][0] += f0.x * w; acc[i][1] += f0.y * w;
            acc[i][2] += f1.x * w; acc[i][3] += f1.y * w;
        }
    }
#pragma unroll
    for (int i = 0; i < RV; i++) {
        int col = i * 128 + lane * 4;
        float4 bb = *(const float4*)(bias + col);
        float v0 = acc[i][0] + bb.x, v1 = acc[i][1] + bb.y;
        float v2 = acc[i][2] + bb.z, v3 = acc[i][3] + bb.w;
        if (RELU) {
            v0 = fmaxf(v0, 0.0f); v1 = fmaxf(v1, 0.0f);
            v2 = fmaxf(v2, 0.0f); v3 = fmaxf(v3, 0.0f);
        }
        if (OUTH) {
            uint2 hv = { pkh(__floats2half2_rn(v0, v1)), pkh(__floats2half2_rn(v2, v3)) };
            *(uint2*)(oh + (size_t)n * D + col) = hv;
        } else {
            __nv_bfloat16 h0 = __float2bfloat16(v0), h1 = __float2bfloat16(v1);
            __nv_bfloat16 h2 = __float2bfloat16(v2), h3 = __float2bfloat16(v3);
            uint2 hv = { pk(h0, h1), pk(h2, h3) };
            uint2 lv = { pk(__float2bfloat16(v0 - __bfloat162float(h0)),
                           __float2bfloat16(v1 - __bfloat162float(h1))),
                         pk(__float2bfloat16(v2 - __bfloat162float(h2)),
                           __float2bfloat16(v3 - __bfloat162float(h3))) };
            *(uint2*)(ohi + (size_t)n * D + col) = hv;
            *(uint2*)(olo + (size_t)n * D + col) = lv;
        }
    }
}

// ---------------- f32x2 SGEMM (W' = Wcat@W1, tiny) ----------------
__global__ __launch_bounds__(256, 2) void sgemm_k(
    const float* __restrict__ A, const float* __restrict__ B,
    float* __restrict__ C, int M, int N, int K)
{
    __shared__ __align__(16) float As2[8][268];
    __shared__ __align__(16) float Bs[8][128];
    int tid = threadIdx.x;
    int bx = blockIdx.x, by = blockIdx.y;
    int ty = tid >> 4, tx = tid & 15;
    int arow = tid >> 1, acol4 = (tid & 1) * 4;
    int brow = tid >> 5, bcol4 = (tid & 31) * 4;
    const float* Ap = A + (size_t)(by * 128 + arow) * K;
    const float* Bp = B + (size_t)brow * N + bx * 128 + bcol4;
    unsigned long long acc[8][4];
#pragma unroll
    for (int i = 0; i < 8; i++)
#pragma unroll
        for (int j = 0; j < 4; j++) acc[i][j] = 0ull;
    for (int kt = 0; kt < K; kt += 8) {
        float4 av = *(const float4*)(Ap + kt + acol4);
        *(float2*)&As2[acol4 + 0][2 * arow] = make_float2(av.x, av.x);
        *(float2*)&As2[acol4 + 1][2 * arow] = make_float2(av.y, av.y);
        *(float2*)&As2[acol4 + 2][2 * arow] = make_float2(av.z, av.z);
        *(float2*)&As2[acol4 + 3][2 * arow] = make_float2(av.w, av.w);
        *(float4*)&Bs[brow][bcol4] = *(const float4*)(Bp + (size_t)kt * N);
        __syncthreads();
#pragma unroll
        for (int k = 0; k < 8; k++) {
            ulonglong2 a0 = *(const ulonglong2*)&As2[k][ty * 16 + 0];
            ulonglong2 a1 = *(const ulonglong2*)&As2[k][ty * 16 + 4];
            ulonglong2 a2 = *(const ulonglong2*)&As2[k][ty * 16 + 8];
            ulonglong2 a3 = *(const ulonglong2*)&As2[k][ty * 16 + 12];
            ulonglong2 b0 = *(const ulonglong2*)&Bs[k][tx * 8 + 0];
            ulonglong2 b1 = *(const ulonglong2*)&Bs[k][tx * 8 + 4];
            unsigned long long ap[8] = {a0.x, a0.y, a1.x, a1.y, a2.x, a2.y, a3.x, a3.y};
            unsigned long long bp[4] = {b0.x, b0.y, b1.x, b1.y};
#pragma unroll
            for (int i = 0; i < 8; i++)
#pragma unroll
                for (int j = 0; j < 4; j++) ffma2(acc[i][j], ap[i], bp[j]);
        }
        __syncthreads();
    }
#pragma unroll
    for (int i = 0; i < 8; i++) {
        float f[8];
#pragma unroll
        for (int j = 0; j < 4; j++) unpack2(acc[i][j], f[2 * j], f[2 * j + 1]);
        float* cp = C + (size_t)(by * 128 + ty * 8 + i) * N + bx * 128 + tx * 8;
        *(float4*)cp       = make_float4(f[0], f[1], f[2], f[3]);
        *(float4*)(cp + 4) = make_float4(f[4], f[5], f[6], f[7]);
    }
}

// ---------------- host launch ----------------
extern "C" void kernel_launch(void* const* d_in, const int* in_sizes, int n_in,
                              void* d_out, int out_size)
{
    const float* x      = (const float*)d_in[0];
    const float* Wt1    = (const float*)d_in[1];
    const float* bt1    = (const float*)d_in[2];
    const float* Wt2    = (const float*)d_in[3];
    const float* bt2    = (const float*)d_in[4];
    const float* W1     = (const float*)d_in[5];
    const float* b1     = (const float*)d_in[6];
    const float* W2     = (const float*)d_in[7];
    const float* b2     = (const float*)d_in[8];
    const float* matrix = (const float*)d_in[9];
    const float* lw     = (const float*)d_in[10];
    const float* lb     = (const float*)d_in[11];
    const void*  ei     = d_in[12];
    float* out = (float*)d_out;

    cudaFuncSetAttribute(hgemm<1>, cudaFuncAttributeMaxDynamicSharedMemorySize, HGEMM_SMEM);
    cudaFuncSetAttribute(hgemm<0>, cudaFuncAttributeMaxDynamicSharedMemorySize, HGEMM_SMEM);
    cudaFuncSetAttribute(mma_gemm_bf, cudaFuncAttributeMaxDynamicSharedMemorySize, GEMM_SMEM);
    cudaFuncSetAttribute(k_scores_mma, cudaFuncAttributeMaxDynamicSharedMemorySize, BUFSTRIDE);

    __half *pxh, *pWpTh, *pW2Th, *pt1h, *ph1h, *ph2linh;
    __nv_bfloat16 *pWmhi, *pWmlo, *ph2hi, *ph2lo, *pThi, *pTlo;
    float *pWcatf, *pWp, *pbprime;
    cudaGetSymbolAddress((void**)&pxh, g_xh);
    cudaGetSymbolAddress((void**)&pWcatf, g_Wcatf);
    cudaGetSymbolAddress((void**)&pWp, g_Wp);
    cudaGetSymbolAddress((void**)&pWpTh, g_WpTh);
    cudaGetSymbolAddress((void**)&pbprime, g_bprime);
    cudaGetSymbolAddress((void**)&pW2Th, g_W2Th);
    cudaGetSymbolAddress((void**)&pWmhi, g_WmThi);
    cudaGetSymbolAddress((void**)&pWmlo, g_WmTlo);
    cudaGetSymbolAddress((void**)&pt1h, g_t1h);
    cudaGetSymbolAddress((void**)&ph1h, g_h1h);
    cudaGetSymbolAddress((void**)&ph2linh, g_h2linh);
    cudaGetSymbolAddress((void**)&ph2hi, g_h2hi);
    cudaGetSymbolAddress((void**)&ph2lo, g_h2lo);
    cudaGetSymbolAddress((void**)&pThi, g_Thi);
    cudaGetSymbolAddress((void**)&pTlo, g_Tlo);

    // 1: convert x -> fp16 + Wcat fp32 + bcat (fused)
    k_prep1<<<65536 + 2048 + 1, 256>>>(x, Wt1, Wt2, bt1, bt2);
    // 2: W' = Wcat @ W1 (fp32, exact)
    sgemm_k<<<dim3(4, 8), 256>>>(pWcatf, W1, pWp, KIN, D1, D1);
    // 3: W'^T -> fp16, b' = bcat @ W1
    k_prep3<<<2049, 256>>>(W1);
    // 4 (profiled): t1 = x @ W' + b'  -> fp16 single-term (fuses GEMM1+GEMM2)
    hgemm<1><<<dim3(4, 1024), 256, HGEMM_SMEM>>>(pxh, pWpTh, pbprime, pt1h, D1, KIN);
    // 5: fused misc (detect + zero_cnt + W2^T fp16 + Wm^T bf16 split)
    k_misc<<<577, 256>>>((const int*)ei, W2, matrix);
    k_count<<<EE / 256, 256>>>(ei);
    k_isq<<<256, 256>>>();
    k_scanA<<<256, 256>>>();
    k_scanB<<<1, 256>>>();
    k_scanC<<<256, 256>>>();
    k_fill<<<EE / 256, 256>>>(ei);
    // h1 = relu(agg(t1) + b1) -> fp16 single
    conv_aggf<D1, 1, 1><<<NN * 32 / 256, 256>>>(pt1h, b1, ph1h, nullptr, nullptr);
    // h2lin = h1 @ W2 -> fp16 single-term
    hgemm<0><<<dim3(1, 1024), 256, HGEMM_SMEM>>>(ph1h, pW2Th, nullptr, ph2linh, DOUTD, D1);
    // h2 = agg(h2lin) + b2 -> bf16 hi/lo
    conv_aggf<DOUTD, 0, 0><<<NN * 32 / 256, 256>>>(ph2linh, b2, nullptr, ph2hi, ph2lo);
    // T = h2 @ matrix -> bf16 hi/lo (3-term, unattenuated stage kept accurate)
    mma_gemm_bf<<<dim3(1, 1024), 256, GEMM_SMEM>>>(
        ph2hi, ph2lo, pWmhi, pWmlo, pThi, pTlo, DOUTD, DOUTD);
    // scores + Linear(1,2) (3-term bf16, accurate)
    k_scores_mma<<<2048, 256, BUFSTRIDE>>>(pThi, pTlo, ph2hi, ph2lo, lw, lb, out);
}

// round 12
// speedup vs baseline: 8.9165x; 1.1071x over previous
#include <cuda_runtime.h>
#include <cuda_bf16.h>
#include <cuda_fp16.h>
#include <cstdint>

#define NN   65536
#define EE   1048576
#define D1   512
#define DOUTD 128
#define KIN  1024

// ---------------- device scratch (static: allocation-free) ----------------
__device__ __half g_xh[(size_t)NN * KIN];             // 128 MB fp16 x
__device__ float g_Wcatf[KIN * D1];                   // 2 MB fp32 concat [Wt1;Wt2]
__device__ float g_Wp[KIN * D1];                      // 2 MB fp32 W' = Wcat@W1
__device__ __half g_WpTh[D1 * KIN];                   // 1 MB  W'^T fp16
__device__ float g_bcat[D1];
__device__ float g_bprime[D1];
__device__ __half g_W2Th[DOUTD * D1];                 // fp16 W2^T
__device__ __half g_WmTh[DOUTD * DOUTD];              // fp16 matrix^T
__device__ __half g_t1h[(size_t)NN * D1];             // 64 MB fp16 t1
__device__ __half g_h1h[(size_t)NN * D1];             // 64 MB fp16 h1
__device__ __half g_h2linh[(size_t)NN * DOUTD];       // 16 MB fp16 h2lin
__device__ __half g_h2h[(size_t)NN * DOUTD];          // 16 MB fp16 h2
__device__ __half g_Th[(size_t)NN * DOUTD];           // 16 MB fp16 T
__device__ float g_isq[NN];
__device__ int   g_cnt[NN];
__device__ int   g_rowptr[NN + 1];
__device__ int   g_cursor[NN];
__device__ int   g_bsum[256];
__device__ int   g_boff[256];
__device__ int   g_adj[EE];
__device__ int   g_is64;

// ---------------- tiny helpers ----------------
__device__ __forceinline__ unsigned pkh(__half2 h) {
    return *(unsigned*)&h;
}
__device__ __forceinline__ uint32_t smem_u32(const void* p) {
    uint32_t a;
    asm("{ .reg .u64 t; cvta.to.shared.u64 t, %1; cvt.u32.u64 %0, t; }" : "=r"(a) : "l"(p));
    return a;
}
__device__ __forceinline__ void ffma2(unsigned long long& d, unsigned long long a, unsigned long long b) {
    asm("fma.rn.f32x2 %0, %1, %2, %0;" : "+l"(d) : "l"(a), "l"(b));
}
__device__ __forceinline__ void unpack2(unsigned long long v, float& lo, float& hi) {
    asm("mov.b64 {%0, %1}, %2;" : "=f"(lo), "=f"(hi) : "l"(v));
}

#define LDSM_X4(r, ad) \
    asm volatile("ldmatrix.sync.aligned.m8n8.x4.shared.b16 {%0,%1,%2,%3}, [%4];" \
                 : "=r"((r)[0]), "=r"((r)[1]), "=r"((r)[2]), "=r"((r)[3]) : "r"(ad))
#define MMAH16816(c, a, b) \
    asm volatile("mma.sync.aligned.m16n8k16.row.col.f32.f16.f16.f32 " \
                 "{%0,%1,%2,%3}, {%4,%5,%6,%7}, {%8,%9}, {%0,%1,%2,%3};" \
                 : "+f"((c)[0]), "+f"((c)[1]), "+f"((c)[2]), "+f"((c)[3]) \
                 : "r"((a)[0]), "r"((a)[1]), "r"((a)[2]), "r"((a)[3]), \
                   "r"((b)[0]), "r"((b)[1]))
#define CP16(sa, gp) \
    asm volatile("cp.async.cg.shared.global [%0], [%1], 16;" :: "r"(sa), "l"(gp))
#define CP_COMMIT() asm volatile("cp.async.commit_group;" ::: "memory")
#define CP_WAIT2()  asm volatile("cp.async.wait_group 2;" ::: "memory")
#define CP_WAIT1()  asm volatile("cp.async.wait_group 1;" ::: "memory")
#define CP_WAIT0()  asm volatile("cp.async.wait_group 0;" ::: "memory")

__device__ __forceinline__ uint32_t swz(uint32_t o) { return o ^ ((o >> 3) & 0x70); }

__device__ __forceinline__ int edge_at(const void* eiv, int idx) {
    if (g_is64) return (int)((const long long*)eiv)[idx];
    return ((const int*)eiv)[idx];
}

// ---------------- fused prep 1: x -> fp16, build fp32 Wcat, bcat ----------
__global__ void k_prep1(const float* __restrict__ x,
                        const float* __restrict__ Wt1, const float* __restrict__ Wt2,
                        const float* __restrict__ bt1, const float* __restrict__ bt2)
{
    int b = blockIdx.x;
    if (b < 65536) {
        size_t i = ((size_t)b * 256 + threadIdx.x) * 4;
        float4 v = *(const float4*)(x + i);
        uint2 hv = { pkh(__floats2half2_rn(v.x, v.y)), pkh(__floats2half2_rn(v.z, v.w)) };
        *(uint2*)(g_xh + i) = hv;
    } else if (b < 65536 + 2048) {
        int idx = (b - 65536) * 256 + threadIdx.x;   // [1024 k][512 n] row-major
        int k = idx >> 9, n = idx & 511;
        g_Wcatf[idx] = (k < 256) ? Wt1[k * D1 + n] : Wt2[(k - 256) * D1 + n];
    } else {
#pragma unroll
        for (int r = 0; r < 2; r++) {
            int j = threadIdx.x + 256 * r;
            g_bcat[j] = bt1[j] + bt2[j];
        }
    }
}

// ---------------- prep 3: W'^T -> fp16 + b' = bcat@W1 ----------------
__global__ void k_prep3(const float* __restrict__ W1) {
    int b = blockIdx.x;
    if (b < 2048) {
        int idx = b * 256 + threadIdx.x;             // [512 n][1024 k]
        int k = idx & 1023;
        int n = idx >> 10;
        g_WpTh[idx] = __float2half(g_Wp[k * D1 + n]);
    } else {
#pragma unroll
        for (int r = 0; r < 2; r++) {
            int j = threadIdx.x + 256 * r;
            float s = 0.0f;
#pragma unroll 4
            for (int i = 0; i < D1; i++) s += g_bcat[i] * W1[i * D1 + j];
            g_bprime[j] = s;
        }
    }
}

// ---------------- fused misc prep: detect + zero_cnt + W2^T + Wm^T ----------
__global__ void k_misc(const int* __restrict__ ei,
                       const float* __restrict__ W2, const float* __restrict__ Wm)
{
    int b = blockIdx.x;
    if (b == 0) {
        if (threadIdx.x < 32) {
            int lane = threadIdx.x;
            int bad = 0;
#pragma unroll
            for (int i = lane; i < 256; i += 32) bad |= (ei[2 * i + 1] != 0);
            unsigned m = __ballot_sync(0xFFFFFFFF, bad);
            if (lane == 0) g_is64 = (m == 0) ? 1 : 0;
        }
    } else if (b < 257) {
        g_cnt[(b - 1) * 256 + threadIdx.x] = 0;
    } else if (b < 513) {
        int idx = (b - 257) * 256 + threadIdx.x;     // [128 n][512 k]
        int n = idx >> 9, k = idx & 511;
        g_W2Th[idx] = __float2half(W2[k * DOUTD + n]);
    } else {
        int idx = (b - 513) * 256 + threadIdx.x;     // [128 n][128 k]
        int n = idx >> 7, k = idx & 127;
        g_WmTh[idx] = __float2half(Wm[k * DOUTD + n]);
    }
}

__global__ void k_count(const void* __restrict__ eiv) {
    int e = blockIdx.x * blockDim.x + threadIdx.x;
    if (e >= EE) return;
    atomicAdd(&g_cnt[edge_at(eiv, EE + e)], 1);
}
__global__ void k_isq() {
    int i = blockIdx.x * blockDim.x + threadIdx.x;
    if (i < NN) g_isq[i] = rsqrtf((float)g_cnt[i] + 1.0f);
}
__global__ void k_scanA() {
    __shared__ int sh[256];
    int t = threadIdx.x, b = blockIdx.x;
    sh[t] = g_cnt[b * 256 + t];
    __syncthreads();
    for (int off = 128; off > 0; off >>= 1) {
        if (t < off) sh[t] += sh[t + off];
        __syncthreads();
    }
    if (t == 0) g_bsum[b] = sh[0];
}
__global__ void k_scanB() {
    __shared__ int sh[256];
    int t = threadIdx.x;
    int v = g_bsum[t];
    sh[t] = v;
    __syncthreads();
    for (int off = 1; off < 256; off <<= 1) {
        int x = (t >= off) ? sh[t - off] : 0;
        __syncthreads();
        sh[t] += x;
        __syncthreads();
    }
    g_boff[t] = sh[t] - v;
    if (t == 255) g_rowptr[NN] = sh[255];
}
__global__ void k_scanC() {
    __shared__ int sh[256];
    int t = threadIdx.x, b = blockIdx.x;
    int i = b * 256 + t;
    int v = g_cnt[i];
    sh[t] = v;
    __syncthreads();
    for (int off = 1; off < 256; off <<= 1) {
        int x = (t >= off) ? sh[t - off] : 0;
        __syncthreads();
        sh[t] += x;
        __syncthreads();
    }
    int excl = sh[t] - v + g_boff[b];
    g_rowptr[i] = excl;
    g_cursor[i] = excl;
}
__global__ void k_fill(const void* __restrict__ eiv) {
    int e = blockIdx.x * blockDim.x + threadIdx.x;
    if (e >= EE) return;
    int s = edge_at(eiv, e);
    int d = edge_at(eiv, EE + e);
    g_adj[atomicAdd(&g_cursor[d], 1)] = s;
}

// ---------------- single-term fp16 warp-MMA GEMM, triple-buffered ----------
// C[M,N] = A[M,K] @ B^T[N,K], fp16 in, fp32 accumulate, fp16 out.
// BM=64, BN=128, BK=64. 256 threads, 8 warps (2 m x 4 n), warp tile 32x32.
// B fragments loaded with ldmatrix.x4 (2 instrs per ks instead of 4).
static constexpr uint32_t HOFF_A = 0, HOFF_B = 8192;
static constexpr uint32_t HBUF = 24576;
#define HGEMM_SMEM 73728

template <int BIAS>
__global__ __launch_bounds__(256, 2) void hgemm(
    const __half* __restrict__ A, const __half* __restrict__ B,
    const float* __restrict__ bias, __half* __restrict__ C, int N, int K)
{
    extern __shared__ char sm[];
    uint32_t smb = smem_u32(sm);
    const int tid = threadIdx.x, wid = tid >> 5, lane = tid & 31;
    const int wm = wid & 1, wn = wid >> 1;
    const int m0 = blockIdx.y * 64, n0 = blockIdx.x * 128;

    float acc[2][4][4];
#pragma unroll
    for (int mi = 0; mi < 2; mi++)
#pragma unroll
        for (int ni = 0; ni < 4; ni++)
#pragma unroll
            for (int q = 0; q < 4; q++) acc[mi][ni][q] = 0.0f;

    const int arow = tid >> 3, ac = tid & 7;
    const uint32_t soff = swz((uint32_t)(arow * 128 + ac * 16));

    auto issue = [&](int buf, int kt) {
        uint32_t sb = smb + (uint32_t)buf * HBUF;
#pragma unroll
        for (int r = 0; r < 2; r++) {
            int row = arow + 32 * r;
            uint32_t off = soff + (uint32_t)(r * 32 * 128);
            const size_t gi = (size_t)(m0 + row) * K + kt + ac * 8;
            CP16(sb + HOFF_A + off, A + gi);
        }
#pragma unroll
        for (int r = 0; r < 4; r++) {
            int row = arow + 32 * r;
            uint32_t off = soff + (uint32_t)(r * 32 * 128);
            const size_t gi = (size_t)(n0 + row) * K + kt + ac * 8;
            CP16(sb + HOFF_B + off, B + gi);
        }
        CP_COMMIT();
    };

    const int Cn = K / 64;
    issue(0, 0);
    issue(1, 64);
    for (int c = 0; c < Cn; c++) {
        if (c + 2 < Cn) { issue((c + 2) % 3, (c + 2) * 64); CP_WAIT2(); }
        else if (c + 1 < Cn) CP_WAIT1();
        else CP_WAIT0();
        __syncthreads();
        uint32_t sbase = smb + (uint32_t)(c % 3) * HBUF;
#pragma unroll
        for (int ks = 0; ks < 4; ks++) {
            uint32_t ah[2][4], bh[4][2];
#pragma unroll
            for (int mi = 0; mi < 2; mi++) {
                int row = wm * 32 + mi * 16 + (lane & 15);
                int kc = ks * 16 + (lane >> 4) * 8;
                uint32_t o = swz((uint32_t)(row * 128 + kc * 2));
                LDSM_X4(ah[mi], sbase + HOFF_A + o);
            }
#pragma unroll
            for (int nq = 0; nq < 2; nq++) {
                int row = wn * 32 + nq * 16 + ((lane >> 4) & 1) * 8 + (lane & 7);
                int kc = ks * 16 + ((lane >> 3) & 1) * 8;
                uint32_t o = swz((uint32_t)(row * 128 + kc * 2));
                uint32_t r4[4];
                LDSM_X4(r4, sbase + HOFF_B + o);
                bh[2 * nq][0] = r4[0]; bh[2 * nq][1] = r4[1];
                bh[2 * nq + 1][0] = r4[2]; bh[2 * nq + 1][1] = r4[3];
            }
#pragma unroll
            for (int mi = 0; mi < 2; mi++)
#pragma unroll
                for (int ni = 0; ni < 4; ni++)
                    MMAH16816(acc[mi][ni], ah[mi], bh[ni]);
        }
        __syncthreads();
    }

    const int r = lane >> 2, cq = (lane & 3) * 2;
#pragma unroll
    for (int mi = 0; mi < 2; mi++) {
        const int mbase = m0 + wm * 32 + mi * 16 + r;
#pragma unroll
        for (int ni = 0; ni < 4; ni++) {
            const int col = n0 + wn * 32 + ni * 8 + cq;
            float b0 = 0.0f, b1 = 0.0f;
            if (BIAS) { float2 bb = *(const float2*)(bias + col); b0 = bb.x; b1 = bb.y; }
#pragma unroll
            for (int h = 0; h < 2; h++) {
                const int m = mbase + 8 * h;
                float v0 = acc[mi][ni][2 * h + 0] + b0;
                float v1 = acc[mi][ni][2 * h + 1] + b1;
                *(__half2*)(C + (size_t)m * N + col) = __floats2half2_rn(v0, v1);
            }
        }
    }
}

// ---------------- bilinear scores, fp16 single-term + Linear(1,2) -----------
// per chunk b: S_b[256,256] = T_b[256,128] @ E_b[256,128]^T
// grid.x = 256 chunks * 8 subtiles (4 m-blocks x 2 n-blocks of 64x128)
__global__ __launch_bounds__(256, 2) void k_scores_h(
    const __half* __restrict__ Th, const __half* __restrict__ Eh,
    const float* __restrict__ lw, const float* __restrict__ lb,
    float* __restrict__ out)
{
    __shared__ __align__(1024) char sm[24576];   // A 8KB + B 16KB
    uint32_t smb = smem_u32(sm);
    const int tid = threadIdx.x, wid = tid >> 5, lane = tid & 31;
    const int wm = wid & 1, wn = wid >> 1;
    const int blk = blockIdx.x;
    const int chunk = blk >> 3, sub = blk & 7;
    const int mblk = sub >> 1, nblk = sub & 1;
    const int m0 = chunk * 256 + mblk * 64;
    const int n0 = chunk * 256 + nblk * 128;
    const int K = DOUTD;

    float acc[2][4][4];
#pragma unroll
    for (int mi = 0; mi < 2; mi++)
#pragma unroll
        for (int ni = 0; ni < 4; ni++)
#pragma unroll
            for (int q = 0; q < 4; q++) acc[mi][ni][q] = 0.0f;

    const int arow = tid >> 3, ac = tid & 7;
    const uint32_t soff = swz((uint32_t)(arow * 128 + ac * 16));

#pragma unroll
    for (int kt = 0; kt < K; kt += 64) {
        __syncthreads();
#pragma unroll
        for (int r = 0; r < 2; r++) {
            int row = arow + 32 * r;
            uint32_t off = soff + (uint32_t)(r * 32 * 128);
            const size_t gi = (size_t)(m0 + row) * K + kt + ac * 8;
            *(uint4*)(sm + HOFF_A + off) = *(const uint4*)(Th + gi);
        }
#pragma unroll
        for (int r = 0; r < 4; r++) {
            int row = arow + 32 * r;
            uint32_t off = soff + (uint32_t)(r * 32 * 128);
            const size_t gi = (size_t)(n0 + row) * K + kt + ac * 8;
            *(uint4*)(sm + HOFF_B + off) = *(const uint4*)(Eh + gi);
        }
        __syncthreads();
#pragma unroll
        for (int ks = 0; ks < 4; ks++) {
            uint32_t ah[2][4], bh[4][2];
#pragma unroll
            for (int mi = 0; mi < 2; mi++) {
                int row = wm * 32 + mi * 16 + (lane & 15);
                int kc = ks * 16 + (lane >> 4) * 8;
                uint32_t o = swz((uint32_t)(row * 128 + kc * 2));
                LDSM_X4(ah[mi], smb + HOFF_A + o);
            }
#pragma unroll
            for (int nq = 0; nq < 2; nq++) {
                int row = wn * 32 + nq * 16 + ((lane >> 4) & 1) * 8 + (lane & 7);
                int kc = ks * 16 + ((lane >> 3) & 1) * 8;
                uint32_t o = swz((uint32_t)(row * 128 + kc * 2));
                uint32_t r4[4];
                LDSM_X4(r4, smb + HOFF_B + o);
                bh[2 * nq][0] = r4[0]; bh[2 * nq][1] = r4[1];
                bh[2 * nq + 1][0] = r4[2]; bh[2 * nq + 1][1] = r4[3];
            }
#pragma unroll
            for (int mi = 0; mi < 2; mi++)
#pragma unroll
                for (int ni = 0; ni < 4; ni++)
                    MMAH16816(acc[mi][ni], ah[mi], bh[ni]);
        }
    }

    const float w0 = lw[0], w1 = lw[1], c0 = lb[0], c1 = lb[1];
    const int r = lane >> 2, cq = (lane & 3) * 2;
#pragma unroll
    for (int mi = 0; mi < 2; mi++) {
        const int irow = mblk * 64 + wm * 32 + mi * 16 + r;
#pragma unroll
        for (int ni = 0; ni < 4; ni++) {
            const int jcol = nblk * 128 + wn * 32 + ni * 8 + cq;
#pragma unroll
            for (int h = 0; h < 2; h++) {
                float s0 = acc[mi][ni][2 * h + 0];
                float s1 = acc[mi][ni][2 * h + 1];
                size_t o = (((size_t)chunk * 256 + irow + 8 * h) * 256 + jcol) * 2;
                *(float4*)(out + o) = make_float4(s0 * w0 + c0, s0 * w1 + c1,
                                                  s1 * w0 + c0, s1 * w1 + c1);
            }
        }
    }
}

// ---------------- CSR aggregate D=512, fp16 in/out, uint4 lanes, relu -------
__global__ void conv_agg512(const __half* __restrict__ hin, const float* __restrict__ bias,
                            __half* __restrict__ oh)
{
    int n = (blockIdx.x * blockDim.x + threadIdx.x) >> 5;
    int lane = threadIdx.x & 31;
    if (n >= NN) return;
    float iq = g_isq[n];
    float acc[2][8];
    {
        float w = iq * iq;
        const uint4* hp = (const uint4*)(hin + (size_t)n * D1);
#pragma unroll
        for (int i = 0; i < 2; i++) {
            uint4 v = hp[lane + 32 * i];
            float2 f0 = __half22float2(*(const __half2*)&v.x);
            float2 f1 = __half22float2(*(const __half2*)&v.y);
            float2 f2 = __half22float2(*(const __half2*)&v.z);
            float2 f3 = __half22float2(*(const __half2*)&v.w);
            acc[i][0] = f0.x * w; acc[i][1] = f0.y * w;
            acc[i][2] = f1.x * w; acc[i][3] = f1.y * w;
            acc[i][4] = f2.x * w; acc[i][5] = f2.y * w;
            acc[i][6] = f3.x * w; acc[i][7] = f3.y * w;
        }
    }
    int beg = g_rowptr[n], end = g_rowptr[n + 1];
    for (int k = beg; k < end; k++) {
        int s = g_adj[k];
        float w = g_isq[s] * iq;
        const uint4* hs = (const uint4*)(hin + (size_t)s * D1);
#pragma unroll
        for (int i = 0; i < 2; i++) {
            uint4 v = hs[lane + 32 * i];
            float2 f0 = __half22float2(*(const __half2*)&v.x);
            float2 f1 = __half22float2(*(const __half2*)&v.y);
            float2 f2 = __half22float2(*(const __half2*)&v.z);
            float2 f3 = __half22float2(*(const __half2*)&v.w);
            acc[i][0] += f0.x * w; acc[i][1] += f0.y * w;
            acc[i][2] += f1.x * w; acc[i][3] += f1.y * w;
            acc[i][4] += f2.x * w; acc[i][5] += f2.y * w;
            acc[i][6] += f3.x * w; acc[i][7] += f3.y * w;
        }
    }
#pragma unroll
    for (int i = 0; i < 2; i++) {
        int col = (lane + 32 * i) * 8;
        float4 b0 = *(const float4*)(bias + col);
        float4 b1 = *(const float4*)(bias + col + 4);
        float v0 = fmaxf(acc[i][0] + b0.x, 0.0f), v1 = fmaxf(acc[i][1] + b0.y, 0.0f);
        float v2 = fmaxf(acc[i][2] + b0.z, 0.0f), v3 = fmaxf(acc[i][3] + b0.w, 0.0f);
        float v4 = fmaxf(acc[i][4] + b1.x, 0.0f), v5 = fmaxf(acc[i][5] + b1.y, 0.0f);
        float v6 = fmaxf(acc[i][6] + b1.z, 0.0f), v7 = fmaxf(acc[i][7] + b1.w, 0.0f);
        uint4 hv = { pkh(__floats2half2_rn(v0, v1)), pkh(__floats2half2_rn(v2, v3)),
                     pkh(__floats2half2_rn(v4, v5)), pkh(__floats2half2_rn(v6, v7)) };
        *(uint4*)(oh + (size_t)n * D1 + col) = hv;
    }
}

// ---------------- CSR aggregate D=128, fp16 in/out, no relu ----------------
__global__ void conv_agg128(const __half* __restrict__ hin, const float* __restrict__ bias,
                            __half* __restrict__ oh)
{
    int n = (blockIdx.x * blockDim.x + threadIdx.x) >> 5;
    int lane = threadIdx.x & 31;
    if (n >= NN) return;
    float iq = g_isq[n];
    float acc[4];
    {
        float w = iq * iq;
        uint2 v = ((const uint2*)(hin + (size_t)n * DOUTD))[lane];
        float2 f0 = __half22float2(*(const __half2*)&v.x);
        float2 f1 = __half22float2(*(const __half2*)&v.y);
        acc[0] = f0.x * w; acc[1] = f0.y * w;
        acc[2] = f1.x * w; acc[3] = f1.y * w;
    }
    int beg = g_rowptr[n], end = g_rowptr[n + 1];
    for (int k = beg; k < end; k++) {
        int s = g_adj[k];
        float w = g_isq[s] * iq;
        uint2 v = ((const uint2*)(hin + (size_t)s * DOUTD))[lane];
        float2 f0 = __half22float2(*(const __half2*)&v.x);
        float2 f1 = __half22float2(*(const __half2*)&v.y);
        acc[0] += f0.x * w; acc[1] += f0.y * w;
        acc[2] += f1.x * w; acc[3] += f1.y * w;
    }
    int col = lane * 4;
    float4 bb = *(const float4*)(bias + col);
    float v0 = acc[0] + bb.x, v1 = acc[1] + bb.y;
    float v2 = acc[2] + bb.z, v3 = acc[3] + bb.w;
    uint2 hv = { pkh(__floats2half2_rn(v0, v1)), pkh(__floats2half2_rn(v2, v3)) };
    *(uint2*)(oh + (size_t)n * DOUTD + col) = hv;
}

// ---------------- f32x2 SGEMM (W' = Wcat@W1, tiny) ----------------
__global__ __launch_bounds__(256, 2) void sgemm_k(
    const float* __restrict__ A, const float* __restrict__ B,
    float* __restrict__ C, int M, int N, int K)
{
    __shared__ __align__(16) float As2[8][268];
    __shared__ __align__(16) float Bs[8][128];
    int tid = threadIdx.x;
    int bx = blockIdx.x, by = blockIdx.y;
    int ty = tid >> 4, tx = tid & 15;
    int arow = tid >> 1, acol4 = (tid & 1) * 4;
    int brow = tid >> 5, bcol4 = (tid & 31) * 4;
    const float* Ap = A + (size_t)(by * 128 + arow) * K;
    const float* Bp = B + (size_t)brow * N + bx * 128 + bcol4;
    unsigned long long acc[8][4];
#pragma unroll
    for (int i = 0; i < 8; i++)
#pragma unroll
        for (int j = 0; j < 4; j++) acc[i][j] = 0ull;
    for (int kt = 0; kt < K; kt += 8) {
        float4 av = *(const float4*)(Ap + kt + acol4);
        *(float2*)&As2[acol4 + 0][2 * arow] = make_float2(av.x, av.x);
        *(float2*)&As2[acol4 + 1][2 * arow] = make_float2(av.y, av.y);
        *(float2*)&As2[acol4 + 2][2 * arow] = make_float2(av.z, av.z);
        *(float2*)&As2[acol4 + 3][2 * arow] = make_float2(av.w, av.w);
        *(float4*)&Bs[brow][bcol4] = *(const float4*)(Bp + (size_t)kt * N);
        __syncthreads();
#pragma unroll
        for (int k = 0; k < 8; k++) {
            ulonglong2 a0 = *(const ulonglong2*)&As2[k][ty * 16 + 0];
            ulonglong2 a1 = *(const ulonglong2*)&As2[k][ty * 16 + 4];
            ulonglong2 a2 = *(const ulonglong2*)&As2[k][ty * 16 + 8];
            ulonglong2 a3 = *(const ulonglong2*)&As2[k][ty * 16 + 12];
            ulonglong2 b0 = *(const ulonglong2*)&Bs[k][tx * 8 + 0];
            ulonglong2 b1 = *(const ulonglong2*)&Bs[k][tx * 8 + 4];
            unsigned long long ap[8] = {a0.x, a0.y, a1.x, a1.y, a2.x, a2.y, a3.x, a3.y};
            unsigned long long bp[4] = {b0.x, b0.y, b1.x, b1.y};
#pragma unroll
            for (int i = 0; i < 8; i++)
#pragma unroll
                for (int j = 0; j < 4; j++) ffma2(acc[i][j], ap[i], bp[j]);
        }
        __syncthreads();
    }
#pragma unroll
    for (int i = 0; i < 8; i++) {
        float f[8];
#pragma unroll
        for (int j = 0; j < 4; j++) unpack2(acc[i][j], f[2 * j], f[2 * j + 1]);
        float* cp = C + (size_t)(by * 128 + ty * 8 + i) * N + bx * 128 + tx * 8;
        *(float4*)cp       = make_float4(f[0], f[1], f[2], f[3]);
        *(float4*)(cp + 4) = make_float4(f[4], f[5], f[6], f[7]);
    }
}

// ---------------- host launch ----------------
extern "C" void kernel_launch(void* const* d_in, const int* in_sizes, int n_in,
                              void* d_out, int out_size)
{
    const float* x      = (const float*)d_in[0];
    const float* Wt1    = (const float*)d_in[1];
    const float* bt1    = (const float*)d_in[2];
    const float* Wt2    = (const float*)d_in[3];
    const float* bt2    = (const float*)d_in[4];
    const float* W1     = (const float*)d_in[5];
    const float* b1     = (const float*)d_in[6];
    const float* W2     = (const float*)d_in[7];
    const float* b2     = (const float*)d_in[8];
    const float* matrix = (const float*)d_in[9];
    const float* lw     = (const float*)d_in[10];
    const float* lb     = (const float*)d_in[11];
    const void*  ei     = d_in[12];
    float* out = (float*)d_out;

    cudaFuncSetAttribute(hgemm<1>, cudaFuncAttributeMaxDynamicSharedMemorySize, HGEMM_SMEM);
    cudaFuncSetAttribute(hgemm<0>, cudaFuncAttributeMaxDynamicSharedMemorySize, HGEMM_SMEM);

    __half *pxh, *pWpTh, *pW2Th, *pWmTh, *pt1h, *ph1h, *ph2linh, *ph2h, *pTh;
    float *pWcatf, *pWp, *pbprime;
    cudaGetSymbolAddress((void**)&pxh, g_xh);
    cudaGetSymbolAddress((void**)&pWcatf, g_Wcatf);
    cudaGetSymbolAddress((void**)&pWp, g_Wp);
    cudaGetSymbolAddress((void**)&pWpTh, g_WpTh);
    cudaGetSymbolAddress((void**)&pbprime, g_bprime);
    cudaGetSymbolAddress((void**)&pW2Th, g_W2Th);
    cudaGetSymbolAddress((void**)&pWmTh, g_WmTh);
    cudaGetSymbolAddress((void**)&pt1h, g_t1h);
    cudaGetSymbolAddress((void**)&ph1h, g_h1h);
    cudaGetSymbolAddress((void**)&ph2linh, g_h2linh);
    cudaGetSymbolAddress((void**)&ph2h, g_h2h);
    cudaGetSymbolAddress((void**)&pTh, g_Th);

    // 1: convert x -> fp16 + Wcat fp32 + bcat (fused)
    k_prep1<<<65536 + 2048 + 1, 256>>>(x, Wt1, Wt2, bt1, bt2);
    // 2: W' = Wcat @ W1 (fp32, exact)
    sgemm_k<<<dim3(4, 8), 256>>>(pWcatf, W1, pWp, KIN, D1, D1);
    // 3: W'^T -> fp16, b' = bcat @ W1
    k_prep3<<<2049, 256>>>(W1);
    // 4 (profiled): t1 = x @ W' + b'  -> fp16 (fuses GEMM1+GEMM2)
    hgemm<1><<<dim3(4, 1024), 256, HGEMM_SMEM>>>(pxh, pWpTh, pbprime, pt1h, D1, KIN);
    // 5: fused misc (detect + zero_cnt + W2^T fp16 + Wm^T fp16)
    k_misc<<<577, 256>>>((const int*)ei, W2, matrix);
    k_count<<<EE / 256, 256>>>(ei);
    k_isq<<<256, 256>>>();
    k_scanA<<<256, 256>>>();
    k_scanB<<<1, 256>>>();
    k_scanC<<<256, 256>>>();
    k_fill<<<EE / 256, 256>>>(ei);
    // h1 = relu(agg(t1) + b1) -> fp16
    conv_agg512<<<NN * 32 / 256, 256>>>(pt1h, b1, ph1h);
    // h2lin = h1 @ W2 -> fp16
    hgemm<0><<<dim3(1, 1024), 256, HGEMM_SMEM>>>(ph1h, pW2Th, nullptr, ph2linh, DOUTD, D1);
    // h2 = agg(h2lin) + b2 -> fp16
    conv_agg128<<<NN * 32 / 256, 256>>>(ph2linh, b2, ph2h);
    // T = h2 @ matrix -> fp16
    hgemm<0><<<dim3(1, 1024), 256, HGEMM_SMEM>>>(ph2h, pWmTh, nullptr, pTh, DOUTD, DOUTD);
    // scores + Linear(1,2)
    k_scores_h<<<2048, 256>>>(pTh, ph2h, lw, lb, out);
}

// round 13
// speedup vs baseline: 9.1284x; 1.0238x over previous
#include <cuda_runtime.h>
#include <cuda_bf16.h>
#include <cuda_fp16.h>
#include <cstdint>

#define NN   65536
#define EE   1048576
#define D1   512
#define DOUTD 128
#define KIN  1024

// ---------------- device scratch (static: allocation-free) ----------------
__device__ __half g_xh[(size_t)NN * KIN];             // 128 MB fp16 x
__device__ float g_Wcatf[KIN * D1];                   // 2 MB fp32 concat [Wt1;Wt2]
__device__ float g_Wp[KIN * D1];                      // 2 MB fp32 W' = Wcat@W1
__device__ __half g_WpTh[D1 * KIN];                   // 1 MB  W'^T fp16
__device__ float g_bcat[D1];
__device__ float g_bprime[D1];
__device__ __half g_W2Th[DOUTD * D1];                 // fp16 W2^T
__device__ __half g_WmTh[DOUTD * DOUTD];              // fp16 matrix^T
__device__ __half g_t1h[(size_t)NN * D1];             // 64 MB fp16 t1
__device__ __half g_h1h[(size_t)NN * D1];             // 64 MB fp16 h1
__device__ __half g_h2linh[(size_t)NN * DOUTD];       // 16 MB fp16 h2lin
__device__ __half g_h2h[(size_t)NN * DOUTD];          // 16 MB fp16 h2
__device__ __half g_Th[(size_t)NN * DOUTD];           // 16 MB fp16 T
__device__ float g_isq[NN];
__device__ int   g_cnt[NN];
__device__ int   g_rowptr[NN + 1];
__device__ int   g_cursor[NN];
__device__ int   g_bsum[256];
__device__ int   g_boff[256];
__device__ int   g_adj[EE];
__device__ int   g_is64;

// ---------------- tiny helpers ----------------
__device__ __forceinline__ unsigned pkh(__half2 h) {
    return *(unsigned*)&h;
}
__device__ __forceinline__ uint32_t smem_u32(const void* p) {
    uint32_t a;
    asm("{ .reg .u64 t; cvta.to.shared.u64 t, %1; cvt.u32.u64 %0, t; }" : "=r"(a) : "l"(p));
    return a;
}
__device__ __forceinline__ void ffma2(unsigned long long& d, unsigned long long a, unsigned long long b) {
    asm("fma.rn.f32x2 %0, %1, %2, %0;" : "+l"(d) : "l"(a), "l"(b));
}
__device__ __forceinline__ void unpack2(unsigned long long v, float& lo, float& hi) {
    asm("mov.b64 {%0, %1}, %2;" : "=f"(lo), "=f"(hi) : "l"(v));
}

#define LDSM_X4(r, ad) \
    asm volatile("ldmatrix.sync.aligned.m8n8.x4.shared.b16 {%0,%1,%2,%3}, [%4];" \
                 : "=r"((r)[0]), "=r"((r)[1]), "=r"((r)[2]), "=r"((r)[3]) : "r"(ad))
#define MMAH16816(c, a, b) \
    asm volatile("mma.sync.aligned.m16n8k16.row.col.f32.f16.f16.f32 " \
                 "{%0,%1,%2,%3}, {%4,%5,%6,%7}, {%8,%9}, {%0,%1,%2,%3};" \
                 : "+f"((c)[0]), "+f"((c)[1]), "+f"((c)[2]), "+f"((c)[3]) \
                 : "r"((a)[0]), "r"((a)[1]), "r"((a)[2]), "r"((a)[3]), \
                   "r"((b)[0]), "r"((b)[1]))
#define CP16(sa, gp) \
    asm volatile("cp.async.cg.shared.global [%0], [%1], 16;" :: "r"(sa), "l"(gp))
#define CP_COMMIT() asm volatile("cp.async.commit_group;" ::: "memory")
#define CP_WAIT2()  asm volatile("cp.async.wait_group 2;" ::: "memory")
#define CP_WAIT1()  asm volatile("cp.async.wait_group 1;" ::: "memory")
#define CP_WAIT0()  asm volatile("cp.async.wait_group 0;" ::: "memory")

__device__ __forceinline__ uint32_t swz(uint32_t o) { return o ^ ((o >> 3) & 0x70); }

__device__ __forceinline__ int edge_at(const void* eiv, int idx) {
    if (g_is64) return (int)((const long long*)eiv)[idx];
    return ((const int*)eiv)[idx];
}

// ---------------- fused prep 1: x -> fp16, build fp32 Wcat, bcat ----------
__global__ void k_prep1(const float* __restrict__ x,
                        const float* __restrict__ Wt1, const float* __restrict__ Wt2,
                        const float* __restrict__ bt1, const float* __restrict__ bt2)
{
    int b = blockIdx.x;
    if (b < 65536) {
        size_t i = ((size_t)b * 256 + threadIdx.x) * 4;
        float4 v = *(const float4*)(x + i);
        uint2 hv = { pkh(__floats2half2_rn(v.x, v.y)), pkh(__floats2half2_rn(v.z, v.w)) };
        *(uint2*)(g_xh + i) = hv;
    } else if (b < 65536 + 2048) {
        int idx = (b - 65536) * 256 + threadIdx.x;   // [1024 k][512 n] row-major
        int k = idx >> 9, n = idx & 511;
        g_Wcatf[idx] = (k < 256) ? Wt1[k * D1 + n] : Wt2[(k - 256) * D1 + n];
    } else {
#pragma unroll
        for (int r = 0; r < 2; r++) {
            int j = threadIdx.x + 256 * r;
            g_bcat[j] = bt1[j] + bt2[j];
        }
    }
}

// ---------------- prep 3: W'^T -> fp16 + b' = bcat@W1 ----------------
__global__ void k_prep3(const float* __restrict__ W1) {
    int b = blockIdx.x;
    if (b < 2048) {
        int idx = b * 256 + threadIdx.x;             // [512 n][1024 k]
        int k = idx & 1023;
        int n = idx >> 10;
        g_WpTh[idx] = __float2half(g_Wp[k * D1 + n]);
    } else {
#pragma unroll
        for (int r = 0; r < 2; r++) {
            int j = threadIdx.x + 256 * r;
            float s = 0.0f;
#pragma unroll 4
            for (int i = 0; i < D1; i++) s += g_bcat[i] * W1[i * D1 + j];
            g_bprime[j] = s;
        }
    }
}

// ---------------- fused misc prep: detect + zero_cnt + W2^T + Wm^T ----------
__global__ void k_misc(const int* __restrict__ ei,
                       const float* __restrict__ W2, const float* __restrict__ Wm)
{
    int b = blockIdx.x;
    if (b == 0) {
        if (threadIdx.x < 32) {
            int lane = threadIdx.x;
            int bad = 0;
#pragma unroll
            for (int i = lane; i < 256; i += 32) bad |= (ei[2 * i + 1] != 0);
            unsigned m = __ballot_sync(0xFFFFFFFF, bad);
            if (lane == 0) g_is64 = (m == 0) ? 1 : 0;
        }
    } else if (b < 257) {
        g_cnt[(b - 1) * 256 + threadIdx.x] = 0;
    } else if (b < 513) {
        int idx = (b - 257) * 256 + threadIdx.x;     // [128 n][512 k]
        int n = idx >> 9, k = idx & 511;
        g_W2Th[idx] = __float2half(W2[k * DOUTD + n]);
    } else {
        int idx = (b - 513) * 256 + threadIdx.x;     // [128 n][128 k]
        int n = idx >> 7, k = idx & 127;
        g_WmTh[idx] = __float2half(Wm[k * DOUTD + n]);
    }
}

__global__ void k_count(const void* __restrict__ eiv) {
    int e = blockIdx.x * blockDim.x + threadIdx.x;
    if (e >= EE) return;
    atomicAdd(&g_cnt[edge_at(eiv, EE + e)], 1);
}
__global__ void k_isq() {
    int i = blockIdx.x * blockDim.x + threadIdx.x;
    if (i < NN) g_isq[i] = rsqrtf((float)g_cnt[i] + 1.0f);
}
__global__ void k_scanA() {
    __shared__ int sh[256];
    int t = threadIdx.x, b = blockIdx.x;
    sh[t] = g_cnt[b * 256 + t];
    __syncthreads();
    for (int off = 128; off > 0; off >>= 1) {
        if (t < off) sh[t] += sh[t + off];
        __syncthreads();
    }
    if (t == 0) g_bsum[b] = sh[0];
}
__global__ void k_scanB() {
    __shared__ int sh[256];
    int t = threadIdx.x;
    int v = g_bsum[t];
    sh[t] = v;
    __syncthreads();
    for (int off = 1; off < 256; off <<= 1) {
        int x = (t >= off) ? sh[t - off] : 0;
        __syncthreads();
        sh[t] += x;
        __syncthreads();
    }
    g_boff[t] = sh[t] - v;
    if (t == 255) g_rowptr[NN] = sh[255];
}
__global__ void k_scanC() {
    __shared__ int sh[256];
    int t = threadIdx.x, b = blockIdx.x;
    int i = b * 256 + t;
    int v = g_cnt[i];
    sh[t] = v;
    __syncthreads();
    for (int off = 1; off < 256; off <<= 1) {
        int x = (t >= off) ? sh[t - off] : 0;
        __syncthreads();
        sh[t] += x;
        __syncthreads();
    }
    int excl = sh[t] - v + g_boff[b];
    g_rowptr[i] = excl;
    g_cursor[i] = excl;
}
__global__ void k_fill(const void* __restrict__ eiv) {
    int e = blockIdx.x * blockDim.x + threadIdx.x;
    if (e >= EE) return;
    int s = edge_at(eiv, e);
    int d = edge_at(eiv, EE + e);
    g_adj[atomicAdd(&g_cursor[d], 1)] = s;
}

// ---------------- fp16 warp-MMA GEMM, templated N-tile ----------------------
// C[M,N] = A[M,K] @ B^T[N,K], fp16 in, fp32 accumulate, fp16 out.
// BM=64, BN in {128, 256}. 256 threads, 8 warps (2 m x 4 n),
// warp tile 32 x (BN/4). BN=128: triple-buffered; BN=256: double-buffered.
#define HGEMM_SMEM_MAX 81920

template <int BIAS, int BN>
__global__ __launch_bounds__(256, 2) void hgemm(
    const __half* __restrict__ A, const __half* __restrict__ B,
    const float* __restrict__ bias, __half* __restrict__ C, int N, int K)
{
    constexpr int WN = BN / 4;          // warp n-tile: 32 or 64
    constexpr int NI = WN / 8;          // MMAs in n per mi: 4 or 8
    constexpr int NQ = WN / 16;         // B LDSM_X4 per ks: 2 or 4
    constexpr int BROWS = BN / 32;      // B cp.async row-reps: 4 or 8
    constexpr uint32_t OFF_B = 8192;    // A tile bytes
    constexpr uint32_t BUF = 8192 + (uint32_t)BN * 128;  // 24576 or 40960
    constexpr int NBUF = (BN == 128) ? 3 : 2;

    extern __shared__ char sm[];
    uint32_t smb = smem_u32(sm);
    const int tid = threadIdx.x, wid = tid >> 5, lane = tid & 31;
    const int wm = wid & 1, wn = wid >> 1;
    const int m0 = blockIdx.y * 64, n0 = blockIdx.x * BN;

    float acc[2][NI][4];
#pragma unroll
    for (int mi = 0; mi < 2; mi++)
#pragma unroll
        for (int ni = 0; ni < NI; ni++)
#pragma unroll
            for (int q = 0; q < 4; q++) acc[mi][ni][q] = 0.0f;

    const int arow = tid >> 3, ac = tid & 7;
    const uint32_t soff = swz((uint32_t)(arow * 128 + ac * 16));

    auto issue = [&](int buf, int kt) {
        uint32_t sb = smb + (uint32_t)buf * BUF;
#pragma unroll
        for (int r = 0; r < 2; r++) {
            int row = arow + 32 * r;
            uint32_t off = soff + (uint32_t)(r * 32 * 128);
            const size_t gi = (size_t)(m0 + row) * K + kt + ac * 8;
            CP16(sb + off, A + gi);
        }
#pragma unroll
        for (int r = 0; r < BROWS; r++) {
            int row = arow + 32 * r;
            uint32_t off = soff + (uint32_t)(r * 32 * 128);
            const size_t gi = (size_t)(n0 + row) * K + kt + ac * 8;
            CP16(sb + OFF_B + off, B + gi);
        }
        CP_COMMIT();
    };

    const int Cn = K / 64;
    issue(0, 0);
    if (NBUF == 3) issue(1, 64);
    for (int c = 0; c < Cn; c++) {
        if (NBUF == 3) {
            if (c + 2 < Cn) { issue((c + 2) % 3, (c + 2) * 64); CP_WAIT2(); }
            else if (c + 1 < Cn) CP_WAIT1();
            else CP_WAIT0();
        } else {
            if (c + 1 < Cn) { issue((c + 1) & 1, (c + 1) * 64); CP_WAIT1(); }
            else CP_WAIT0();
        }
        __syncthreads();
        uint32_t sbase = smb + (uint32_t)(c % NBUF) * BUF;
#pragma unroll
        for (int ks = 0; ks < 4; ks++) {
            uint32_t ah[2][4], bh[2 * NQ][2];
#pragma unroll
            for (int mi = 0; mi < 2; mi++) {
                int row = wm * 32 + mi * 16 + (lane & 15);
                int kc = ks * 16 + (lane >> 4) * 8;
                uint32_t o = swz((uint32_t)(row * 128 + kc * 2));
                LDSM_X4(ah[mi], sbase + o);
            }
#pragma unroll
            for (int nq = 0; nq < NQ; nq++) {
                int row = wn * WN + nq * 16 + ((lane >> 4) & 1) * 8 + (lane & 7);
                int kc = ks * 16 + ((lane >> 3) & 1) * 8;
                uint32_t o = swz((uint32_t)(row * 128 + kc * 2));
                uint32_t r4[4];
                LDSM_X4(r4, sbase + OFF_B + o);
                bh[2 * nq][0] = r4[0]; bh[2 * nq][1] = r4[1];
                bh[2 * nq + 1][0] = r4[2]; bh[2 * nq + 1][1] = r4[3];
            }
#pragma unroll
            for (int mi = 0; mi < 2; mi++)
#pragma unroll
                for (int ni = 0; ni < NI; ni++)
                    MMAH16816(acc[mi][ni], ah[mi], bh[ni]);
        }
        __syncthreads();
    }

    const int r = lane >> 2, cq = (lane & 3) * 2;
#pragma unroll
    for (int mi = 0; mi < 2; mi++) {
        const int mbase = m0 + wm * 32 + mi * 16 + r;
#pragma unroll
        for (int ni = 0; ni < NI; ni++) {
            const int col = n0 + wn * WN + ni * 8 + cq;
            float b0 = 0.0f, b1 = 0.0f;
            if (BIAS) { float2 bb = *(const float2*)(bias + col); b0 = bb.x; b1 = bb.y; }
#pragma unroll
            for (int h = 0; h < 2; h++) {
                const int m = mbase + 8 * h;
                float v0 = acc[mi][ni][2 * h + 0] + b0;
                float v1 = acc[mi][ni][2 * h + 1] + b1;
                *(__half2*)(C + (size_t)m * N + col) = __floats2half2_rn(v0, v1);
            }
        }
    }
}

// ---------------- bilinear scores, fp16 single-term + Linear(1,2) -----------
// per chunk b: S_b[256,256] = T_b[256,128] @ E_b[256,128]^T
// grid.x = 256 chunks * 8 subtiles (4 m-blocks x 2 n-blocks of 64x128)
__global__ __launch_bounds__(256, 2) void k_scores_h(
    const __half* __restrict__ Th, const __half* __restrict__ Eh,
    const float* __restrict__ lw, const float* __restrict__ lb,
    float* __restrict__ out)
{
    __shared__ __align__(1024) char sm[24576];   // A 8KB + B 16KB
    uint32_t smb = smem_u32(sm);
    const int tid = threadIdx.x, wid = tid >> 5, lane = tid & 31;
    const int wm = wid & 1, wn = wid >> 1;
    const int blk = blockIdx.x;
    const int chunk = blk >> 3, sub = blk & 7;
    const int mblk = sub >> 1, nblk = sub & 1;
    const int m0 = chunk * 256 + mblk * 64;
    const int n0 = chunk * 256 + nblk * 128;
    const int K = DOUTD;

    float acc[2][4][4];
#pragma unroll
    for (int mi = 0; mi < 2; mi++)
#pragma unroll
        for (int ni = 0; ni < 4; ni++)
#pragma unroll
            for (int q = 0; q < 4; q++) acc[mi][ni][q] = 0.0f;

    const int arow = tid >> 3, ac = tid & 7;
    const uint32_t soff = swz((uint32_t)(arow * 128 + ac * 16));

#pragma unroll
    for (int kt = 0; kt < K; kt += 64) {
        __syncthreads();
#pragma unroll
        for (int r = 0; r < 2; r++) {
            int row = arow + 32 * r;
            uint32_t off = soff + (uint32_t)(r * 32 * 128);
            const size_t gi = (size_t)(m0 + row) * K + kt + ac * 8;
            *(uint4*)(sm + off) = *(const uint4*)(Th + gi);
        }
#pragma unroll
        for (int r = 0; r < 4; r++) {
            int row = arow + 32 * r;
            uint32_t off = soff + (uint32_t)(r * 32 * 128);
            const size_t gi = (size_t)(n0 + row) * K + kt + ac * 8;
            *(uint4*)(sm + 8192 + off) = *(const uint4*)(Eh + gi);
        }
        __syncthreads();
#pragma unroll
        for (int ks = 0; ks < 4; ks++) {
            uint32_t ah[2][4], bh[4][2];
#pragma unroll
            for (int mi = 0; mi < 2; mi++) {
                int row = wm * 32 + mi * 16 + (lane & 15);
                int kc = ks * 16 + (lane >> 4) * 8;
                uint32_t o = swz((uint32_t)(row * 128 + kc * 2));
                LDSM_X4(ah[mi], smb + o);
            }
#pragma unroll
            for (int nq = 0; nq < 2; nq++) {
                int row = wn * 32 + nq * 16 + ((lane >> 4) & 1) * 8 + (lane & 7);
                int kc = ks * 16 + ((lane >> 3) & 1) * 8;
                uint32_t o = swz((uint32_t)(row * 128 + kc * 2));
                uint32_t r4[4];
                LDSM_X4(r4, smb + 8192 + o);
                bh[2 * nq][0] = r4[0]; bh[2 * nq][1] = r4[1];
                bh[2 * nq + 1][0] = r4[2]; bh[2 * nq + 1][1] = r4[3];
            }
#pragma unroll
            for (int mi = 0; mi < 2; mi++)
#pragma unroll
                for (int ni = 0; ni < 4; ni++)
                    MMAH16816(acc[mi][ni], ah[mi], bh[ni]);
        }
    }

    const float w0 = lw[0], w1 = lw[1], c0 = lb[0], c1 = lb[1];
    const int r = lane >> 2, cq = (lane & 3) * 2;
#pragma unroll
    for (int mi = 0; mi < 2; mi++) {
        const int irow = mblk * 64 + wm * 32 + mi * 16 + r;
#pragma unroll
        for (int ni = 0; ni < 4; ni++) {
            const int jcol = nblk * 128 + wn * 32 + ni * 8 + cq;
#pragma unroll
            for (int h = 0; h < 2; h++) {
                float s0 = acc[mi][ni][2 * h + 0];
                float s1 = acc[mi][ni][2 * h + 1];
                size_t o = (((size_t)chunk * 256 + irow + 8 * h) * 256 + jcol) * 2;
                *(float4*)(out + o) = make_float4(s0 * w0 + c0, s0 * w1 + c1,
                                                  s1 * w0 + c0, s1 * w1 + c1);
            }
        }
    }
}

// ---------------- CSR aggregate D=512, fp16 in/out, uint4 lanes, relu -------
__global__ void conv_agg512(const __half* __restrict__ hin, const float* __restrict__ bias,
                            __half* __restrict__ oh)
{
    int n = (blockIdx.x * blockDim.x + threadIdx.x) >> 5;
    int lane = threadIdx.x & 31;
    if (n >= NN) return;
    float iq = g_isq[n];
    float acc[2][8];
    {
        float w = iq * iq;
        const uint4* hp = (const uint4*)(hin + (size_t)n * D1);
#pragma unroll
        for (int i = 0; i < 2; i++) {
            uint4 v = hp[lane + 32 * i];
            float2 f0 = __half22float2(*(const __half2*)&v.x);
            float2 f1 = __half22float2(*(const __half2*)&v.y);
            float2 f2 = __half22float2(*(const __half2*)&v.z);
            float2 f3 = __half22float2(*(const __half2*)&v.w);
            acc[i][0] = f0.x * w; acc[i][1] = f0.y * w;
            acc[i][2] = f1.x * w; acc[i][3] = f1.y * w;
            acc[i][4] = f2.x * w; acc[i][5] = f2.y * w;
            acc[i][6] = f3.x * w; acc[i][7] = f3.y * w;
        }
    }
    int beg = g_rowptr[n], end = g_rowptr[n + 1];
    for (int k = beg; k < end; k++) {
        int s = g_adj[k];
        float w = g_isq[s] * iq;
        const uint4* hs = (const uint4*)(hin + (size_t)s * D1);
#pragma unroll
        for (int i = 0; i < 2; i++) {
            uint4 v = hs[lane + 32 * i];
            float2 f0 = __half22float2(*(const __half2*)&v.x);
            float2 f1 = __half22float2(*(const __half2*)&v.y);
            float2 f2 = __half22float2(*(const __half2*)&v.z);
            float2 f3 = __half22float2(*(const __half2*)&v.w);
            acc[i][0] += f0.x * w; acc[i][1] += f0.y * w;
            acc[i][2] += f1.x * w; acc[i][3] += f1.y * w;
            acc[i][4] += f2.x * w; acc[i][5] += f2.y * w;
            acc[i][6] += f3.x * w; acc[i][7] += f3.y * w;
        }
    }
#pragma unroll
    for (int i = 0; i < 2; i++) {
        int col = (lane + 32 * i) * 8;
        float4 b0 = *(const float4*)(bias + col);
        float4 b1 = *(const float4*)(bias + col + 4);
        float v0 = fmaxf(acc[i][0] + b0.x, 0.0f), v1 = fmaxf(acc[i][1] + b0.y, 0.0f);
        float v2 = fmaxf(acc[i][2] + b0.z, 0.0f), v3 = fmaxf(acc[i][3] + b0.w, 0.0f);
        float v4 = fmaxf(acc[i][4] + b1.x, 0.0f), v5 = fmaxf(acc[i][5] + b1.y, 0.0f);
        float v6 = fmaxf(acc[i][6] + b1.z, 0.0f), v7 = fmaxf(acc[i][7] + b1.w, 0.0f);
        uint4 hv = { pkh(__floats2half2_rn(v0, v1)), pkh(__floats2half2_rn(v2, v3)),
                     pkh(__floats2half2_rn(v4, v5)), pkh(__floats2half2_rn(v6, v7)) };
        *(uint4*)(oh + (size_t)n * D1 + col) = hv;
    }
}

// ---------------- CSR aggregate D=128, fp16 in/out, no relu ----------------
__global__ void conv_agg128(const __half* __restrict__ hin, const float* __restrict__ bias,
                            __half* __restrict__ oh)
{
    int n = (blockIdx.x * blockDim.x + threadIdx.x) >> 5;
    int lane = threadIdx.x & 31;
    if (n >= NN) return;
    float iq = g_isq[n];
    float acc[4];
    {
        float w = iq * iq;
        uint2 v = ((const uint2*)(hin + (size_t)n * DOUTD))[lane];
        float2 f0 = __half22float2(*(const __half2*)&v.x);
        float2 f1 = __half22float2(*(const __half2*)&v.y);
        acc[0] = f0.x * w; acc[1] = f0.y * w;
        acc[2] = f1.x * w; acc[3] = f1.y * w;
    }
    int beg = g_rowptr[n], end = g_rowptr[n + 1];
    for (int k = beg; k < end; k++) {
        int s = g_adj[k];
        float w = g_isq[s] * iq;
        uint2 v = ((const uint2*)(hin + (size_t)s * DOUTD))[lane];
        float2 f0 = __half22float2(*(const __half2*)&v.x);
        float2 f1 = __half22float2(*(const __half2*)&v.y);
        acc[0] += f0.x * w; acc[1] += f0.y * w;
        acc[2] += f1.x * w; acc[3] += f1.y * w;
    }
    int col = lane * 4;
    float4 bb = *(const float4*)(bias + col);
    float v0 = acc[0] + bb.x, v1 = acc[1] + bb.y;
    float v2 = acc[2] + bb.z, v3 = acc[3] + bb.w;
    uint2 hv = { pkh(__floats2half2_rn(v0, v1)), pkh(__floats2half2_rn(v2, v3)) };
    *(uint2*)(oh + (size_t)n * DOUTD + col) = hv;
}

// ---------------- f32x2 SGEMM (W' = Wcat@W1, tiny) ----------------
__global__ __launch_bounds__(256, 2) void sgemm_k(
    const float* __restrict__ A, const float* __restrict__ B,
    float* __restrict__ C, int M, int N, int K)
{
    __shared__ __align__(16) float As2[8][268];
    __shared__ __align__(16) float Bs[8][128];
    int tid = threadIdx.x;
    int bx = blockIdx.x, by = blockIdx.y;
    int ty = tid >> 4, tx = tid & 15;
    int arow = tid >> 1, acol4 = (tid & 1) * 4;
    int brow = tid >> 5, bcol4 = (tid & 31) * 4;
    const float* Ap = A + (size_t)(by * 128 + arow) * K;
    const float* Bp = B + (size_t)brow * N + bx * 128 + bcol4;
    unsigned long long acc[8][4];
#pragma unroll
    for (int i = 0; i < 8; i++)
#pragma unroll
        for (int j = 0; j < 4; j++) acc[i][j] = 0ull;
    for (int kt = 0; kt < K; kt += 8) {
        float4 av = *(const float4*)(Ap + kt + acol4);
        *(float2*)&As2[acol4 + 0][2 * arow] = make_float2(av.x, av.x);
        *(float2*)&As2[acol4 + 1][2 * arow] = make_float2(av.y, av.y);
        *(float2*)&As2[acol4 + 2][2 * arow] = make_float2(av.z, av.z);
        *(float2*)&As2[acol4 + 3][2 * arow] = make_float2(av.w, av.w);
        *(float4*)&Bs[brow][bcol4] = *(const float4*)(Bp + (size_t)kt * N);
        __syncthreads();
#pragma unroll
        for (int k = 0; k < 8; k++) {
            ulonglong2 a0 = *(const ulonglong2*)&As2[k][ty * 16 + 0];
            ulonglong2 a1 = *(const ulonglong2*)&As2[k][ty * 16 + 4];
            ulonglong2 a2 = *(const ulonglong2*)&As2[k][ty * 16 + 8];
            ulonglong2 a3 = *(const ulonglong2*)&As2[k][ty * 16 + 12];
            ulonglong2 b0 = *(const ulonglong2*)&Bs[k][tx * 8 + 0];
            ulonglong2 b1 = *(const ulonglong2*)&Bs[k][tx * 8 + 4];
            unsigned long long ap[8] = {a0.x, a0.y, a1.x, a1.y, a2.x, a2.y, a3.x, a3.y};
            unsigned long long bp[4] = {b0.x, b0.y, b1.x, b1.y};
#pragma unroll
            for (int i = 0; i < 8; i++)
#pragma unroll
                for (int j = 0; j < 4; j++) ffma2(acc[i][j], ap[i], bp[j]);
        }
        __syncthreads();
    }
#pragma unroll
    for (int i = 0; i < 8; i++) {
        float f[8];
#pragma unroll
        for (int j = 0; j < 4; j++) unpack2(acc[i][j], f[2 * j], f[2 * j + 1]);
        float* cp = C + (size_t)(by * 128 + ty * 8 + i) * N + bx * 128 + tx * 8;
        *(float4*)cp       = make_float4(f[0], f[1], f[2], f[3]);
        *(float4*)(cp + 4) = make_float4(f[4], f[5], f[6], f[7]);
    }
}

// ---------------- host launch ----------------
extern "C" void kernel_launch(void* const* d_in, const int* in_sizes, int n_in,
                              void* d_out, int out_size)
{
    const float* x      = (const float*)d_in[0];
    const float* Wt1    = (const float*)d_in[1];
    const float* bt1    = (const float*)d_in[2];
    const float* Wt2    = (const float*)d_in[3];
    const float* bt2    = (const float*)d_in[4];
    const float* W1     = (const float*)d_in[5];
    const float* b1     = (const float*)d_in[6];
    const float* W2     = (const float*)d_in[7];
    const float* b2     = (const float*)d_in[8];
    const float* matrix = (const float*)d_in[9];
    const float* lw     = (const float*)d_in[10];
    const float* lb     = (const float*)d_in[11];
    const void*  ei     = d_in[12];
    float* out = (float*)d_out;

    cudaFuncSetAttribute(hgemm<1, 256>, cudaFuncAttributeMaxDynamicSharedMemorySize, HGEMM_SMEM_MAX);
    cudaFuncSetAttribute(hgemm<0, 128>, cudaFuncAttributeMaxDynamicSharedMemorySize, HGEMM_SMEM_MAX);

    __half *pxh, *pWpTh, *pW2Th, *pWmTh, *pt1h, *ph1h, *ph2linh, *ph2h, *pTh;
    float *pWcatf, *pWp, *pbprime;
    cudaGetSymbolAddress((void**)&pxh, g_xh);
    cudaGetSymbolAddress((void**)&pWcatf, g_Wcatf);
    cudaGetSymbolAddress((void**)&pWp, g_Wp);
    cudaGetSymbolAddress((void**)&pWpTh, g_WpTh);
    cudaGetSymbolAddress((void**)&pbprime, g_bprime);
    cudaGetSymbolAddress((void**)&pW2Th, g_W2Th);
    cudaGetSymbolAddress((void**)&pWmTh, g_WmTh);
    cudaGetSymbolAddress((void**)&pt1h, g_t1h);
    cudaGetSymbolAddress((void**)&ph1h, g_h1h);
    cudaGetSymbolAddress((void**)&ph2linh, g_h2linh);
    cudaGetSymbolAddress((void**)&ph2h, g_h2h);
    cudaGetSymbolAddress((void**)&pTh, g_Th);

    // 1: convert x -> fp16 + Wcat fp32 + bcat (fused)
    k_prep1<<<65536 + 2048 + 1, 256>>>(x, Wt1, Wt2, bt1, bt2);
    // 2: W' = Wcat @ W1 (fp32, exact)
    sgemm_k<<<dim3(4, 8), 256>>>(pWcatf, W1, pWp, KIN, D1, D1);
    // 3: W'^T -> fp16, b' = bcat @ W1
    k_prep3<<<2049, 256>>>(W1);
    // 4 (profiled): t1 = x @ W' + b'  -> fp16 (fuses GEMM1+GEMM2), BN=256 tile
    hgemm<1, 256><<<dim3(2, 1024), 256, HGEMM_SMEM_MAX>>>(pxh, pWpTh, pbprime, pt1h, D1, KIN);
    // 5: fused misc (detect + zero_cnt + W2^T fp16 + Wm^T fp16)
    k_misc<<<577, 256>>>((const int*)ei, W2, matrix);
    k_count<<<EE / 256, 256>>>(ei);
    k_isq<<<256, 256>>>();
    k_scanA<<<256, 256>>>();
    k_scanB<<<1, 256>>>();
    k_scanC<<<256, 256>>>();
    k_fill<<<EE / 256, 256>>>(ei);
    // h1 = relu(agg(t1) + b1) -> fp16
    conv_agg512<<<NN * 32 / 256, 256>>>(pt1h, b1, ph1h);
    // h2lin = h1 @ W2 -> fp16
    hgemm<0, 128><<<dim3(1, 1024), 256, HGEMM_SMEM_MAX>>>(ph1h, pW2Th, nullptr, ph2linh, DOUTD, D1);
    // h2 = agg(h2lin) + b2 -> fp16
    conv_agg128<<<NN * 32 / 256, 256>>>(ph2linh, b2, ph2h);
    // T = h2 @ matrix -> fp16
    hgemm<0, 128><<<dim3(1, 1024), 256, HGEMM_SMEM_MAX>>>(ph2h, pWmTh, nullptr, pTh, DOUTD, DOUTD);
    // scores + Linear(1,2)
    k_scores_h<<<2048, 256>>>(pTh, ph2h, lw, lb, out);
}

// round 14
// speedup vs baseline: 9.4016x; 1.0299x over previous
#include <cuda_runtime.h>
#include <cuda_bf16.h>
#include <cuda_fp16.h>
#include <cstdint>

#define NN   65536
#define EE   1048576
#define D1   512
#define DOUTD 128
#define KIN  1024

// ---------------- device scratch (static: allocation-free) ----------------
__device__ float g_Wcatf[KIN * D1];                   // 2 MB fp32 concat [Wt1;Wt2]
__device__ float g_Wp[KIN * D1];                      // 2 MB fp32 W' = Wcat@W1
__device__ __half g_WpTh[D1 * KIN];                   // 1 MB  W'^T fp16
__device__ float g_bcat[D1];
__device__ float g_bprime[D1];
__device__ __half g_W2Th[DOUTD * D1];                 // fp16 W2^T
__device__ __half g_WmTh[DOUTD * DOUTD];              // fp16 matrix^T
__device__ __half g_t1h[(size_t)NN * D1];             // 64 MB fp16 t1
__device__ __half g_h1h[(size_t)NN * D1];             // 64 MB fp16 h1
__device__ __half g_h2linh[(size_t)NN * DOUTD];       // 16 MB fp16 h2lin
__device__ __half g_h2h[(size_t)NN * DOUTD];          // 16 MB fp16 h2
__device__ __half g_Th[(size_t)NN * DOUTD];           // 16 MB fp16 T
__device__ float g_isq[NN];
__device__ int   g_cnt[NN];
__device__ int   g_rowptr[NN + 1];
__device__ int   g_cursor[NN];
__device__ int   g_bsum[256];
__device__ int   g_boff[256];
__device__ int   g_adj[EE];
__device__ int   g_is64;

// ---------------- tiny helpers ----------------
__device__ __forceinline__ unsigned pkh(__half2 h) {
    return *(unsigned*)&h;
}
__device__ __forceinline__ uint32_t smem_u32(const void* p) {
    uint32_t a;
    asm("{ .reg .u64 t; cvta.to.shared.u64 t, %1; cvt.u32.u64 %0, t; }" : "=r"(a) : "l"(p));
    return a;
}
__device__ __forceinline__ void ffma2(unsigned long long& d, unsigned long long a, unsigned long long b) {
    asm("fma.rn.f32x2 %0, %1, %2, %0;" : "+l"(d) : "l"(a), "l"(b));
}
__device__ __forceinline__ void unpack2(unsigned long long v, float& lo, float& hi) {
    asm("mov.b64 {%0, %1}, %2;" : "=f"(lo), "=f"(hi) : "l"(v));
}

#define LDSM_X4(r, ad) \
    asm volatile("ldmatrix.sync.aligned.m8n8.x4.shared.b16 {%0,%1,%2,%3}, [%4];" \
                 : "=r"((r)[0]), "=r"((r)[1]), "=r"((r)[2]), "=r"((r)[3]) : "r"(ad))
#define MMAH16816(c, a, b) \
    asm volatile("mma.sync.aligned.m16n8k16.row.col.f32.f16.f16.f32 " \
                 "{%0,%1,%2,%3}, {%4,%5,%6,%7}, {%8,%9}, {%0,%1,%2,%3};" \
                 : "+f"((c)[0]), "+f"((c)[1]), "+f"((c)[2]), "+f"((c)[3]) \
                 : "r"((a)[0]), "r"((a)[1]), "r"((a)[2]), "r"((a)[3]), \
                   "r"((b)[0]), "r"((b)[1]))
#define CP16(sa, gp) \
    asm volatile("cp.async.cg.shared.global [%0], [%1], 16;" :: "r"(sa), "l"(gp))
#define CP_COMMIT() asm volatile("cp.async.commit_group;" ::: "memory")
#define CP_WAIT2()  asm volatile("cp.async.wait_group 2;" ::: "memory")
#define CP_WAIT1()  asm volatile("cp.async.wait_group 1;" ::: "memory")
#define CP_WAIT0()  asm volatile("cp.async.wait_group 0;" ::: "memory")

__device__ __forceinline__ uint32_t swz(uint32_t o) { return o ^ ((o >> 3) & 0x70); }

__device__ __forceinline__ int edge_at(const void* eiv, int idx) {
    if (g_is64) return (int)((const long long*)eiv)[idx];
    return ((const int*)eiv)[idx];
}

// ---------------- prep 1: build fp32 Wcat, bcat (x stays in place) ----------
__global__ void k_prep1(const float* __restrict__ Wt1, const float* __restrict__ Wt2,
                        const float* __restrict__ bt1, const float* __restrict__ bt2)
{
    int b = blockIdx.x;
    if (b < 2048) {
        int idx = b * 256 + threadIdx.x;             // [1024 k][512 n] row-major
        int k = idx >> 9, n = idx & 511;
        g_Wcatf[idx] = (k < 256) ? Wt1[k * D1 + n] : Wt2[(k - 256) * D1 + n];
    } else {
#pragma unroll
        for (int r = 0; r < 2; r++) {
            int j = threadIdx.x + 256 * r;
            g_bcat[j] = bt1[j] + bt2[j];
        }
    }
}

// ---------------- prep 3: W'^T -> fp16 + b' = bcat@W1 ----------------
__global__ void k_prep3(const float* __restrict__ W1) {
    int b = blockIdx.x;
    if (b < 2048) {
        int idx = b * 256 + threadIdx.x;             // [512 n][1024 k]
        int k = idx & 1023;
        int n = idx >> 10;
        g_WpTh[idx] = __float2half(g_Wp[k * D1 + n]);
    } else {
#pragma unroll
        for (int r = 0; r < 2; r++) {
            int j = threadIdx.x + 256 * r;
            float s = 0.0f;
#pragma unroll 4
            for (int i = 0; i < D1; i++) s += g_bcat[i] * W1[i * D1 + j];
            g_bprime[j] = s;
        }
    }
}

// ---------------- fused misc prep: detect + zero_cnt + W2^T + Wm^T ----------
__global__ void k_misc(const int* __restrict__ ei,
                       const float* __restrict__ W2, const float* __restrict__ Wm)
{
    int b = blockIdx.x;
    if (b == 0) {
        if (threadIdx.x < 32) {
            int lane = threadIdx.x;
            int bad = 0;
#pragma unroll
            for (int i = lane; i < 256; i += 32) bad |= (ei[2 * i + 1] != 0);
            unsigned m = __ballot_sync(0xFFFFFFFF, bad);
            if (lane == 0) g_is64 = (m == 0) ? 1 : 0;
        }
    } else if (b < 257) {
        g_cnt[(b - 1) * 256 + threadIdx.x] = 0;
    } else if (b < 513) {
        int idx = (b - 257) * 256 + threadIdx.x;     // [128 n][512 k]
        int n = idx >> 9, k = idx & 511;
        g_W2Th[idx] = __float2half(W2[k * DOUTD + n]);
    } else {
        int idx = (b - 513) * 256 + threadIdx.x;     // [128 n][128 k]
        int n = idx >> 7, k = idx & 127;
        g_WmTh[idx] = __float2half(Wm[k * DOUTD + n]);
    }
}

__global__ void k_count(const void* __restrict__ eiv) {
    int e = blockIdx.x * blockDim.x + threadIdx.x;
    if (e >= EE) return;
    atomicAdd(&g_cnt[edge_at(eiv, EE + e)], 1);
}
// block sum + per-node isq fused
__global__ void k_scanA() {
    __shared__ int sh[256];
    int t = threadIdx.x, b = blockIdx.x;
    int v = g_cnt[b * 256 + t];
    g_isq[b * 256 + t] = rsqrtf((float)v + 1.0f);
    sh[t] = v;
    __syncthreads();
    for (int off = 128; off > 0; off >>= 1) {
        if (t < off) sh[t] += sh[t + off];
        __syncthreads();
    }
    if (t == 0) g_bsum[b] = sh[0];
}
__global__ void k_scanB() {
    __shared__ int sh[256];
    int t = threadIdx.x;
    int v = g_bsum[t];
    sh[t] = v;
    __syncthreads();
    for (int off = 1; off < 256; off <<= 1) {
        int x = (t >= off) ? sh[t - off] : 0;
        __syncthreads();
        sh[t] += x;
        __syncthreads();
    }
    g_boff[t] = sh[t] - v;
    if (t == 255) g_rowptr[NN] = sh[255];
}
__global__ void k_scanC() {
    __shared__ int sh[256];
    int t = threadIdx.x, b = blockIdx.x;
    int i = b * 256 + t;
    int v = g_cnt[i];
    sh[t] = v;
    __syncthreads();
    for (int off = 1; off < 256; off <<= 1) {
        int x = (t >= off) ? sh[t - off] : 0;
        __syncthreads();
        sh[t] += x;
        __syncthreads();
    }
    int excl = sh[t] - v + g_boff[b];
    g_rowptr[i] = excl;
    g_cursor[i] = excl;
}
__global__ void k_fill(const void* __restrict__ eiv) {
    int e = blockIdx.x * blockDim.x + threadIdx.x;
    if (e >= EE) return;
    int s = edge_at(eiv, e);
    int d = edge_at(eiv, EE + e);
    g_adj[atomicAdd(&g_cursor[d], 1)] = s;
}

// ---------------- fp16 warp-MMA GEMM, templated N-tile + fp32-A fusion ------
// C[M,N] = A[M,K] @ B^T[N,K], fp32 accumulate, fp16 out.
// BM=64, BN in {128, 256}. 256 threads, 8 warps (2 m x 4 n), warp tile 32x(BN/4).
// A32=1: A read as fp32, converted to fp16 via SMEM staging inside the kernel.
#define HGEMM_SMEM_MAX 114688

template <int BIAS, int BN, int A32>
__global__ __launch_bounds__(256, 2) void hgemm(
    const float* __restrict__ Af, const __half* __restrict__ Ah,
    const __half* __restrict__ B,
    const float* __restrict__ bias, __half* __restrict__ C, int N, int K)
{
    constexpr int WN = BN / 4;          // warp n-tile
    constexpr int NI = WN / 8;          // MMAs in n per mi
    constexpr int NQ = WN / 16;         // B LDSM_X4 per ks
    constexpr int BROWS = BN / 32;      // B cp.async row-reps
    constexpr uint32_t STG = A32 ? 16384u : 0u;       // fp32 staging bytes
    constexpr uint32_t OFF_A16 = STG;                 // fp16 A tile
    constexpr uint32_t OFF_B = STG + 8192u;
    constexpr uint32_t BUF = STG + 8192u + (uint32_t)BN * 128u;
    constexpr int NBUF = (BN == 128) ? 3 : 2;

    extern __shared__ char sm[];
    uint32_t smb = smem_u32(sm);
    const int tid = threadIdx.x, wid = tid >> 5, lane = tid & 31;
    const int wm = wid & 1, wn = wid >> 1;
    const int m0 = blockIdx.y * 64, n0 = blockIdx.x * BN;

    float acc[2][NI][4];
#pragma unroll
    for (int mi = 0; mi < 2; mi++)
#pragma unroll
        for (int ni = 0; ni < NI; ni++)
#pragma unroll
            for (int q = 0; q < 4; q++) acc[mi][ni][q] = 0.0f;

    const int arow = tid >> 3, ac = tid & 7;
    const uint32_t soff = swz((uint32_t)(arow * 128 + ac * 16));
    // A32 staging indexing: row = tid>>2, 4 granules of 16B each
    const int srow = tid >> 2, sq = tid & 3;

    auto issue = [&](int buf, int kt) {
        uint32_t sb = smb + (uint32_t)buf * BUF;
        if (A32) {
#pragma unroll
            for (int r = 0; r < 4; r++) {
                int g = sq * 4 + r;
                uint32_t off = (uint32_t)(srow * 256 + g * 16) ^ ((uint32_t)(srow & 7) << 4);
                const float* gp = Af + (size_t)(m0 + srow) * K + kt + g * 4;
                CP16(sb + off, gp);
            }
        } else {
#pragma unroll
            for (int r = 0; r < 2; r++) {
                int row = arow + 32 * r;
                uint32_t off = soff + (uint32_t)(r * 32 * 128);
                const size_t gi = (size_t)(m0 + row) * K + kt + ac * 8;
                CP16(sb + off, Ah + gi);
            }
        }
#pragma unroll
        for (int r = 0; r < BROWS; r++) {
            int row = arow + 32 * r;
            uint32_t off = soff + (uint32_t)(r * 32 * 128);
            const size_t gi = (size_t)(n0 + row) * K + kt + ac * 8;
            CP16(sb + OFF_B + off, B + gi);
        }
        CP_COMMIT();
    };

    const int Cn = K / 64;
    issue(0, 0);
    if (NBUF == 3) issue(1, 64);
    for (int c = 0; c < Cn; c++) {
        if (NBUF == 3) {
            if (c + 2 < Cn) { issue((c + 2) % 3, (c + 2) * 64); CP_WAIT2(); }
            else if (c + 1 < Cn) CP_WAIT1();
            else CP_WAIT0();
        } else {
            if (c + 1 < Cn) { issue((c + 1) & 1, (c + 1) * 64); CP_WAIT1(); }
            else CP_WAIT0();
        }
        __syncthreads();
        uint32_t sbase = smb + (uint32_t)(c % NBUF) * BUF;
        if (A32) {
            // convert staging fp32 -> fp16 tile (bank-conflict-free via XOR)
            char* sbp = sm + (size_t)(c % NBUF) * BUF;
#pragma unroll
            for (int p = 0; p < 2; p++) {
                uint32_t w[4];
#pragma unroll
                for (int i = 0; i < 2; i++) {
                    int g = sq * 4 + p * 2 + i;
                    uint32_t off = (uint32_t)(srow * 256 + g * 16) ^ ((uint32_t)(srow & 7) << 4);
                    float4 f = *(const float4*)(sbp + off);
                    w[2 * i + 0] = pkh(__floats2half2_rn(f.x, f.y));
                    w[2 * i + 1] = pkh(__floats2half2_rn(f.z, f.w));
                }
                uint32_t o16 = swz((uint32_t)(srow * 128 + sq * 32 + p * 16));
                *(uint4*)(sbp + OFF_A16 + o16) = make_uint4(w[0], w[1], w[2], w[3]);
            }
            __syncthreads();
        }
#pragma unroll
        for (int ks = 0; ks < 4; ks++) {
            uint32_t ah[2][4], bh[2 * NQ][2];
#pragma unroll
            for (int mi = 0; mi < 2; mi++) {
                int row = wm * 32 + mi * 16 + (lane & 15);
                int kc = ks * 16 + (lane >> 4) * 8;
                uint32_t o = swz((uint32_t)(row * 128 + kc * 2));
                LDSM_X4(ah[mi], sbase + OFF_A16 + o);
            }
#pragma unroll
            for (int nq = 0; nq < NQ; nq++) {
                int row = wn * WN + nq * 16 + ((lane >> 4) & 1) * 8 + (lane & 7);
                int kc = ks * 16 + ((lane >> 3) & 1) * 8;
                uint32_t o = swz((uint32_t)(row * 128 + kc * 2));
                uint32_t r4[4];
                LDSM_X4(r4, sbase + OFF_B + o);
                bh[2 * nq][0] = r4[0]; bh[2 * nq][1] = r4[1];
                bh[2 * nq + 1][0] = r4[2]; bh[2 * nq + 1][1] = r4[3];
            }
#pragma unroll
            for (int mi = 0; mi < 2; mi++)
#pragma unroll
                for (int ni = 0; ni < NI; ni++)
                    MMAH16816(acc[mi][ni], ah[mi], bh[ni]);
        }
        __syncthreads();
    }

    const int r = lane >> 2, cq = (lane & 3) * 2;
#pragma unroll
    for (int mi = 0; mi < 2; mi++) {
        const int mbase = m0 + wm * 32 + mi * 16 + r;
#pragma unroll
        for (int ni = 0; ni < NI; ni++) {
            const int col = n0 + wn * WN + ni * 8 + cq;
            float b0 = 0.0f, b1 = 0.0f;
            if (BIAS) { float2 bb = *(const float2*)(bias + col); b0 = bb.x; b1 = bb.y; }
#pragma unroll
            for (int h = 0; h < 2; h++) {
                const int m = mbase + 8 * h;
                float v0 = acc[mi][ni][2 * h + 0] + b0;
                float v1 = acc[mi][ni][2 * h + 1] + b1;
                *(__half2*)(C + (size_t)m * N + col) = __floats2half2_rn(v0, v1);
            }
        }
    }
}

// ---------------- bilinear scores, fp16 single-term + Linear(1,2) -----------
__global__ __launch_bounds__(256, 2) void k_scores_h(
    const __half* __restrict__ Th, const __half* __restrict__ Eh,
    const float* __restrict__ lw, const float* __restrict__ lb,
    float* __restrict__ out)
{
    __shared__ __align__(1024) char sm[24576];   // A 8KB + B 16KB
    uint32_t smb = smem_u32(sm);
    const int tid = threadIdx.x, wid = tid >> 5, lane = tid & 31;
    const int wm = wid & 1, wn = wid >> 1;
    const int blk = blockIdx.x;
    const int chunk = blk >> 3, sub = blk & 7;
    const int mblk = sub >> 1, nblk = sub & 1;
    const int m0 = chunk * 256 + mblk * 64;
    const int n0 = chunk * 256 + nblk * 128;
    const int K = DOUTD;

    float acc[2][4][4];
#pragma unroll
    for (int mi = 0; mi < 2; mi++)
#pragma unroll
        for (int ni = 0; ni < 4; ni++)
#pragma unroll
            for (int q = 0; q < 4; q++) acc[mi][ni][q] = 0.0f;

    const int arow = tid >> 3, ac = tid & 7;
    const uint32_t soff = swz((uint32_t)(arow * 128 + ac * 16));

#pragma unroll
    for (int kt = 0; kt < K; kt += 64) {
        __syncthreads();
#pragma unroll
        for (int r = 0; r < 2; r++) {
            int row = arow + 32 * r;
            uint32_t off = soff + (uint32_t)(r * 32 * 128);
            const size_t gi = (size_t)(m0 + row) * K + kt + ac * 8;
            *(uint4*)(sm + off) = *(const uint4*)(Th + gi);
        }
#pragma unroll
        for (int r = 0; r < 4; r++) {
            int row = arow + 32 * r;
            uint32_t off = soff + (uint32_t)(r * 32 * 128);
            const size_t gi = (size_t)(n0 + row) * K + kt + ac * 8;
            *(uint4*)(sm + 8192 + off) = *(const uint4*)(Eh + gi);
        }
        __syncthreads();
#pragma unroll
        for (int ks = 0; ks < 4; ks++) {
            uint32_t ah[2][4], bh[4][2];
#pragma unroll
            for (int mi = 0; mi < 2; mi++) {
                int row = wm * 32 + mi * 16 + (lane & 15);
                int kc = ks * 16 + (lane >> 4) * 8;
                uint32_t o = swz((uint32_t)(row * 128 + kc * 2));
                LDSM_X4(ah[mi], smb + o);
            }
#pragma unroll
            for (int nq = 0; nq < 2; nq++) {
                int row = wn * 32 + nq * 16 + ((lane >> 4) & 1) * 8 + (lane & 7);
                int kc = ks * 16 + ((lane >> 3) & 1) * 8;
                uint32_t o = swz((uint32_t)(row * 128 + kc * 2));
                uint32_t r4[4];
                LDSM_X4(r4, smb + 8192 + o);
                bh[2 * nq][0] = r4[0]; bh[2 * nq][1] = r4[1];
                bh[2 * nq + 1][0] = r4[2]; bh[2 * nq + 1][1] = r4[3];
            }
#pragma unroll
            for (int mi = 0; mi < 2; mi++)
#pragma unroll
                for (int ni = 0; ni < 4; ni++)
                    MMAH16816(acc[mi][ni], ah[mi], bh[ni]);
        }
    }

    const float w0 = lw[0], w1 = lw[1], c0 = lb[0], c1 = lb[1];
    const int r = lane >> 2, cq = (lane & 3) * 2;
#pragma unroll
    for (int mi = 0; mi < 2; mi++) {
        const int irow = mblk * 64 + wm * 32 + mi * 16 + r;
#pragma unroll
        for (int ni = 0; ni < 4; ni++) {
            const int jcol = nblk * 128 + wn * 32 + ni * 8 + cq;
#pragma unroll
            for (int h = 0; h < 2; h++) {
                float s0 = acc[mi][ni][2 * h + 0];
                float s1 = acc[mi][ni][2 * h + 1];
                size_t o = (((size_t)chunk * 256 + irow + 8 * h) * 256 + jcol) * 2;
                *(float4*)(out + o) = make_float4(s0 * w0 + c0, s0 * w1 + c1,
                                                  s1 * w0 + c0, s1 * w1 + c1);
            }
        }
    }
}

// ---------------- CSR aggregate D=512, fp16 in/out, uint4 lanes, relu -------
__global__ void conv_agg512(const __half* __restrict__ hin, const float* __restrict__ bias,
                            __half* __restrict__ oh)
{
    int n = (blockIdx.x * blockDim.x + threadIdx.x) >> 5;
    int lane = threadIdx.x & 31;
    if (n >= NN) return;
    float iq = g_isq[n];
    float acc[2][8];
    {
        float w = iq * iq;
        const uint4* hp = (const uint4*)(hin + (size_t)n * D1);
#pragma unroll
        for (int i = 0; i < 2; i++) {
            uint4 v = hp[lane + 32 * i];
            float2 f0 = __half22float2(*(const __half2*)&v.x);
            float2 f1 = __half22float2(*(const __half2*)&v.y);
            float2 f2 = __half22float2(*(const __half2*)&v.z);
            float2 f3 = __half22float2(*(const __half2*)&v.w);
            acc[i][0] = f0.x * w; acc[i][1] = f0.y * w;
            acc[i][2] = f1.x * w; acc[i][3] = f1.y * w;
            acc[i][4] = f2.x * w; acc[i][5] = f2.y * w;
            acc[i][6] = f3.x * w; acc[i][7] = f3.y * w;
        }
    }
    int beg = g_rowptr[n], end = g_rowptr[n + 1];
    for (int k = beg; k < end; k++) {
        int s = g_adj[k];
        float w = g_isq[s] * iq;
        const uint4* hs = (const uint4*)(hin + (size_t)s * D1);
#pragma unroll
        for (int i = 0; i < 2; i++) {
            uint4 v = hs[lane + 32 * i];
            float2 f0 = __half22float2(*(const __half2*)&v.x);
            float2 f1 = __half22float2(*(const __half2*)&v.y);
            float2 f2 = __half22float2(*(const __half2*)&v.z);
            float2 f3 = __half22float2(*(const __half2*)&v.w);
            acc[i][0] += f0.x * w; acc[i][1] += f0.y * w;
            acc[i][2] += f1.x * w; acc[i][3] += f1.y * w;
            acc[i][4] += f2.x * w; acc[i][5] += f2.y * w;
            acc[i][6] += f3.x * w; acc[i][7] += f3.y * w;
        }
    }
#pragma unroll
    for (int i = 0; i < 2; i++) {
        int col = (lane + 32 * i) * 8;
        float4 b0 = *(const float4*)(bias + col);
        float4 b1 = *(const float4*)(bias + col + 4);
        float v0 = fmaxf(acc[i][0] + b0.x, 0.0f), v1 = fmaxf(acc[i][1] + b0.y, 0.0f);
        float v2 = fmaxf(acc[i][2] + b0.z, 0.0f), v3 = fmaxf(acc[i][3] + b0.w, 0.0f);
        float v4 = fmaxf(acc[i][4] + b1.x, 0.0f), v5 = fmaxf(acc[i][5] + b1.y, 0.0f);
        float v6 = fmaxf(acc[i][6] + b1.z, 0.0f), v7 = fmaxf(acc[i][7] + b1.w, 0.0f);
        uint4 hv = { pkh(__floats2half2_rn(v0, v1)), pkh(__floats2half2_rn(v2, v3)),
                     pkh(__floats2half2_rn(v4, v5)), pkh(__floats2half2_rn(v6, v7)) };
        *(uint4*)(oh + (size_t)n * D1 + col) = hv;
    }
}

// ---------------- CSR aggregate D=128, fp16 in/out, no relu ----------------
__global__ void conv_agg128(const __half* __restrict__ hin, const float* __restrict__ bias,
                            __half* __restrict__ oh)
{
    int n = (blockIdx.x * blockDim.x + threadIdx.x) >> 5;
    int lane = threadIdx.x & 31;
    if (n >= NN) return;
    float iq = g_isq[n];
    float acc[4];
    {
        float w = iq * iq;
        uint2 v = ((const uint2*)(hin + (size_t)n * DOUTD))[lane];
        float2 f0 = __half22float2(*(const __half2*)&v.x);
        float2 f1 = __half22float2(*(const __half2*)&v.y);
        acc[0] = f0.x * w; acc[1] = f0.y * w;
        acc[2] = f1.x * w; acc[3] = f1.y * w;
    }
    int beg = g_rowptr[n], end = g_rowptr[n + 1];
    for (int k = beg; k < end; k++) {
        int s = g_adj[k];
        float w = g_isq[s] * iq;
        uint2 v = ((const uint2*)(hin + (size_t)s * DOUTD))[lane];
        float2 f0 = __half22float2(*(const __half2*)&v.x);
        float2 f1 = __half22float2(*(const __half2*)&v.y);
        acc[0] += f0.x * w; acc[1] += f0.y * w;
        acc[2] += f1.x * w; acc[3] += f1.y * w;
    }
    int col = lane * 4;
    float4 bb = *(const float4*)(bias + col);
    float v0 = acc[0] + bb.x, v1 = acc[1] + bb.y;
    float v2 = acc[2] + bb.z, v3 = acc[3] + bb.w;
    uint2 hv = { pkh(__floats2half2_rn(v0, v1)), pkh(__floats2half2_rn(v2, v3)) };
    *(uint2*)(oh + (size_t)n * DOUTD + col) = hv;
}

// ---------------- f32x2 SGEMM (W' = Wcat@W1, tiny) ----------------
__global__ __launch_bounds__(256, 2) void sgemm_k(
    const float* __restrict__ A, const float* __restrict__ B,
    float* __restrict__ C, int M, int N, int K)
{
    __shared__ __align__(16) float As2[8][268];
    __shared__ __align__(16) float Bs[8][128];
    int tid = threadIdx.x;
    int bx = blockIdx.x, by = blockIdx.y;
    int ty = tid >> 4, tx = tid & 15;
    int arow = tid >> 1, acol4 = (tid & 1) * 4;
    int brow = tid >> 5, bcol4 = (tid & 31) * 4;
    const float* Ap = A + (size_t)(by * 128 + arow) * K;
    const float* Bp = B + (size_t)brow * N + bx * 128 + bcol4;
    unsigned long long acc[8][4];
#pragma unroll
    for (int i = 0; i < 8; i++)
#pragma unroll
        for (int j = 0; j < 4; j++) acc[i][j] = 0ull;
    for (int kt = 0; kt < K; kt += 8) {
        float4 av = *(const float4*)(Ap + kt + acol4);
        *(float2*)&As2[acol4 + 0][2 * arow] = make_float2(av.x, av.x);
        *(float2*)&As2[acol4 + 1][2 * arow] = make_float2(av.y, av.y);
        *(float2*)&As2[acol4 + 2][2 * arow] = make_float2(av.z, av.z);
        *(float2*)&As2[acol4 + 3][2 * arow] = make_float2(av.w, av.w);
        *(float4*)&Bs[brow][bcol4] = *(const float4*)(Bp + (size_t)kt * N);
        __syncthreads();
#pragma unroll
        for (int k = 0; k < 8; k++) {
            ulonglong2 a0 = *(const ulonglong2*)&As2[k][ty * 16 + 0];
            ulonglong2 a1 = *(const ulonglong2*)&As2[k][ty * 16 + 4];
            ulonglong2 a2 = *(const ulonglong2*)&As2[k][ty * 16 + 8];
            ulonglong2 a3 = *(const ulonglong2*)&As2[k][ty * 16 + 12];
            ulonglong2 b0 = *(const ulonglong2*)&Bs[k][tx * 8 + 0];
            ulonglong2 b1 = *(const ulonglong2*)&Bs[k][tx * 8 + 4];
            unsigned long long ap[8] = {a0.x, a0.y, a1.x, a1.y, a2.x, a2.y, a3.x, a3.y};
            unsigned long long bp[4] = {b0.x, b0.y, b1.x, b1.y};
#pragma unroll
            for (int i = 0; i < 8; i++)
#pragma unroll
                for (int j = 0; j < 4; j++) ffma2(acc[i][j], ap[i], bp[j]);
        }
        __syncthreads();
    }
#pragma unroll
    for (int i = 0; i < 8; i++) {
        float f[8];
#pragma unroll
        for (int j = 0; j < 4; j++) unpack2(acc[i][j], f[2 * j], f[2 * j + 1]);
        float* cp = C + (size_t)(by * 128 + ty * 8 + i) * N + bx * 128 + tx * 8;
        *(float4*)cp       = make_float4(f[0], f[1], f[2], f[3]);
        *(float4*)(cp + 4) = make_float4(f[4], f[5], f[6], f[7]);
    }
}

// ---------------- host launch ----------------
extern "C" void kernel_launch(void* const* d_in, const int* in_sizes, int n_in,
                              void* d_out, int out_size)
{
    const float* x      = (const float*)d_in[0];
    const float* Wt1    = (const float*)d_in[1];
    const float* bt1    = (const float*)d_in[2];
    const float* Wt2    = (const float*)d_in[3];
    const float* bt2    = (const float*)d_in[4];
    const float* W1     = (const float*)d_in[5];
    const float* b1     = (const float*)d_in[6];
    const float* W2     = (const float*)d_in[7];
    const float* b2     = (const float*)d_in[8];
    const float* matrix = (const float*)d_in[9];
    const float* lw     = (const float*)d_in[10];
    const float* lb     = (const float*)d_in[11];
    const void*  ei     = d_in[12];
    float* out = (float*)d_out;

    cudaFuncSetAttribute(hgemm<1, 256, 1>, cudaFuncAttributeMaxDynamicSharedMemorySize, HGEMM_SMEM_MAX);
    cudaFuncSetAttribute(hgemm<0, 128, 0>, cudaFuncAttributeMaxDynamicSharedMemorySize, 73728);

    __half *pWpTh, *pW2Th, *pWmTh, *pt1h, *ph1h, *ph2linh, *ph2h, *pTh;
    float *pWcatf, *pWp, *pbprime;
    cudaGetSymbolAddress((void**)&pWcatf, g_Wcatf);
    cudaGetSymbolAddress((void**)&pWp, g_Wp);
    cudaGetSymbolAddress((void**)&pWpTh, g_WpTh);
    cudaGetSymbolAddress((void**)&pbprime, g_bprime);
    cudaGetSymbolAddress((void**)&pW2Th, g_W2Th);
    cudaGetSymbolAddress((void**)&pWmTh, g_WmTh);
    cudaGetSymbolAddress((void**)&pt1h, g_t1h);
    cudaGetSymbolAddress((void**)&ph1h, g_h1h);
    cudaGetSymbolAddress((void**)&ph2linh, g_h2linh);
    cudaGetSymbolAddress((void**)&ph2h, g_h2h);
    cudaGetSymbolAddress((void**)&pTh, g_Th);

    // 1: Wcat fp32 + bcat
    k_prep1<<<2049, 256>>>(Wt1, Wt2, bt1, bt2);
    // 2: W' = Wcat @ W1 (fp32, exact)
    sgemm_k<<<dim3(4, 8), 256>>>(pWcatf, W1, pWp, KIN, D1, D1);
    // 3: W'^T -> fp16, b' = bcat @ W1
    k_prep3<<<2049, 256>>>(W1);
    // 4 (profiled): t1 = x @ W' + b' -> fp16; x read fp32, converted in-kernel
    hgemm<1, 256, 1><<<dim3(2, 1024), 256, HGEMM_SMEM_MAX>>>(
        x, nullptr, pWpTh, pbprime, pt1h, D1, KIN);
    // 5: fused misc (detect + zero_cnt + W2^T fp16 + Wm^T fp16)
    k_misc<<<577, 256>>>((const int*)ei, W2, matrix);
    k_count<<<EE / 256, 256>>>(ei);
    k_scanA<<<256, 256>>>();
    k_scanB<<<1, 256>>>();
    k_scanC<<<256, 256>>>();
    k_fill<<<EE / 256, 256>>>(ei);
    // h1 = relu(agg(t1) + b1) -> fp16
    conv_agg512<<<NN * 32 / 256, 256>>>(pt1h, b1, ph1h);
    // h2lin = h1 @ W2 -> fp16
    hgemm<0, 128, 0><<<dim3(1, 1024), 256, 73728>>>(
        nullptr, ph1h, pW2Th, nullptr, ph2linh, DOUTD, D1);
    // h2 = agg(h2lin) + b2 -> fp16
    conv_agg128<<<NN * 32 / 256, 256>>>(ph2linh, b2, ph2h);
    // T = h2 @ matrix -> fp16
    hgemm<0, 128, 0><<<dim3(1, 1024), 256, 73728>>>(
        nullptr, ph2h, pWmTh, nullptr, pTh, DOUTD, DOUTD);
    // scores + Linear(1,2)
    k_scores_h<<<2048, 256>>>(pTh, ph2h, lw, lb, out);
}